// round 11
// baseline (speedup 1.0000x reference)
#include <cuda_runtime.h>
#include <cuda_fp16.h>
#include <math.h>
#include <cstdint>

// ---------------------------------------------------------------------------
// Problem constants
// ---------------------------------------------------------------------------
#define NV   16384      // nodes
#define DV   128        // node dim
#define EDV  32         // edge feat dim
#define EV   262144     // edges
#define GV   32         // graphs
#define SV   512        // seq per graph
#define HV   4          // heads
#define HDV  32         // head dim

// ---------------------------------------------------------------------------
// Scratch buffers (device globals; no runtime allocation allowed)
// ---------------------------------------------------------------------------
__device__ float  g_xn   [NV * DV];
__device__ __half g_pdps [NV * 512];    // [Pd | Ps] per node, fp16
__device__ float  g_aggrH[NV * 256];
__device__ float  g_t1   [NV * DV];
__device__ __half g_qkvh [NV * 3 * DV]; // qkv fp16
__device__ float  g_obuf [NV * DV];
__device__ float  g_h1   [NV * DV];
__device__ float  g_ffn  [NV * 2 * DV];
__device__ float  g_uw   [384 * 128];   // [U1a ; W2@U1b]
__device__ float  g_b2u  [128];         // msg_b2 @ U1b
__device__ int    g_cnt   [NV];
__device__ int    g_offs  [NV + 1];
__device__ int    g_cursor[NV];
__device__ int    g_eperm [EV];
__device__ int    g_ssrc  [EV];
__device__ int    g_sdst  [EV];
__device__ float  g_deg   [NV];
__device__ int    g_bsum  [8];

// fp16 transposed weight tables [N][K]
__device__ __half g_wh_pdps[512 * 128];
__device__ __half g_wh_uw  [128 * 384];
__device__ __half g_wh_u2  [128 * 128];
__device__ __half g_wh_qkv [384 * 128];
__device__ __half g_wh_out [128 * 128];
__device__ __half g_wh_f1  [256 * 128];
__device__ __half g_wh_f2  [128 * 256];

// ---------------------------------------------------------------------------
// f32x2 packed-math helpers
// ---------------------------------------------------------------------------
typedef unsigned long long u64;

__device__ __forceinline__ u64 dup2(float x) {
    u64 r; asm("mov.b64 %0, {%1, %1};" : "=l"(r) : "f"(x)); return r;
}
__device__ __forceinline__ float2 unpack2(u64 v) {
    float2 r; asm("mov.b64 {%0, %1}, %2;" : "=f"(r.x), "=f"(r.y) : "l"(v)); return r;
}
__device__ __forceinline__ void fma2(u64& d, u64 a, u64 b) {
    asm("fma.rn.f32x2 %0, %1, %2, %0;" : "+l"(d) : "l"(a), "l"(b));
}

__device__ __forceinline__ float gelu_f(float v) {
    return 0.5f * v * (1.0f + erff(v * 0.70710678118654752f));
}

__device__ __forceinline__ void mma16816(
    float* d, const uint32_t* a, uint32_t b0, uint32_t b1)
{
    asm volatile(
        "mma.sync.aligned.m16n8k16.row.col.f32.f16.f16.f32 "
        "{%0,%1,%2,%3}, {%4,%5,%6,%7}, {%8,%9}, {%0,%1,%2,%3};"
        : "+f"(d[0]), "+f"(d[1]), "+f"(d[2]), "+f"(d[3])
        : "r"(a[0]), "r"(a[1]), "r"(a[2]), "r"(a[3]), "r"(b0), "r"(b1));
}

__device__ __forceinline__ uint32_t packh2(float a, float b) {
    __half2 h = __floats2half2_rn(a, b);
    return *(uint32_t*)&h;
}

// ---------------------------------------------------------------------------
// Batched weight conversion: all tables in one launch (1024 blocks x 256).
// ---------------------------------------------------------------------------
__global__ __launch_bounds__(256) void convw_all_kernel(
    const float* msg_w1, const float* uw, const float* upd_w2,
    const float* in_w, const float* out_w,
    const float* ffn_w1, const float* ffn_w2,
    __half* whpdps, __half* whuw, __half* whu2,
    __half* whqkv, __half* whout, __half* whf1, __half* whf2)
{
    int b = blockIdx.x;
    if (b < 256) {
        int idx = b * 256 + threadIdx.x;
        int n = idx >> 7, k = idx & 127;
        float w = (n < 256) ? msg_w1[k * 256 + n]
                            : msg_w1[(128 + k) * 256 + (n - 256)];
        whpdps[idx] = __float2half(w);
        return;
    }
    const float* W; __half* Wh; int K, N, base;
    if      (b < 448)  { W = uw;     Wh = whuw;  K = 384; N = 128; base = 256; }
    else if (b < 512)  { W = upd_w2; Wh = whu2;  K = 128; N = 128; base = 448; }
    else if (b < 704)  { W = in_w;   Wh = whqkv; K = 128; N = 384; base = 512; }
    else if (b < 768)  { W = out_w;  Wh = whout; K = 128; N = 128; base = 704; }
    else if (b < 896)  { W = ffn_w1; Wh = whf1;  K = 128; N = 256; base = 768; }
    else               { W = ffn_w2; Wh = whf2;  K = 256; N = 128; base = 896; }
    int idx = (b - base) * 256 + threadIdx.x;
    int k = idx / N, n = idx % N;
    Wh[(size_t)n * K + k] = __float2half(W[idx]);
}

// ---------------------------------------------------------------------------
// LayerNorm (standalone: only used for xn = LN(x)).
// ---------------------------------------------------------------------------
__global__ __launch_bounds__(256) void ln_kernel(
    const float* __restrict__ a, const float* __restrict__ g,
    const float* __restrict__ be, float* __restrict__ out)
{
    int row  = blockIdx.x * 8 + (threadIdx.x >> 5);
    int lane = threadIdx.x & 31;
    size_t off = (size_t)row * 128 + lane * 4;
    float4 v = *(const float4*)(a + off);
    float s  = v.x + v.y + v.z + v.w;
    float ss = v.x*v.x + v.y*v.y + v.z*v.z + v.w*v.w;
    #pragma unroll
    for (int o = 16; o > 0; o >>= 1) {
        s  += __shfl_xor_sync(0xffffffffu, s,  o);
        ss += __shfl_xor_sync(0xffffffffu, ss, o);
    }
    float mean = s * (1.0f / 128.0f);
    float var  = ss * (1.0f / 128.0f) - mean * mean;
    float rstd = rsqrtf(var + 1e-5f);
    float4 gg = *(const float4*)(g  + lane * 4);
    float4 bb = *(const float4*)(be + lane * 4);
    float4 o4;
    o4.x = (v.x - mean) * rstd * gg.x + bb.x;
    o4.y = (v.y - mean) * rstd * gg.y + bb.y;
    o4.z = (v.z - mean) * rstd * gg.z + bb.z;
    o4.w = (v.w - mean) * rstd * gg.w + bb.w;
    *(float4*)(out + off) = o4;
}

// ---------------------------------------------------------------------------
// Small fp32 GEMM (prep only): BM=128, BN=64, BK=16, 256 threads, FFMA2.
// ---------------------------------------------------------------------------
__global__ __launch_bounds__(256) void gemm_kernel(
    const float* __restrict__ A1, int K1,
    const float* __restrict__ B,
    float* __restrict__ C, int M, int NN)
{
    const int T = K1 >> 4;
    __shared__ float As[2][16 * 128];
    __shared__ float Bs[2][16 * 64];
    const int t  = threadIdx.x;
    const int m0 = blockIdx.x * 128;
    const int n0 = blockIdx.y * 64;
    const int mg = t >> 4;
    const int ng = t & 15;
    const int k4own = (t & 3) * 4;
    int rowA[2];
    #pragma unroll
    for (int i = 0; i < 2; i++) rowA[i] = m0 + ((t + i * 256) >> 2);

    float4 ra[2], rb;
    auto ldg_tile = [&](int kt) {
        int kb = kt * 16;
        #pragma unroll
        for (int i = 0; i < 2; i++)
            ra[i] = *(const float4*)(A1 + (size_t)rowA[i] * K1 + kb + k4own);
        int r = t >> 4, c4 = t & 15;
        rb = *(const float4*)(B + (size_t)(kb + r) * NN + n0 + c4 * 4);
    };
    auto sts_tile = [&](int buf) {
        #pragma unroll
        for (int i = 0; i < 2; i++) {
            int cc = t + i * 256;
            int m = cc >> 2, k4 = cc & 3;
            As[buf][(k4 * 4 + 0) * 128 + m] = ra[i].x;
            As[buf][(k4 * 4 + 1) * 128 + m] = ra[i].y;
            As[buf][(k4 * 4 + 2) * 128 + m] = ra[i].z;
            As[buf][(k4 * 4 + 3) * 128 + m] = ra[i].w;
        }
        int r = t >> 4, c4 = t & 15;
        *(float4*)&Bs[buf][r * 64 + c4 * 4] = rb;
    };

    u64 acc[4][4];
    #pragma unroll
    for (int i = 0; i < 4; i++)
        #pragma unroll
        for (int j = 0; j < 4; j++) acc[i][j] = 0ull;

    ldg_tile(0); sts_tile(0);
    for (int kt = 0; kt < T; kt++) {
        __syncthreads();
        if (kt + 1 < T) ldg_tile(kt + 1);
        const float* ap = As[kt & 1];
        const float* bp = Bs[kt & 1];
        #pragma unroll
        for (int k = 0; k < 16; k++) {
            ulonglong2 a01 = *(const ulonglong2*)(ap + k * 128 + mg * 8);
            ulonglong2 a23 = *(const ulonglong2*)(ap + k * 128 + mg * 8 + 4);
            float4 b = *(const float4*)(bp + k * 64 + ng * 4);
            u64 am[4] = {a01.x, a01.y, a23.x, a23.y};
            u64 bd[4] = {dup2(b.x), dup2(b.y), dup2(b.z), dup2(b.w)};
            #pragma unroll
            for (int i = 0; i < 4; i++)
                #pragma unroll
                for (int j = 0; j < 4; j++)
                    fma2(acc[i][j], am[i], bd[j]);
        }
        if (kt + 1 < T) sts_tile((kt + 1) & 1);
    }

    #pragma unroll
    for (int i = 0; i < 4; i++) {
        int r0 = m0 + mg * 8 + 2 * i;
        float2 v0 = unpack2(acc[i][0]);
        float2 v1 = unpack2(acc[i][1]);
        float2 v2 = unpack2(acc[i][2]);
        float2 v3 = unpack2(acc[i][3]);
        *(float4*)(C + (size_t)r0       * NN + n0 + ng * 4) = make_float4(v0.x, v1.x, v2.x, v3.x);
        *(float4*)(C + (size_t)(r0 + 1) * NN + n0 + ng * 4) = make_float4(v0.y, v1.y, v2.y, v3.y);
    }
}

// ---------------------------------------------------------------------------
// HMMA GEMM body with epilogue functor.
// epi(row, col, v0, v1, v2, v3): values for (row,col),(row,col+1),
// (row+8,col),(row+8,col+1). BM=128, BN=128, BK=32, 256 threads.
// ---------------------------------------------------------------------------
template<bool GELU, class Epi>
__device__ __forceinline__ void hgemm_body(
    const float* __restrict__ A1, int K1,
    const float* __restrict__ A2, int K2,
    const __half* __restrict__ Bh,
    const float* __restrict__ bias,
    const float* __restrict__ bias2,
    const float* __restrict__ rowscale,
    int m0, int n0, __half* Ah, __half* Bs, Epi epi)
{
    const int K = K1 + K2;
    const int T = K >> 5;
    const int t = threadIdx.x;

    const int arow = t >> 1, aseg = (t & 1) * 16;
    const int brow = t >> 1, bseg = (t & 1) * 16;

    float4 raf[4];
    uint4 rbu0, rbu1;
    auto ldg_tile = [&](int kb) {
        #pragma unroll
        for (int i = 0; i < 4; i++) {
            int gk = kb + aseg + i * 4;
            const float* src = (gk < K1)
                ? (A1 + (size_t)(m0 + arow) * K1 + gk)
                : (A2 + (size_t)(m0 + arow) * K2 + (gk - K1));
            raf[i] = *(const float4*)src;
        }
        const __half* bsrc = Bh + (size_t)(n0 + brow) * K + kb + bseg;
        rbu0 = *(const uint4*)bsrc;
        rbu1 = *(const uint4*)(bsrc + 8);
    };
    auto sts_tile = [&](int buf) {
        __half2* ad = (__half2*)&Ah[buf * 128 * 40 + arow * 40 + aseg];
        #pragma unroll
        for (int i = 0; i < 4; i++) {
            ad[i * 2]     = __floats2half2_rn(raf[i].x, raf[i].y);
            ad[i * 2 + 1] = __floats2half2_rn(raf[i].z, raf[i].w);
        }
        __half* bd = &Bs[buf * 128 * 40 + brow * 40 + bseg];
        *(uint4*)bd       = rbu0;
        *(uint4*)(bd + 8) = rbu1;
    };

    const int wid = t >> 5, lane = t & 31;
    const int wm = wid & 3;
    const int wn = wid >> 2;
    const int lq = lane >> 2;
    const int lr = lane & 3;

    float d[2][8][4];
    #pragma unroll
    for (int mt = 0; mt < 2; mt++)
        #pragma unroll
        for (int nt = 0; nt < 8; nt++)
            #pragma unroll
            for (int c = 0; c < 4; c++) d[mt][nt][c] = 0.0f;

    ldg_tile(0); sts_tile(0);
    for (int kt = 0; kt < T; kt++) {
        __syncthreads();
        if (kt + 1 < T) ldg_tile((kt + 1) * 32);
        const __half* ap = Ah + (kt & 1) * 128 * 40;
        const __half* bp = Bs + (kt & 1) * 128 * 40;

        uint32_t afr[2][2][4];
        #pragma unroll
        for (int mt = 0; mt < 2; mt++) {
            int r = wm * 32 + mt * 16 + lq;
            #pragma unroll
            for (int ks = 0; ks < 2; ks++) {
                int k = ks * 16 + lr * 2;
                afr[mt][ks][0] = *(const uint32_t*)&ap[r * 40 + k];
                afr[mt][ks][1] = *(const uint32_t*)&ap[(r + 8) * 40 + k];
                afr[mt][ks][2] = *(const uint32_t*)&ap[r * 40 + k + 8];
                afr[mt][ks][3] = *(const uint32_t*)&ap[(r + 8) * 40 + k + 8];
            }
        }
        #pragma unroll
        for (int nt = 0; nt < 8; nt++) {
            int n = wn * 64 + nt * 8 + lq;
            uint32_t b00 = *(const uint32_t*)&bp[n * 40 + lr * 2];
            uint32_t b10 = *(const uint32_t*)&bp[n * 40 + lr * 2 + 8];
            uint32_t b01 = *(const uint32_t*)&bp[n * 40 + 16 + lr * 2];
            uint32_t b11 = *(const uint32_t*)&bp[n * 40 + 16 + lr * 2 + 8];
            #pragma unroll
            for (int mt = 0; mt < 2; mt++) {
                mma16816(d[mt][nt], afr[mt][0], b00, b10);
                mma16816(d[mt][nt], afr[mt][1], b01, b11);
            }
        }
        if (kt + 1 < T) sts_tile((kt + 1) & 1);
    }

    #pragma unroll
    for (int mt = 0; mt < 2; mt++) {
        int row = m0 + wm * 32 + mt * 16 + lq;
        float rs0 = rowscale ? rowscale[row]     : 0.0f;
        float rs8 = rowscale ? rowscale[row + 8] : 0.0f;
        #pragma unroll
        for (int nt = 0; nt < 8; nt++) {
            int col = n0 + wn * 64 + nt * 8 + lr * 2;
            float b0v = bias ? bias[col]     : 0.0f;
            float b1v = bias ? bias[col + 1] : 0.0f;
            float c0  = bias2 ? bias2[col]     : 0.0f;
            float c1  = bias2 ? bias2[col + 1] : 0.0f;
            float v0 = d[mt][nt][0] + b0v + rs0 * c0;
            float v1 = d[mt][nt][1] + b1v + rs0 * c1;
            float v2 = d[mt][nt][2] + b0v + rs8 * c0;
            float v3 = d[mt][nt][3] + b1v + rs8 * c1;
            if (GELU) {
                v0 = gelu_f(v0); v1 = gelu_f(v1);
                v2 = gelu_f(v2); v3 = gelu_f(v3);
            }
            epi(row, col, v0, v1, v2, v3);
        }
    }
}

// fp32-out wrapper (upd1, ffn1)
template<bool GELU>
__global__ __launch_bounds__(256) void hgemm_kernel(
    const float* __restrict__ A1, int K1,
    const float* __restrict__ A2, int K2,
    const __half* __restrict__ Bh,
    const float* __restrict__ bias,
    const float* __restrict__ bias2,
    const float* __restrict__ rowscale,
    float* __restrict__ C, int NN)
{
    __shared__ __align__(16) __half Ah[2 * 128 * 40];
    __shared__ __align__(16) __half Bs[2 * 128 * 40];
    hgemm_body<GELU>(A1, K1, A2, K2, Bh, bias, bias2, rowscale,
        blockIdx.x * 128, blockIdx.y * 128, Ah, Bs,
        [&](int row, int col, float v0, float v1, float v2, float v3) {
            *(float2*)(C + (size_t)row       * NN + col) = make_float2(v0, v1);
            *(float2*)(C + (size_t)(row + 8) * NN + col) = make_float2(v2, v3);
        });
}

// Combined pdps (y<4) + qkv (y>=4) launch, both fp16-out.
__global__ __launch_bounds__(256) void pdps_qkv_kernel(
    const float* __restrict__ xn, const __half* __restrict__ whpdps,
    __half* __restrict__ pdps,
    const float* __restrict__ x, const __half* __restrict__ whqkv,
    const float* __restrict__ in_b, __half* __restrict__ qkvh)
{
    __shared__ __align__(16) __half Ah[2 * 128 * 40];
    __shared__ __align__(16) __half Bs[2 * 128 * 40];
    if (blockIdx.y < 4) {
        __half* C = pdps;
        hgemm_body<false>(xn, 128, nullptr, 0, whpdps, nullptr, nullptr,
            nullptr, blockIdx.x * 128, blockIdx.y * 128, Ah, Bs,
            [&](int row, int col, float v0, float v1, float v2, float v3) {
                *(__half2*)(C + (size_t)row       * 512 + col) = __floats2half2_rn(v0, v1);
                *(__half2*)(C + (size_t)(row + 8) * 512 + col) = __floats2half2_rn(v2, v3);
            });
    } else {
        __half* C = qkvh;
        hgemm_body<false>(x, 128, nullptr, 0, whqkv, in_b, nullptr,
            nullptr, blockIdx.x * 128, (blockIdx.y - 4) * 128, Ah, Bs,
            [&](int row, int col, float v0, float v1, float v2, float v3) {
                *(__half2*)(C + (size_t)row       * 384 + col) = __floats2half2_rn(v0, v1);
                *(__half2*)(C + (size_t)(row + 8) * 384 + col) = __floats2half2_rn(v2, v3);
            });
    }
}

// Fused: h1 = LN( x + t1@U2+b2 + obuf@Wout+bout ) with n1 params.
// One block per 128 rows; two sequential GEMMs into a smem tile, then LN.
__global__ __launch_bounds__(256) void upd2_out_ln_kernel(
    const float* __restrict__ t1, const __half* __restrict__ whu2,
    const float* __restrict__ upd_b2,
    const float* __restrict__ obuf, const __half* __restrict__ whout,
    const float* __restrict__ out_b,
    const float* __restrict__ x,
    const float* __restrict__ n1_g, const float* __restrict__ n1_b,
    float* __restrict__ h1)
{
    __shared__ __align__(16) __half Ah[2 * 128 * 40];
    __shared__ __align__(16) __half Bs[2 * 128 * 40];
    extern __shared__ float Gs[];          // [128][132]
    const int m0 = blockIdx.x * 128;

    hgemm_body<false>(t1, 128, nullptr, 0, whu2, upd_b2, nullptr, nullptr,
        m0, 0, Ah, Bs,
        [&](int row, int col, float v0, float v1, float v2, float v3) {
            int rl = row - m0;
            float2 x0 = *(const float2*)(x + (size_t)row       * 128 + col);
            float2 x8 = *(const float2*)(x + (size_t)(row + 8) * 128 + col);
            Gs[rl * 132 + col]           = v0 + x0.x;
            Gs[rl * 132 + col + 1]       = v1 + x0.y;
            Gs[(rl + 8) * 132 + col]     = v2 + x8.x;
            Gs[(rl + 8) * 132 + col + 1] = v3 + x8.y;
        });
    __syncthreads();
    hgemm_body<false>(obuf, 128, nullptr, 0, whout, out_b, nullptr, nullptr,
        m0, 0, Ah, Bs,
        [&](int row, int col, float v0, float v1, float v2, float v3) {
            int rl = row - m0;
            Gs[rl * 132 + col]           += v0;
            Gs[rl * 132 + col + 1]       += v1;
            Gs[(rl + 8) * 132 + col]     += v2;
            Gs[(rl + 8) * 132 + col + 1] += v3;
        });
    __syncthreads();

    // LN per row (8 warps x 16 rows)
    const int t = threadIdx.x, w = t >> 5, lane = t & 31;
    float4 gg = *(const float4*)(n1_g + lane * 4);
    float4 bb = *(const float4*)(n1_b + lane * 4);
    #pragma unroll 4
    for (int i = 0; i < 16; i++) {
        int r = w * 16 + i;
        float4 v = *(const float4*)&Gs[r * 132 + lane * 4];
        float s  = v.x + v.y + v.z + v.w;
        float ss = v.x*v.x + v.y*v.y + v.z*v.z + v.w*v.w;
        #pragma unroll
        for (int o = 16; o > 0; o >>= 1) {
            s  += __shfl_xor_sync(0xffffffffu, s,  o);
            ss += __shfl_xor_sync(0xffffffffu, ss, o);
        }
        float mean = s * (1.0f / 128.0f);
        float var  = ss * (1.0f / 128.0f) - mean * mean;
        float rstd = rsqrtf(var + 1e-5f);
        float4 o4;
        o4.x = (v.x - mean) * rstd * gg.x + bb.x;
        o4.y = (v.y - mean) * rstd * gg.y + bb.y;
        o4.z = (v.z - mean) * rstd * gg.z + bb.z;
        o4.w = (v.w - mean) * rstd * gg.w + bb.w;
        *(float4*)(h1 + (size_t)(m0 + r) * 128 + lane * 4) = o4;
    }
}

// Fused: out = LN( h1 + ffn@W2+b2 ) with n2 params.
__global__ __launch_bounds__(256) void ffn_ln_kernel(
    const float* __restrict__ ffnb, const __half* __restrict__ whf2,
    const float* __restrict__ ffn_b2,
    const float* __restrict__ h1,
    const float* __restrict__ n2_g, const float* __restrict__ n2_b,
    float* __restrict__ out)
{
    __shared__ __align__(16) __half Ah[2 * 128 * 40];
    __shared__ __align__(16) __half Bs[2 * 128 * 40];
    extern __shared__ float Gs[];          // [128][132]
    const int m0 = blockIdx.x * 128;

    hgemm_body<false>(ffnb, 256, nullptr, 0, whf2, ffn_b2, nullptr, nullptr,
        m0, 0, Ah, Bs,
        [&](int row, int col, float v0, float v1, float v2, float v3) {
            int rl = row - m0;
            float2 h0 = *(const float2*)(h1 + (size_t)row       * 128 + col);
            float2 h8 = *(const float2*)(h1 + (size_t)(row + 8) * 128 + col);
            Gs[rl * 132 + col]           = v0 + h0.x;
            Gs[rl * 132 + col + 1]       = v1 + h0.y;
            Gs[(rl + 8) * 132 + col]     = v2 + h8.x;
            Gs[(rl + 8) * 132 + col + 1] = v3 + h8.y;
        });
    __syncthreads();

    const int t = threadIdx.x, w = t >> 5, lane = t & 31;
    float4 gg = *(const float4*)(n2_g + lane * 4);
    float4 bb = *(const float4*)(n2_b + lane * 4);
    #pragma unroll 4
    for (int i = 0; i < 16; i++) {
        int r = w * 16 + i;
        float4 v = *(const float4*)&Gs[r * 132 + lane * 4];
        float s  = v.x + v.y + v.z + v.w;
        float ss = v.x*v.x + v.y*v.y + v.z*v.z + v.w*v.w;
        #pragma unroll
        for (int o = 16; o > 0; o >>= 1) {
            s  += __shfl_xor_sync(0xffffffffu, s,  o);
            ss += __shfl_xor_sync(0xffffffffu, ss, o);
        }
        float mean = s * (1.0f / 128.0f);
        float var  = ss * (1.0f / 128.0f) - mean * mean;
        float rstd = rsqrtf(var + 1e-5f);
        float4 o4;
        o4.x = (v.x - mean) * rstd * gg.x + bb.x;
        o4.y = (v.y - mean) * rstd * gg.y + bb.y;
        o4.z = (v.z - mean) * rstd * gg.z + bb.z;
        o4.w = (v.w - mean) * rstd * gg.w + bb.w;
        *(float4*)(out + (size_t)(m0 + r) * 128 + lane * 4) = o4;
    }
}

// ---------------------------------------------------------------------------
// Fused edge kernel + in-block segmented reduce (pdps fp16).
// ---------------------------------------------------------------------------
__global__ __launch_bounds__(256) void edge_fused_kernel(
    const float* __restrict__ ea, const int* __restrict__ eperm,
    const float* __restrict__ W1c, const float* __restrict__ b1,
    const __half* __restrict__ pdps,
    const int* __restrict__ sdst, const int* __restrict__ ssrc,
    float* __restrict__ aggrH)
{
    extern __shared__ __align__(16) char smraw[];
    __half* Ws  = (__half*)smraw;                  // [256][36]
    __half* As  = Ws + 256 * 36;                   // [64][36]
    __half* Gsm = As + 64 * 36;                    // [64][264]
    float*  b1s = (float*)(Gsm + 64 * 264);        // [256]
    int*    ds  = (int*)(b1s + 256);               // [64]
    const int t  = threadIdx.x;
    const int e0 = blockIdx.x * 64;

    {
        int n = t;
        b1s[n] = b1[n];
        #pragma unroll
        for (int k = 0; k < 32; k++)
            Ws[n * 36 + k] = __float2half(W1c[k * 256 + n]);
    }
    {
        int el = t >> 2, part = t & 3;
        int e = eperm[e0 + el];
        const float4* src = (const float4*)(ea + (size_t)e * 32 + part * 8);
        float4 v0 = src[0], v1 = src[1];
        __half2* dst = (__half2*)(As + el * 36 + part * 8);
        dst[0] = __floats2half2_rn(v0.x, v0.y);
        dst[1] = __floats2half2_rn(v0.z, v0.w);
        dst[2] = __floats2half2_rn(v1.x, v1.y);
        dst[3] = __floats2half2_rn(v1.z, v1.w);
    }
    if (t < 64) ds[t] = sdst[e0 + t];
    __syncthreads();

    const int wid = t >> 5, lane = t & 31;
    const int wm = wid >> 2;
    const int wn = wid & 3;
    const int lq = lane >> 2;
    const int lr = lane & 3;

    float d[2][8][4];
    #pragma unroll
    for (int mt = 0; mt < 2; mt++)
        #pragma unroll
        for (int nt = 0; nt < 8; nt++)
            #pragma unroll
            for (int c = 0; c < 4; c++) d[mt][nt][c] = 0.0f;

    uint32_t afr[2][2][4];
    #pragma unroll
    for (int mt = 0; mt < 2; mt++) {
        int r = wm * 32 + mt * 16 + lq;
        #pragma unroll
        for (int ks = 0; ks < 2; ks++) {
            int k = ks * 16 + lr * 2;
            afr[mt][ks][0] = *(const uint32_t*)&As[r * 36 + k];
            afr[mt][ks][1] = *(const uint32_t*)&As[(r + 8) * 36 + k];
            afr[mt][ks][2] = *(const uint32_t*)&As[r * 36 + k + 8];
            afr[mt][ks][3] = *(const uint32_t*)&As[(r + 8) * 36 + k + 8];
        }
    }

    #pragma unroll
    for (int nt = 0; nt < 8; nt++) {
        int n = wn * 64 + nt * 8 + lq;
        uint32_t b0k0 = *(const uint32_t*)&Ws[n * 36 + lr * 2];
        uint32_t b1k0 = *(const uint32_t*)&Ws[n * 36 + lr * 2 + 8];
        uint32_t b0k1 = *(const uint32_t*)&Ws[n * 36 + 16 + lr * 2];
        uint32_t b1k1 = *(const uint32_t*)&Ws[n * 36 + 16 + lr * 2 + 8];
        #pragma unroll
        for (int mt = 0; mt < 2; mt++) {
            mma16816(d[mt][nt], afr[mt][0], b0k0, b1k0);
            mma16816(d[mt][nt], afr[mt][1], b0k1, b1k1);
        }
    }

    #pragma unroll
    for (int mt = 0; mt < 2; mt++) {
        int l0 = wm * 32 + mt * 16 + lq;
        int l8 = l0 + 8;
        int j0 = e0 + l0, j8 = e0 + l8;
        const __half* pd0 = pdps + (size_t)sdst[j0] * 512;
        const __half* ps0 = pdps + (size_t)ssrc[j0] * 512 + 256;
        const __half* pd8 = pdps + (size_t)sdst[j8] * 512;
        const __half* ps8 = pdps + (size_t)ssrc[j8] * 512 + 256;
        #pragma unroll
        for (int nt = 0; nt < 8; nt++) {
            int col = wn * 64 + nt * 8 + lr * 2;
            float2 a0 = __half22float2(*(const __half2*)(pd0 + col));
            float2 s0 = __half22float2(*(const __half2*)(ps0 + col));
            float2 a8 = __half22float2(*(const __half2*)(pd8 + col));
            float2 s8 = __half22float2(*(const __half2*)(ps8 + col));
            float bx = b1s[col], by = b1s[col + 1];
            float v0 = gelu_f(d[mt][nt][0] + bx + a0.x + s0.x);
            float v1 = gelu_f(d[mt][nt][1] + by + a0.y + s0.y);
            float v2 = gelu_f(d[mt][nt][2] + bx + a8.x + s8.x);
            float v3 = gelu_f(d[mt][nt][3] + by + a8.y + s8.y);
            *(__half2*)(Gsm + l0 * 264 + col) = __floats2half2_rn(v0, v1);
            *(__half2*)(Gsm + l8 * 264 + col) = __floats2half2_rn(v2, v3);
        }
    }
    __syncthreads();

    {
        int c = t;
        float acc = 0.0f;
        int prev = ds[0];
        #pragma unroll 8
        for (int r = 0; r < 64; r++) {
            int nd = ds[r];
            if (nd != prev) {
                atomicAdd(&aggrH[(size_t)prev * 256 + c], acc);
                acc = 0.0f;
                prev = nd;
            }
            acc += __half2float(Gsm[r * 264 + c]);
        }
        atomicAdd(&aggrH[(size_t)prev * 256 + c], acc);
    }
}

// ---------------------------------------------------------------------------
// b2u[n] = sum_k msg_b2[k] * U1b[k][n]
// ---------------------------------------------------------------------------
__global__ __launch_bounds__(128) void bias2_kernel(
    const float* __restrict__ b2, const float* __restrict__ U1b,
    float* __restrict__ out)
{
    int n = threadIdx.x;
    float s = 0.0f;
    for (int k = 0; k < 128; k++) s = fmaf(b2[k], U1b[k * 128 + n], s);
    out[n] = s;
}

// ---------------------------------------------------------------------------
// Counting sort of edges by dst
// ---------------------------------------------------------------------------
__global__ __launch_bounds__(256) void hist_kernel(
    const int* __restrict__ dstp, int* __restrict__ cnt)
{
    int e = blockIdx.x * 256 + threadIdx.x;
    atomicAdd(&cnt[dstp[e]], 1);
}

__global__ __launch_bounds__(1024) void scan_local_kernel(
    const int* __restrict__ cnt, int* __restrict__ offs,
    float* __restrict__ degf, int* __restrict__ bsum)
{
    __shared__ int wsum[32];
    int t = threadIdx.x;
    int i0 = blockIdx.x * 2048 + t * 2;
    int c0 = cnt[i0], c1 = cnt[i0 + 1];
    int s = c0 + c1;
    int lane = t & 31, wid = t >> 5;
    int v = s;
    #pragma unroll
    for (int o = 1; o < 32; o <<= 1) {
        int u = __shfl_up_sync(0xffffffffu, v, o);
        if (lane >= o) v += u;
    }
    if (lane == 31) wsum[wid] = v;
    __syncthreads();
    if (wid == 0) {
        int w = wsum[lane];
        #pragma unroll
        for (int o = 1; o < 32; o <<= 1) {
            int u = __shfl_up_sync(0xffffffffu, w, o);
            if (lane >= o) w += u;
        }
        wsum[lane] = w;
    }
    __syncthreads();
    int ex = (wid ? wsum[wid - 1] : 0) + (v - s);
    offs[i0]     = ex;
    offs[i0 + 1] = ex + c0;
    degf[i0]     = (float)c0;
    degf[i0 + 1] = (float)c1;
    if (t == 0) bsum[blockIdx.x] = wsum[31];
}

__global__ __launch_bounds__(1024) void scan_fix_kernel(
    int* __restrict__ offs, int* __restrict__ cursor,
    const int* __restrict__ bsum)
{
    int i = blockIdx.x * 1024 + threadIdx.x;
    int b = i >> 11;
    int add = 0;
    #pragma unroll
    for (int k = 0; k < 8; k++) if (k < b) add += bsum[k];
    int v = offs[i] + add;
    offs[i] = v;
    cursor[i] = v;
    if (i == 0) offs[NV] = EV;
}

__global__ __launch_bounds__(256) void scatter_kernel(
    const int* __restrict__ dstp, const int* __restrict__ srcp,
    int* __restrict__ cursor, int* __restrict__ eperm,
    int* __restrict__ ssrc, int* __restrict__ sdst)
{
    int e = blockIdx.x * 256 + threadIdx.x;
    int d = dstp[e];
    int pos = atomicAdd(&cursor[d], 1);
    eperm[pos] = e;
    ssrc[pos]  = srcp[e];
    sdst[pos]  = d;
}

// ---------------------------------------------------------------------------
// Flash attention via HMMA, qkv in fp16.
// ---------------------------------------------------------------------------
#define VTS 514
__global__ __launch_bounds__(128) void attn_flash_kernel(
    const __half* __restrict__ qkv, float* __restrict__ o)
{
    extern __shared__ __half smh[];
    __half* Ks = smh;                       // [512][40]
    __half* Vt = smh + 512 * 40;            // [32][VTS]
    __half* Qs = Vt + 32 * VTS;             // [64][40]
    const int t  = threadIdx.x;
    const int b  = blockIdx.x;
    const int g  = b >> 5;
    const int h  = (b >> 3) & 3;
    const int qb = b & 7;
    const size_t gb = (size_t)g * 512;
    const float scale = 0.17677669529663687f;

    #pragma unroll
    for (int i = 0; i < 32; i++) {
        int task = t + i * 128;
        int row = task >> 3, seg = task & 7;
        uint2 v = *(const uint2*)(qkv + (gb + row) * 384 + 128 + h * 32 + seg * 4);
        *(uint2*)&Ks[row * 40 + seg * 4] = v;
    }
    #pragma unroll
    for (int i = 0; i < 32; i++) {
        int task = t + i * 128;
        int row = task >> 3, seg = task & 7;
        const __half* src = qkv + (gb + row) * 384 + 256 + h * 32 + seg * 4;
        int d0 = seg * 4;
        Vt[(d0 + 0) * VTS + row] = src[0];
        Vt[(d0 + 1) * VTS + row] = src[1];
        Vt[(d0 + 2) * VTS + row] = src[2];
        Vt[(d0 + 3) * VTS + row] = src[3];
    }
    #pragma unroll
    for (int i = 0; i < 4; i++) {
        int task = t + i * 128;
        int row = task >> 3, seg = task & 7;
        const __half2* src = (const __half2*)(qkv + (gb + qb * 64 + row) * 384 + h * 32 + seg * 4);
        float2 v0 = __half22float2(src[0]);
        float2 v1 = __half22float2(src[1]);
        __half2* d = (__half2*)&Qs[row * 40 + seg * 4];
        d[0] = __floats2half2_rn(v0.x * scale, v0.y * scale);
        d[1] = __floats2half2_rn(v1.x * scale, v1.y * scale);
    }
    __syncthreads();

    const int wq = t >> 5, lane = t & 31;
    const int lq = lane >> 2, lr = lane & 3;

    uint32_t aq[2][4];
    #pragma unroll
    for (int ks = 0; ks < 2; ks++) {
        int base = (wq * 16 + lq) * 40 + ks * 16 + lr * 2;
        aq[ks][0] = *(const uint32_t*)&Qs[base];
        aq[ks][1] = *(const uint32_t*)&Qs[base + 8 * 40];
        aq[ks][2] = *(const uint32_t*)&Qs[base + 8];
        aq[ks][3] = *(const uint32_t*)&Qs[base + 8 * 40 + 8];
    }

    float m0 = -1e30f, m1 = -1e30f, l0 = 0.0f, l1 = 0.0f;
    float oA[4][4];
    #pragma unroll
    for (int n = 0; n < 4; n++)
        #pragma unroll
        for (int c = 0; c < 4; c++) oA[n][c] = 0.0f;

    for (int c = 0; c < 8; c++) {
        float s[8][4];
        #pragma unroll
        for (int nt = 0; nt < 8; nt++)
            #pragma unroll
            for (int q = 0; q < 4; q++) s[nt][q] = 0.0f;
        #pragma unroll
        for (int nt = 0; nt < 8; nt++) {
            int kb = (c * 64 + nt * 8 + lq) * 40 + lr * 2;
            mma16816(s[nt], aq[0], *(const uint32_t*)&Ks[kb],
                                    *(const uint32_t*)&Ks[kb + 8]);
            mma16816(s[nt], aq[1], *(const uint32_t*)&Ks[kb + 16],
                                    *(const uint32_t*)&Ks[kb + 24]);
        }
        float mc0 = -1e30f, mc1 = -1e30f;
        #pragma unroll
        for (int nt = 0; nt < 8; nt++) {
            mc0 = fmaxf(mc0, fmaxf(s[nt][0], s[nt][1]));
            mc1 = fmaxf(mc1, fmaxf(s[nt][2], s[nt][3]));
        }
        mc0 = fmaxf(mc0, __shfl_xor_sync(0xffffffffu, mc0, 1));
        mc0 = fmaxf(mc0, __shfl_xor_sync(0xffffffffu, mc0, 2));
        mc1 = fmaxf(mc1, __shfl_xor_sync(0xffffffffu, mc1, 1));
        mc1 = fmaxf(mc1, __shfl_xor_sync(0xffffffffu, mc1, 2));
        float mn0 = fmaxf(m0, mc0), mn1 = fmaxf(m1, mc1);
        float cr0 = __expf(m0 - mn0), cr1 = __expf(m1 - mn1);
        m0 = mn0; m1 = mn1;
        float rs0 = 0.0f, rs1 = 0.0f;
        #pragma unroll
        for (int nt = 0; nt < 8; nt++) {
            s[nt][0] = __expf(s[nt][0] - m0); rs0 += s[nt][0];
            s[nt][1] = __expf(s[nt][1] - m0); rs0 += s[nt][1];
            s[nt][2] = __expf(s[nt][2] - m1); rs1 += s[nt][2];
            s[nt][3] = __expf(s[nt][3] - m1); rs1 += s[nt][3];
        }
        rs0 += __shfl_xor_sync(0xffffffffu, rs0, 1);
        rs0 += __shfl_xor_sync(0xffffffffu, rs0, 2);
        rs1 += __shfl_xor_sync(0xffffffffu, rs1, 1);
        rs1 += __shfl_xor_sync(0xffffffffu, rs1, 2);
        l0 = l0 * cr0 + rs0;
        l1 = l1 * cr1 + rs1;
        #pragma unroll
        for (int n = 0; n < 4; n++) {
            oA[n][0] *= cr0; oA[n][1] *= cr0;
            oA[n][2] *= cr1; oA[n][3] *= cr1;
        }
        #pragma unroll
        for (int kt = 0; kt < 4; kt++) {
            uint32_t a[4];
            a[0] = packh2(s[2 * kt][0],     s[2 * kt][1]);
            a[1] = packh2(s[2 * kt][2],     s[2 * kt][3]);
            a[2] = packh2(s[2 * kt + 1][0], s[2 * kt + 1][1]);
            a[3] = packh2(s[2 * kt + 1][2], s[2 * kt + 1][3]);
            #pragma unroll
            for (int nd = 0; nd < 4; nd++) {
                int vb = (nd * 8 + lq) * VTS + c * 64 + kt * 16 + lr * 2;
                mma16816(oA[nd], a, *(const uint32_t*)&Vt[vb],
                                     *(const uint32_t*)&Vt[vb + 8]);
            }
        }
    }

    float i0 = 1.0f / l0, i1 = 1.0f / l1;
    int row = qb * 64 + wq * 16 + lq;
    float* orow = o + (gb + row) * 128 + h * 32;
    #pragma unroll
    for (int nd = 0; nd < 4; nd++) {
        *(float2*)(orow + nd * 8 + lr * 2) =
            make_float2(oA[nd][0] * i0, oA[nd][1] * i0);
        *(float2*)(orow + 8 * 128 + nd * 8 + lr * 2) =
            make_float2(oA[nd][2] * i1, oA[nd][3] * i1);
    }
}

// ---------------------------------------------------------------------------
// Host launcher
// ---------------------------------------------------------------------------
extern "C" void kernel_launch(void* const* d_in, const int* in_sizes, int n_in,
                              void* d_out, int out_size)
{
    const float* x      = (const float*)d_in[0];
    const int*   eidx   = (const int*)  d_in[1];
    const float* ea     = (const float*)d_in[2];
    /* d_in[3] = batch (unused) */
    const float* gnn_g  = (const float*)d_in[4];
    const float* gnn_b  = (const float*)d_in[5];
    const float* msg_w1 = (const float*)d_in[6];
    const float* msg_b1 = (const float*)d_in[7];
    const float* msg_w2 = (const float*)d_in[8];
    const float* msg_b2 = (const float*)d_in[9];
    const float* upd_w1 = (const float*)d_in[10];
    const float* upd_b1 = (const float*)d_in[11];
    const float* upd_w2 = (const float*)d_in[12];
    const float* upd_b2 = (const float*)d_in[13];
    const float* in_w   = (const float*)d_in[14];
    const float* in_b   = (const float*)d_in[15];
    const float* out_w  = (const float*)d_in[16];
    const float* out_b  = (const float*)d_in[17];
    const float* ffn_w1 = (const float*)d_in[18];
    const float* ffn_b1 = (const float*)d_in[19];
    const float* ffn_w2 = (const float*)d_in[20];
    const float* ffn_b2 = (const float*)d_in[21];
    const float* n1_g   = (const float*)d_in[22];
    const float* n1_b   = (const float*)d_in[23];
    const float* n2_g   = (const float*)d_in[24];
    const float* n2_b   = (const float*)d_in[25];
    float* out = (float*)d_out;

    const int* srcp = eidx;
    const int* dstp = eidx + EV;

    float *xn, *aggrH, *t1, *obuf, *h1, *ffn, *deg, *uw, *b2u;
    __half *pdps, *qkvh, *whpdps, *whuw, *whu2, *whqkv, *whout, *whf1, *whf2;
    int *cnt, *offs, *cursor, *eperm, *ssrc, *sdst, *bsum;
    cudaGetSymbolAddress((void**)&xn,    g_xn);
    cudaGetSymbolAddress((void**)&pdps,  g_pdps);
    cudaGetSymbolAddress((void**)&aggrH, g_aggrH);
    cudaGetSymbolAddress((void**)&t1,    g_t1);
    cudaGetSymbolAddress((void**)&qkvh,  g_qkvh);
    cudaGetSymbolAddress((void**)&obuf,  g_obuf);
    cudaGetSymbolAddress((void**)&h1,    g_h1);
    cudaGetSymbolAddress((void**)&ffn,   g_ffn);
    cudaGetSymbolAddress((void**)&deg,   g_deg);
    cudaGetSymbolAddress((void**)&uw,    g_uw);
    cudaGetSymbolAddress((void**)&b2u,   g_b2u);
    cudaGetSymbolAddress((void**)&cnt,   g_cnt);
    cudaGetSymbolAddress((void**)&offs,  g_offs);
    cudaGetSymbolAddress((void**)&cursor,g_cursor);
    cudaGetSymbolAddress((void**)&eperm, g_eperm);
    cudaGetSymbolAddress((void**)&ssrc,  g_ssrc);
    cudaGetSymbolAddress((void**)&sdst,  g_sdst);
    cudaGetSymbolAddress((void**)&bsum,  g_bsum);
    cudaGetSymbolAddress((void**)&whpdps,g_wh_pdps);
    cudaGetSymbolAddress((void**)&whuw,  g_wh_uw);
    cudaGetSymbolAddress((void**)&whu2,  g_wh_u2);
    cudaGetSymbolAddress((void**)&whqkv, g_wh_qkv);
    cudaGetSymbolAddress((void**)&whout, g_wh_out);
    cudaGetSymbolAddress((void**)&whf1,  g_wh_f1);
    cudaGetSymbolAddress((void**)&whf2,  g_wh_f2);

    cudaFuncSetAttribute(attn_flash_kernel,
                         cudaFuncAttributeMaxDynamicSharedMemorySize, 78976);
    cudaFuncSetAttribute(edge_fused_kernel,
                         cudaFuncAttributeMaxDynamicSharedMemorySize, 58112);
    cudaFuncSetAttribute(upd2_out_ln_kernel,
                         cudaFuncAttributeMaxDynamicSharedMemorySize, 67584);
    cudaFuncSetAttribute(ffn_ln_kernel,
                         cudaFuncAttributeMaxDynamicSharedMemorySize, 67584);

    // 0) independent memsets first (off the critical path)
    cudaMemsetAsync(aggrH, 0, (size_t)NV * 256 * sizeof(float), 0);
    cudaMemsetAsync(cnt, 0, NV * sizeof(int), 0);

    // 1) weight prep
    cudaMemcpyAsync(uw, upd_w1, 128 * 128 * sizeof(float),
                    cudaMemcpyDeviceToDevice, 0);
    gemm_kernel<<<dim3(2, 2), 256>>>(msg_w2, 128, upd_w1 + 128 * 128,
                                     uw + 128 * 128, 256, 128);
    bias2_kernel<<<1, 128>>>(msg_b2, upd_w1 + 128 * 128, b2u);
    convw_all_kernel<<<1024, 256>>>(
        msg_w1, uw, upd_w2, in_w, out_w, ffn_w1, ffn_w2,
        whpdps, whuw, whu2, whqkv, whout, whf1, whf2);

    // 2) counting sort of edges by dst
    hist_kernel<<<EV / 256, 256>>>(dstp, cnt);
    scan_local_kernel<<<8, 1024>>>(cnt, offs, deg, bsum);
    scan_fix_kernel<<<16, 1024>>>(offs, cursor, bsum);
    scatter_kernel<<<EV / 256, 256>>>(dstp, srcp, cursor, eperm, ssrc, sdst);

    // 3) xn = LN(x)
    ln_kernel<<<NV / 8, 256>>>(x, gnn_g, gnn_b, xn);

    // 4) combined [Pd|Ps] table + qkv projection in ONE launch (fp16 out)
    pdps_qkv_kernel<<<dim3(NV / 128, 7), 256>>>(
        xn, whpdps, pdps, x, whqkv, in_b, qkvh);

    // 5) fused edge MLP + gelu + in-block segmented reduce -> aggrH
    edge_fused_kernel<<<EV / 64, 256, 58112>>>(
        ea, eperm, msg_w1 + 256 * 256, msg_b1, pdps, sdst, ssrc, aggrH);

    // 6) flash attention (independent of edge path)
    attn_flash_kernel<<<1024, 128, 78976>>>(qkvh, obuf);

    // 7) fused update-MLP layer 1
    hgemm_kernel<true><<<dim3(NV / 128, 1), 256>>>(
        xn, 128, aggrH, 256, whuw, upd_b1, b2u, deg, t1, 128);

    // 8) fused: h1 = LN(x + upd2(t1) + outproj(obuf))
    upd2_out_ln_kernel<<<NV / 128, 256, 67584>>>(
        t1, whu2, upd_b2, obuf, whout, out_b, x, n1_g, n1_b, h1);

    // 9) FFN layer 1
    hgemm_kernel<true><<<dim3(NV / 128, 2), 256>>>(
        h1, 128, nullptr, 0, whf1, ffn_b1, nullptr, nullptr, ffn, 256);

    // 10) fused: out = LN(h1 + ffn2(ffn))
    ffn_ln_kernel<<<NV / 128, 256, 67584>>>(
        ffn, whf2, ffn_b2, h1, n2_g, n2_b, out);
}

// round 13
// speedup vs baseline: 1.0048x; 1.0048x over previous
#include <cuda_runtime.h>
#include <cuda_fp16.h>
#include <math.h>
#include <cstdint>

// ---------------------------------------------------------------------------
// Problem constants
// ---------------------------------------------------------------------------
#define NV   16384      // nodes
#define DV   128        // node dim
#define EDV  32         // edge feat dim
#define EV   262144     // edges
#define GV   32         // graphs
#define SV   512        // seq per graph
#define HV   4          // heads
#define HDV  32         // head dim

// ---------------------------------------------------------------------------
// Scratch buffers (device globals; no runtime allocation allowed)
// ---------------------------------------------------------------------------
__device__ float  g_xn   [NV * DV];
__device__ __half g_pdps [NV * 512];    // [Pd | Ps] per node, fp16
__device__ float  g_aggrH[NV * 256];
__device__ float  g_t1   [NV * DV];
__device__ __half g_qkvh [NV * 3 * DV]; // qkv fp16
__device__ float  g_obuf [NV * DV];
__device__ float  g_h1   [NV * DV];
__device__ float  g_ffn  [NV * 2 * DV];
__device__ float  g_uw   [384 * 128];   // [U1a ; W2@U1b]
__device__ float  g_b2u  [128];         // msg_b2 @ U1b
__device__ float  g_bcat [128];         // upd_b2 + out_b
__device__ int    g_cnt   [NV];
__device__ int    g_offs  [NV + 1];
__device__ int    g_cursor[NV];
__device__ int    g_eperm [EV];
__device__ int    g_ssrc  [EV];
__device__ int    g_sdst  [EV];
__device__ float  g_deg   [NV];
__device__ int    g_bsum  [8];

// fp16 transposed weight tables [N][K]
__device__ __half g_wh_pdps [512 * 128];
__device__ __half g_wh_uw   [128 * 384];
__device__ __half g_wh_u2out[128 * 256];  // [n][k]: k<128 -> U2, k>=128 -> Wout
__device__ __half g_wh_qkv  [384 * 128];
__device__ __half g_wh_f1   [256 * 128];
__device__ __half g_wh_f2   [128 * 256];
__device__ __half g_wh_w1c  [256 * 32];   // W1c transposed [n][k] fp16

// ---------------------------------------------------------------------------
// f32x2 packed-math helpers
// ---------------------------------------------------------------------------
typedef unsigned long long u64;

__device__ __forceinline__ u64 dup2(float x) {
    u64 r; asm("mov.b64 %0, {%1, %1};" : "=l"(r) : "f"(x)); return r;
}
__device__ __forceinline__ float2 unpack2(u64 v) {
    float2 r; asm("mov.b64 {%0, %1}, %2;" : "=f"(r.x), "=f"(r.y) : "l"(v)); return r;
}
__device__ __forceinline__ void fma2(u64& d, u64 a, u64 b) {
    asm("fma.rn.f32x2 %0, %1, %2, %0;" : "+l"(d) : "l"(a), "l"(b));
}

__device__ __forceinline__ float gelu_f(float v) {
    return 0.5f * v * (1.0f + erff(v * 0.70710678118654752f));
}

__device__ __forceinline__ void mma16816(
    float* d, const uint32_t* a, uint32_t b0, uint32_t b1)
{
    asm volatile(
        "mma.sync.aligned.m16n8k16.row.col.f32.f16.f16.f32 "
        "{%0,%1,%2,%3}, {%4,%5,%6,%7}, {%8,%9}, {%0,%1,%2,%3};"
        : "+f"(d[0]), "+f"(d[1]), "+f"(d[2]), "+f"(d[3])
        : "r"(a[0]), "r"(a[1]), "r"(a[2]), "r"(a[3]), "r"(b0), "r"(b1));
}

__device__ __forceinline__ uint32_t packh2(float a, float b) {
    __half2 h = __floats2half2_rn(a, b);
    return *(uint32_t*)&h;
}

// ---------------------------------------------------------------------------
// Batched weight conversion: all tables in one launch (1056 blocks x 256).
// ---------------------------------------------------------------------------
__global__ __launch_bounds__(256) void convw_all_kernel(
    const float* msg_w1, const float* uw, const float* upd_w2,
    const float* in_w, const float* out_w,
    const float* ffn_w1, const float* ffn_w2,
    __half* whpdps, __half* whuw, __half* whu2out,
    __half* whqkv, __half* whf1, __half* whf2, __half* whw1c)
{
    int b = blockIdx.x;
    if (b < 256) {
        // pdps: [512][128]
        int idx = b * 256 + threadIdx.x;
        int n = idx >> 7, k = idx & 127;
        float w = (n < 256) ? msg_w1[k * 256 + n]
                            : msg_w1[(128 + k) * 256 + (n - 256)];
        whpdps[idx] = __float2half(w);
        return;
    }
    if (b < 448) {
        // uw: K=384, N=128
        int idx = (b - 256) * 256 + threadIdx.x;
        int k = idx / 128, n = idx % 128;
        whuw[(size_t)n * 384 + k] = __float2half(uw[idx]);
        return;
    }
    if (b < 576) {
        // u2out: [n][k], K=256: k<128 -> upd_w2[k][n], else out_w[k-128][n]
        int idx = (b - 448) * 256 + threadIdx.x;   // 0..32767
        int n = idx >> 8, k = idx & 255;
        float w = (k < 128) ? upd_w2[k * 128 + n] : out_w[(k - 128) * 128 + n];
        whu2out[idx] = __float2half(w);
        return;
    }
    if (b < 768) {
        // qkv: K=128, N=384
        int idx = (b - 576) * 256 + threadIdx.x;
        int k = idx / 384, n = idx % 384;
        whqkv[(size_t)n * 128 + k] = __float2half(in_w[idx]);
        return;
    }
    if (b < 896) {
        // f1: K=128, N=256
        int idx = (b - 768) * 256 + threadIdx.x;
        int k = idx / 256, n = idx % 256;
        whf1[(size_t)n * 128 + k] = __float2half(ffn_w1[idx]);
        return;
    }
    if (b < 1024) {
        // f2: K=256, N=128
        int idx = (b - 896) * 256 + threadIdx.x;
        int k = idx / 128, n = idx % 128;
        whf2[(size_t)n * 256 + k] = __float2half(ffn_w2[idx]);
        return;
    }
    {
        // w1c: [256][32] from msg_w1c[k][n] (k<32, n<256)
        int idx = (b - 1024) * 256 + threadIdx.x;  // 0..8191
        int n = idx >> 5, k = idx & 31;
        whw1c[idx] = __float2half(msg_w1[(256 + k) * 256 + n]);
    }
}

// ---------------------------------------------------------------------------
// LayerNorm (standalone: only used for xn = LN(x)).
// ---------------------------------------------------------------------------
__global__ __launch_bounds__(256) void ln_kernel(
    const float* __restrict__ a, const float* __restrict__ g,
    const float* __restrict__ be, float* __restrict__ out)
{
    int row  = blockIdx.x * 8 + (threadIdx.x >> 5);
    int lane = threadIdx.x & 31;
    size_t off = (size_t)row * 128 + lane * 4;
    float4 v = *(const float4*)(a + off);
    float s  = v.x + v.y + v.z + v.w;
    float ss = v.x*v.x + v.y*v.y + v.z*v.z + v.w*v.w;
    #pragma unroll
    for (int o = 16; o > 0; o >>= 1) {
        s  += __shfl_xor_sync(0xffffffffu, s,  o);
        ss += __shfl_xor_sync(0xffffffffu, ss, o);
    }
    float mean = s * (1.0f / 128.0f);
    float var  = ss * (1.0f / 128.0f) - mean * mean;
    float rstd = rsqrtf(var + 1e-5f);
    float4 gg = *(const float4*)(g  + lane * 4);
    float4 bb = *(const float4*)(be + lane * 4);
    float4 o4;
    o4.x = (v.x - mean) * rstd * gg.x + bb.x;
    o4.y = (v.y - mean) * rstd * gg.y + bb.y;
    o4.z = (v.z - mean) * rstd * gg.z + bb.z;
    o4.w = (v.w - mean) * rstd * gg.w + bb.w;
    *(float4*)(out + off) = o4;
}

// ---------------------------------------------------------------------------
// Small fp32 GEMM (prep only): BM=128, BN=64, BK=16, 256 threads, FFMA2.
// ---------------------------------------------------------------------------
__global__ __launch_bounds__(256) void gemm_kernel(
    const float* __restrict__ A1, int K1,
    const float* __restrict__ B,
    float* __restrict__ C, int M, int NN)
{
    const int T = K1 >> 4;
    __shared__ float As[2][16 * 128];
    __shared__ float Bs[2][16 * 64];
    const int t  = threadIdx.x;
    const int m0 = blockIdx.x * 128;
    const int n0 = blockIdx.y * 64;
    const int mg = t >> 4;
    const int ng = t & 15;
    const int k4own = (t & 3) * 4;
    int rowA[2];
    #pragma unroll
    for (int i = 0; i < 2; i++) rowA[i] = m0 + ((t + i * 256) >> 2);

    float4 ra[2], rb;
    auto ldg_tile = [&](int kt) {
        int kb = kt * 16;
        #pragma unroll
        for (int i = 0; i < 2; i++)
            ra[i] = *(const float4*)(A1 + (size_t)rowA[i] * K1 + kb + k4own);
        int r = t >> 4, c4 = t & 15;
        rb = *(const float4*)(B + (size_t)(kb + r) * NN + n0 + c4 * 4);
    };
    auto sts_tile = [&](int buf) {
        #pragma unroll
        for (int i = 0; i < 2; i++) {
            int cc = t + i * 256;
            int m = cc >> 2, k4 = cc & 3;
            As[buf][(k4 * 4 + 0) * 128 + m] = ra[i].x;
            As[buf][(k4 * 4 + 1) * 128 + m] = ra[i].y;
            As[buf][(k4 * 4 + 2) * 128 + m] = ra[i].z;
            As[buf][(k4 * 4 + 3) * 128 + m] = ra[i].w;
        }
        int r = t >> 4, c4 = t & 15;
        *(float4*)&Bs[buf][r * 64 + c4 * 4] = rb;
    };

    u64 acc[4][4];
    #pragma unroll
    for (int i = 0; i < 4; i++)
        #pragma unroll
        for (int j = 0; j < 4; j++) acc[i][j] = 0ull;

    ldg_tile(0); sts_tile(0);
    for (int kt = 0; kt < T; kt++) {
        __syncthreads();
        if (kt + 1 < T) ldg_tile(kt + 1);
        const float* ap = As[kt & 1];
        const float* bp = Bs[kt & 1];
        #pragma unroll
        for (int k = 0; k < 16; k++) {
            ulonglong2 a01 = *(const ulonglong2*)(ap + k * 128 + mg * 8);
            ulonglong2 a23 = *(const ulonglong2*)(ap + k * 128 + mg * 8 + 4);
            float4 b = *(const float4*)(bp + k * 64 + ng * 4);
            u64 am[4] = {a01.x, a01.y, a23.x, a23.y};
            u64 bd[4] = {dup2(b.x), dup2(b.y), dup2(b.z), dup2(b.w)};
            #pragma unroll
            for (int i = 0; i < 4; i++)
                #pragma unroll
                for (int j = 0; j < 4; j++)
                    fma2(acc[i][j], am[i], bd[j]);
        }
        if (kt + 1 < T) sts_tile((kt + 1) & 1);
    }

    #pragma unroll
    for (int i = 0; i < 4; i++) {
        int r0 = m0 + mg * 8 + 2 * i;
        float2 v0 = unpack2(acc[i][0]);
        float2 v1 = unpack2(acc[i][1]);
        float2 v2 = unpack2(acc[i][2]);
        float2 v3 = unpack2(acc[i][3]);
        *(float4*)(C + (size_t)r0       * NN + n0 + ng * 4) = make_float4(v0.x, v1.x, v2.x, v3.x);
        *(float4*)(C + (size_t)(r0 + 1) * NN + n0 + ng * 4) = make_float4(v0.y, v1.y, v2.y, v3.y);
    }
}

// ---------------------------------------------------------------------------
// HMMA GEMM body with epilogue functor.
// ---------------------------------------------------------------------------
template<bool GELU, class Epi>
__device__ __forceinline__ void hgemm_body(
    const float* __restrict__ A1, int K1,
    const float* __restrict__ A2, int K2,
    const __half* __restrict__ Bh,
    const float* __restrict__ bias,
    const float* __restrict__ bias2,
    const float* __restrict__ rowscale,
    int m0, int n0, __half* Ah, __half* Bs, Epi epi)
{
    const int K = K1 + K2;
    const int T = K >> 5;
    const int t = threadIdx.x;

    const int arow = t >> 1, aseg = (t & 1) * 16;
    const int brow = t >> 1, bseg = (t & 1) * 16;

    float4 raf[4];
    uint4 rbu0, rbu1;
    auto ldg_tile = [&](int kb) {
        #pragma unroll
        for (int i = 0; i < 4; i++) {
            int gk = kb + aseg + i * 4;
            const float* src = (gk < K1)
                ? (A1 + (size_t)(m0 + arow) * K1 + gk)
                : (A2 + (size_t)(m0 + arow) * K2 + (gk - K1));
            raf[i] = *(const float4*)src;
        }
        const __half* bsrc = Bh + (size_t)(n0 + brow) * K + kb + bseg;
        rbu0 = *(const uint4*)bsrc;
        rbu1 = *(const uint4*)(bsrc + 8);
    };
    auto sts_tile = [&](int buf) {
        __half2* ad = (__half2*)&Ah[buf * 128 * 40 + arow * 40 + aseg];
        #pragma unroll
        for (int i = 0; i < 4; i++) {
            ad[i * 2]     = __floats2half2_rn(raf[i].x, raf[i].y);
            ad[i * 2 + 1] = __floats2half2_rn(raf[i].z, raf[i].w);
        }
        __half* bd = &Bs[buf * 128 * 40 + brow * 40 + bseg];
        *(uint4*)bd       = rbu0;
        *(uint4*)(bd + 8) = rbu1;
    };

    const int wid = t >> 5, lane = t & 31;
    const int wm = wid & 3;
    const int wn = wid >> 2;
    const int lq = lane >> 2;
    const int lr = lane & 3;

    float d[2][8][4];
    #pragma unroll
    for (int mt = 0; mt < 2; mt++)
        #pragma unroll
        for (int nt = 0; nt < 8; nt++)
            #pragma unroll
            for (int c = 0; c < 4; c++) d[mt][nt][c] = 0.0f;

    ldg_tile(0); sts_tile(0);
    for (int kt = 0; kt < T; kt++) {
        __syncthreads();
        if (kt + 1 < T) ldg_tile((kt + 1) * 32);
        const __half* ap = Ah + (kt & 1) * 128 * 40;
        const __half* bp = Bs + (kt & 1) * 128 * 40;

        uint32_t afr[2][2][4];
        #pragma unroll
        for (int mt = 0; mt < 2; mt++) {
            int r = wm * 32 + mt * 16 + lq;
            #pragma unroll
            for (int ks = 0; ks < 2; ks++) {
                int k = ks * 16 + lr * 2;
                afr[mt][ks][0] = *(const uint32_t*)&ap[r * 40 + k];
                afr[mt][ks][1] = *(const uint32_t*)&ap[(r + 8) * 40 + k];
                afr[mt][ks][2] = *(const uint32_t*)&ap[r * 40 + k + 8];
                afr[mt][ks][3] = *(const uint32_t*)&ap[(r + 8) * 40 + k + 8];
            }
        }
        #pragma unroll
        for (int nt = 0; nt < 8; nt++) {
            int n = wn * 64 + nt * 8 + lq;
            uint32_t b00 = *(const uint32_t*)&bp[n * 40 + lr * 2];
            uint32_t b10 = *(const uint32_t*)&bp[n * 40 + lr * 2 + 8];
            uint32_t b01 = *(const uint32_t*)&bp[n * 40 + 16 + lr * 2];
            uint32_t b11 = *(const uint32_t*)&bp[n * 40 + 16 + lr * 2 + 8];
            #pragma unroll
            for (int mt = 0; mt < 2; mt++) {
                mma16816(d[mt][nt], afr[mt][0], b00, b10);
                mma16816(d[mt][nt], afr[mt][1], b01, b11);
            }
        }
        if (kt + 1 < T) sts_tile((kt + 1) & 1);
    }

    #pragma unroll
    for (int mt = 0; mt < 2; mt++) {
        int row = m0 + wm * 32 + mt * 16 + lq;
        float rs0 = rowscale ? rowscale[row]     : 0.0f;
        float rs8 = rowscale ? rowscale[row + 8] : 0.0f;
        #pragma unroll
        for (int nt = 0; nt < 8; nt++) {
            int col = n0 + wn * 64 + nt * 8 + lr * 2;
            float b0v = bias ? bias[col]     : 0.0f;
            float b1v = bias ? bias[col + 1] : 0.0f;
            float c0  = bias2 ? bias2[col]     : 0.0f;
            float c1  = bias2 ? bias2[col + 1] : 0.0f;
            float v0 = d[mt][nt][0] + b0v + rs0 * c0;
            float v1 = d[mt][nt][1] + b1v + rs0 * c1;
            float v2 = d[mt][nt][2] + b0v + rs8 * c0;
            float v3 = d[mt][nt][3] + b1v + rs8 * c1;
            if (GELU) {
                v0 = gelu_f(v0); v1 = gelu_f(v1);
                v2 = gelu_f(v2); v3 = gelu_f(v3);
            }
            epi(row, col, v0, v1, v2, v3);
        }
    }
}

// fp32-out wrapper (upd1, ffn1)
template<bool GELU>
__global__ __launch_bounds__(256) void hgemm_kernel(
    const float* __restrict__ A1, int K1,
    const float* __restrict__ A2, int K2,
    const __half* __restrict__ Bh,
    const float* __restrict__ bias,
    const float* __restrict__ bias2,
    const float* __restrict__ rowscale,
    float* __restrict__ C, int NN)
{
    __shared__ __align__(16) __half Ah[2 * 128 * 40];
    __shared__ __align__(16) __half Bs[2 * 128 * 40];
    hgemm_body<GELU>(A1, K1, A2, K2, Bh, bias, bias2, rowscale,
        blockIdx.x * 128, blockIdx.y * 128, Ah, Bs,
        [&](int row, int col, float v0, float v1, float v2, float v3) {
            *(float2*)(C + (size_t)row       * NN + col) = make_float2(v0, v1);
            *(float2*)(C + (size_t)(row + 8) * NN + col) = make_float2(v2, v3);
        });
}

// Combined pdps (y<4) + qkv (y>=4) launch, both fp16-out.
__global__ __launch_bounds__(256) void pdps_qkv_kernel(
    const float* __restrict__ xn, const __half* __restrict__ whpdps,
    __half* __restrict__ pdps,
    const float* __restrict__ x, const __half* __restrict__ whqkv,
    const float* __restrict__ in_b, __half* __restrict__ qkvh)
{
    __shared__ __align__(16) __half Ah[2 * 128 * 40];
    __shared__ __align__(16) __half Bs[2 * 128 * 40];
    if (blockIdx.y < 4) {
        __half* C = pdps;
        hgemm_body<false>(xn, 128, nullptr, 0, whpdps, nullptr, nullptr,
            nullptr, blockIdx.x * 128, blockIdx.y * 128, Ah, Bs,
            [&](int row, int col, float v0, float v1, float v2, float v3) {
                *(__half2*)(C + (size_t)row       * 512 + col) = __floats2half2_rn(v0, v1);
                *(__half2*)(C + (size_t)(row + 8) * 512 + col) = __floats2half2_rn(v2, v3);
            });
    } else {
        __half* C = qkvh;
        hgemm_body<false>(x, 128, nullptr, 0, whqkv, in_b, nullptr,
            nullptr, blockIdx.x * 128, (blockIdx.y - 4) * 128, Ah, Bs,
            [&](int row, int col, float v0, float v1, float v2, float v3) {
                *(__half2*)(C + (size_t)row       * 384 + col) = __floats2half2_rn(v0, v1);
                *(__half2*)(C + (size_t)(row + 8) * 384 + col) = __floats2half2_rn(v2, v3);
            });
    }
}

// Fused: h1 = LN( x + [t1|obuf]@[U2;Wout] + (b2+bout) ) with n1 params.
// Single K=256 GEMM into smem tile, then per-row LN.
__global__ __launch_bounds__(256) void upd2_out_ln_kernel(
    const float* __restrict__ t1, const float* __restrict__ obuf,
    const __half* __restrict__ whu2out, const float* __restrict__ bcat,
    const float* __restrict__ x,
    const float* __restrict__ n1_g, const float* __restrict__ n1_b,
    float* __restrict__ h1)
{
    __shared__ __align__(16) __half Ah[2 * 128 * 40];
    __shared__ __align__(16) __half Bs[2 * 128 * 40];
    extern __shared__ float Gs[];          // [128][132]
    const int m0 = blockIdx.x * 128;

    hgemm_body<false>(t1, 128, obuf, 128, whu2out, bcat, nullptr, nullptr,
        m0, 0, Ah, Bs,
        [&](int row, int col, float v0, float v1, float v2, float v3) {
            int rl = row - m0;
            float2 x0 = *(const float2*)(x + (size_t)row       * 128 + col);
            float2 x8 = *(const float2*)(x + (size_t)(row + 8) * 128 + col);
            Gs[rl * 132 + col]           = v0 + x0.x;
            Gs[rl * 132 + col + 1]       = v1 + x0.y;
            Gs[(rl + 8) * 132 + col]     = v2 + x8.x;
            Gs[(rl + 8) * 132 + col + 1] = v3 + x8.y;
        });
    __syncthreads();

    const int t = threadIdx.x, w = t >> 5, lane = t & 31;
    float4 gg = *(const float4*)(n1_g + lane * 4);
    float4 bb = *(const float4*)(n1_b + lane * 4);
    #pragma unroll 4
    for (int i = 0; i < 16; i++) {
        int r = w * 16 + i;
        float4 v = *(const float4*)&Gs[r * 132 + lane * 4];
        float s  = v.x + v.y + v.z + v.w;
        float ss = v.x*v.x + v.y*v.y + v.z*v.z + v.w*v.w;
        #pragma unroll
        for (int o = 16; o > 0; o >>= 1) {
            s  += __shfl_xor_sync(0xffffffffu, s,  o);
            ss += __shfl_xor_sync(0xffffffffu, ss, o);
        }
        float mean = s * (1.0f / 128.0f);
        float var  = ss * (1.0f / 128.0f) - mean * mean;
        float rstd = rsqrtf(var + 1e-5f);
        float4 o4;
        o4.x = (v.x - mean) * rstd * gg.x + bb.x;
        o4.y = (v.y - mean) * rstd * gg.y + bb.y;
        o4.z = (v.z - mean) * rstd * gg.z + bb.z;
        o4.w = (v.w - mean) * rstd * gg.w + bb.w;
        *(float4*)(h1 + (size_t)(m0 + r) * 128 + lane * 4) = o4;
    }
}

// Fused: out = LN( h1 + ffn@W2+b2 ) with n2 params.
__global__ __launch_bounds__(256) void ffn_ln_kernel(
    const float* __restrict__ ffnb, const __half* __restrict__ whf2,
    const float* __restrict__ ffn_b2,
    const float* __restrict__ h1,
    const float* __restrict__ n2_g, const float* __restrict__ n2_b,
    float* __restrict__ out)
{
    __shared__ __align__(16) __half Ah[2 * 128 * 40];
    __shared__ __align__(16) __half Bs[2 * 128 * 40];
    extern __shared__ float Gs[];          // [128][132]
    const int m0 = blockIdx.x * 128;

    hgemm_body<false>(ffnb, 256, nullptr, 0, whf2, ffn_b2, nullptr, nullptr,
        m0, 0, Ah, Bs,
        [&](int row, int col, float v0, float v1, float v2, float v3) {
            int rl = row - m0;
            float2 h0 = *(const float2*)(h1 + (size_t)row       * 128 + col);
            float2 h8 = *(const float2*)(h1 + (size_t)(row + 8) * 128 + col);
            Gs[rl * 132 + col]           = v0 + h0.x;
            Gs[rl * 132 + col + 1]       = v1 + h0.y;
            Gs[(rl + 8) * 132 + col]     = v2 + h8.x;
            Gs[(rl + 8) * 132 + col + 1] = v3 + h8.y;
        });
    __syncthreads();

    const int t = threadIdx.x, w = t >> 5, lane = t & 31;
    float4 gg = *(const float4*)(n2_g + lane * 4);
    float4 bb = *(const float4*)(n2_b + lane * 4);
    #pragma unroll 4
    for (int i = 0; i < 16; i++) {
        int r = w * 16 + i;
        float4 v = *(const float4*)&Gs[r * 132 + lane * 4];
        float s  = v.x + v.y + v.z + v.w;
        float ss = v.x*v.x + v.y*v.y + v.z*v.z + v.w*v.w;
        #pragma unroll
        for (int o = 16; o > 0; o >>= 1) {
            s  += __shfl_xor_sync(0xffffffffu, s,  o);
            ss += __shfl_xor_sync(0xffffffffu, ss, o);
        }
        float mean = s * (1.0f / 128.0f);
        float var  = ss * (1.0f / 128.0f) - mean * mean;
        float rstd = rsqrtf(var + 1e-5f);
        float4 o4;
        o4.x = (v.x - mean) * rstd * gg.x + bb.x;
        o4.y = (v.y - mean) * rstd * gg.y + bb.y;
        o4.z = (v.z - mean) * rstd * gg.z + bb.z;
        o4.w = (v.w - mean) * rstd * gg.w + bb.w;
        *(float4*)(out + (size_t)(m0 + r) * 128 + lane * 4) = o4;
    }
}

// ---------------------------------------------------------------------------
// Fused edge kernel + in-block segmented reduce (pdps fp16, W1c fp16 table).
// ---------------------------------------------------------------------------
__global__ __launch_bounds__(256) void edge_fused_kernel(
    const float* __restrict__ ea, const int* __restrict__ eperm,
    const __half* __restrict__ whw1c, const float* __restrict__ b1,
    const __half* __restrict__ pdps,
    const int* __restrict__ sdst, const int* __restrict__ ssrc,
    float* __restrict__ aggrH)
{
    extern __shared__ __align__(16) char smraw[];
    __half* Ws  = (__half*)smraw;                  // [256][36]
    __half* As  = Ws + 256 * 36;                   // [64][36]
    __half* Gsm = As + 64 * 36;                    // [64][264]
    float*  b1s = (float*)(Gsm + 64 * 264);        // [256]
    int*    ds  = (int*)(b1s + 256);               // [64]
    const int t  = threadIdx.x;
    const int e0 = blockIdx.x * 64;

    // vectorized W table copy: uint4 global loads, uint2 smem stores
    // (smem rows have stride 36 halfs = 72B, only 8B-aligned for odd rows)
    {
        b1s[t] = b1[t];
        const uint4* wsrc = (const uint4*)whw1c;
        #pragma unroll
        for (int i = 0; i < 4; i++) {
            int u = t * 4 + i;               // 0..1023 (uint4 = 8 halfs)
            int row = u >> 2, seg = (u & 3) * 8;
            uint4 v = wsrc[u];
            uint2* dst = (uint2*)&Ws[row * 36 + seg];   // 8B-aligned
            dst[0] = make_uint2(v.x, v.y);
            dst[1] = make_uint2(v.z, v.w);
        }
    }
    {
        int el = t >> 2, part = t & 3;
        int e = eperm[e0 + el];
        const float4* src = (const float4*)(ea + (size_t)e * 32 + part * 8);
        float4 v0 = src[0], v1 = src[1];
        __half2* dst = (__half2*)(As + el * 36 + part * 8);
        dst[0] = __floats2half2_rn(v0.x, v0.y);
        dst[1] = __floats2half2_rn(v0.z, v0.w);
        dst[2] = __floats2half2_rn(v1.x, v1.y);
        dst[3] = __floats2half2_rn(v1.z, v1.w);
    }
    if (t < 64) ds[t] = sdst[e0 + t];
    __syncthreads();

    const int wid = t >> 5, lane = t & 31;
    const int wm = wid >> 2;
    const int wn = wid & 3;
    const int lq = lane >> 2;
    const int lr = lane & 3;

    float d[2][8][4];
    #pragma unroll
    for (int mt = 0; mt < 2; mt++)
        #pragma unroll
        for (int nt = 0; nt < 8; nt++)
            #pragma unroll
            for (int c = 0; c < 4; c++) d[mt][nt][c] = 0.0f;

    uint32_t afr[2][2][4];
    #pragma unroll
    for (int mt = 0; mt < 2; mt++) {
        int r = wm * 32 + mt * 16 + lq;
        #pragma unroll
        for (int ks = 0; ks < 2; ks++) {
            int k = ks * 16 + lr * 2;
            afr[mt][ks][0] = *(const uint32_t*)&As[r * 36 + k];
            afr[mt][ks][1] = *(const uint32_t*)&As[(r + 8) * 36 + k];
            afr[mt][ks][2] = *(const uint32_t*)&As[r * 36 + k + 8];
            afr[mt][ks][3] = *(const uint32_t*)&As[(r + 8) * 36 + k + 8];
        }
    }

    #pragma unroll
    for (int nt = 0; nt < 8; nt++) {
        int n = wn * 64 + nt * 8 + lq;
        uint32_t b0k0 = *(const uint32_t*)&Ws[n * 36 + lr * 2];
        uint32_t b1k0 = *(const uint32_t*)&Ws[n * 36 + lr * 2 + 8];
        uint32_t b0k1 = *(const uint32_t*)&Ws[n * 36 + 16 + lr * 2];
        uint32_t b1k1 = *(const uint32_t*)&Ws[n * 36 + 16 + lr * 2 + 8];
        #pragma unroll
        for (int mt = 0; mt < 2; mt++) {
            mma16816(d[mt][nt], afr[mt][0], b0k0, b1k0);
            mma16816(d[mt][nt], afr[mt][1], b0k1, b1k1);
        }
    }

    #pragma unroll
    for (int mt = 0; mt < 2; mt++) {
        int l0 = wm * 32 + mt * 16 + lq;
        int l8 = l0 + 8;
        int j0 = e0 + l0, j8 = e0 + l8;
        const __half* pd0 = pdps + (size_t)sdst[j0] * 512;
        const __half* ps0 = pdps + (size_t)ssrc[j0] * 512 + 256;
        const __half* pd8 = pdps + (size_t)sdst[j8] * 512;
        const __half* ps8 = pdps + (size_t)ssrc[j8] * 512 + 256;
        #pragma unroll
        for (int nt = 0; nt < 8; nt++) {
            int col = wn * 64 + nt * 8 + lr * 2;
            float2 a0 = __half22float2(*(const __half2*)(pd0 + col));
            float2 s0 = __half22float2(*(const __half2*)(ps0 + col));
            float2 a8 = __half22float2(*(const __half2*)(pd8 + col));
            float2 s8 = __half22float2(*(const __half2*)(ps8 + col));
            float bx = b1s[col], by = b1s[col + 1];
            float v0 = gelu_f(d[mt][nt][0] + bx + a0.x + s0.x);
            float v1 = gelu_f(d[mt][nt][1] + by + a0.y + s0.y);
            float v2 = gelu_f(d[mt][nt][2] + bx + a8.x + s8.x);
            float v3 = gelu_f(d[mt][nt][3] + by + a8.y + s8.y);
            *(__half2*)(Gsm + l0 * 264 + col) = __floats2half2_rn(v0, v1);
            *(__half2*)(Gsm + l8 * 264 + col) = __floats2half2_rn(v2, v3);
        }
    }
    __syncthreads();

    {
        int c = t;
        float acc = 0.0f;
        int prev = ds[0];
        #pragma unroll 8
        for (int r = 0; r < 64; r++) {
            int nd = ds[r];
            if (nd != prev) {
                atomicAdd(&aggrH[(size_t)prev * 256 + c], acc);
                acc = 0.0f;
                prev = nd;
            }
            acc += __half2float(Gsm[r * 264 + c]);
        }
        atomicAdd(&aggrH[(size_t)prev * 256 + c], acc);
    }
}

// ---------------------------------------------------------------------------
// Prep biases: b2u = msg_b2 @ U1b ; bcat = upd_b2 + out_b
// ---------------------------------------------------------------------------
__global__ __launch_bounds__(128) void prep_bias_kernel(
    const float* __restrict__ b2, const float* __restrict__ U1b,
    const float* __restrict__ upd_b2, const float* __restrict__ out_b,
    float* __restrict__ b2u, float* __restrict__ bcat)
{
    int n = threadIdx.x;
    float s = 0.0f;
    for (int k = 0; k < 128; k++) s = fmaf(b2[k], U1b[k * 128 + n], s);
    b2u[n]  = s;
    bcat[n] = upd_b2[n] + out_b[n];
}

// ---------------------------------------------------------------------------
// Counting sort of edges by dst
// ---------------------------------------------------------------------------
__global__ __launch_bounds__(256) void hist_kernel(
    const int* __restrict__ dstp, int* __restrict__ cnt)
{
    int e = blockIdx.x * 256 + threadIdx.x;
    atomicAdd(&cnt[dstp[e]], 1);
}

__global__ __launch_bounds__(1024) void scan_local_kernel(
    const int* __restrict__ cnt, int* __restrict__ offs,
    float* __restrict__ degf, int* __restrict__ bsum)
{
    __shared__ int wsum[32];
    int t = threadIdx.x;
    int i0 = blockIdx.x * 2048 + t * 2;
    int c0 = cnt[i0], c1 = cnt[i0 + 1];
    int s = c0 + c1;
    int lane = t & 31, wid = t >> 5;
    int v = s;
    #pragma unroll
    for (int o = 1; o < 32; o <<= 1) {
        int u = __shfl_up_sync(0xffffffffu, v, o);
        if (lane >= o) v += u;
    }
    if (lane == 31) wsum[wid] = v;
    __syncthreads();
    if (wid == 0) {
        int w = wsum[lane];
        #pragma unroll
        for (int o = 1; o < 32; o <<= 1) {
            int u = __shfl_up_sync(0xffffffffu, w, o);
            if (lane >= o) w += u;
        }
        wsum[lane] = w;
    }
    __syncthreads();
    int ex = (wid ? wsum[wid - 1] : 0) + (v - s);
    offs[i0]     = ex;
    offs[i0 + 1] = ex + c0;
    degf[i0]     = (float)c0;
    degf[i0 + 1] = (float)c1;
    if (t == 0) bsum[blockIdx.x] = wsum[31];
}

__global__ __launch_bounds__(1024) void scan_fix_kernel(
    int* __restrict__ offs, int* __restrict__ cursor,
    const int* __restrict__ bsum)
{
    int i = blockIdx.x * 1024 + threadIdx.x;
    int b = i >> 11;
    int add = 0;
    #pragma unroll
    for (int k = 0; k < 8; k++) if (k < b) add += bsum[k];
    int v = offs[i] + add;
    offs[i] = v;
    cursor[i] = v;
    if (i == 0) offs[NV] = EV;
}

__global__ __launch_bounds__(256) void scatter_kernel(
    const int* __restrict__ dstp, const int* __restrict__ srcp,
    int* __restrict__ cursor, int* __restrict__ eperm,
    int* __restrict__ ssrc, int* __restrict__ sdst)
{
    int e = blockIdx.x * 256 + threadIdx.x;
    int d = dstp[e];
    int pos = atomicAdd(&cursor[d], 1);
    eperm[pos] = e;
    ssrc[pos]  = srcp[e];
    sdst[pos]  = d;
}

// ---------------------------------------------------------------------------
// Flash attention via HMMA, qkv in fp16.
// ---------------------------------------------------------------------------
#define VTS 514
__global__ __launch_bounds__(128) void attn_flash_kernel(
    const __half* __restrict__ qkv, float* __restrict__ o)
{
    extern __shared__ __half smh[];
    __half* Ks = smh;                       // [512][40]
    __half* Vt = smh + 512 * 40;            // [32][VTS]
    __half* Qs = Vt + 32 * VTS;             // [64][40]
    const int t  = threadIdx.x;
    const int b  = blockIdx.x;
    const int g  = b >> 5;
    const int h  = (b >> 3) & 3;
    const int qb = b & 7;
    const size_t gb = (size_t)g * 512;
    const float scale = 0.17677669529663687f;

    #pragma unroll
    for (int i = 0; i < 32; i++) {
        int task = t + i * 128;
        int row = task >> 3, seg = task & 7;
        uint2 v = *(const uint2*)(qkv + (gb + row) * 384 + 128 + h * 32 + seg * 4);
        *(uint2*)&Ks[row * 40 + seg * 4] = v;
    }
    #pragma unroll
    for (int i = 0; i < 32; i++) {
        int task = t + i * 128;
        int row = task >> 3, seg = task & 7;
        const __half* src = qkv + (gb + row) * 384 + 256 + h * 32 + seg * 4;
        int d0 = seg * 4;
        Vt[(d0 + 0) * VTS + row] = src[0];
        Vt[(d0 + 1) * VTS + row] = src[1];
        Vt[(d0 + 2) * VTS + row] = src[2];
        Vt[(d0 + 3) * VTS + row] = src[3];
    }
    #pragma unroll
    for (int i = 0; i < 4; i++) {
        int task = t + i * 128;
        int row = task >> 3, seg = task & 7;
        const __half2* src = (const __half2*)(qkv + (gb + qb * 64 + row) * 384 + h * 32 + seg * 4);
        float2 v0 = __half22float2(src[0]);
        float2 v1 = __half22float2(src[1]);
        __half2* d = (__half2*)&Qs[row * 40 + seg * 4];
        d[0] = __floats2half2_rn(v0.x * scale, v0.y * scale);
        d[1] = __floats2half2_rn(v1.x * scale, v1.y * scale);
    }
    __syncthreads();

    const int wq = t >> 5, lane = t & 31;
    const int lq = lane >> 2, lr = lane & 3;

    uint32_t aq[2][4];
    #pragma unroll
    for (int ks = 0; ks < 2; ks++) {
        int base = (wq * 16 + lq) * 40 + ks * 16 + lr * 2;
        aq[ks][0] = *(const uint32_t*)&Qs[base];
        aq[ks][1] = *(const uint32_t*)&Qs[base + 8 * 40];
        aq[ks][2] = *(const uint32_t*)&Qs[base + 8];
        aq[ks][3] = *(const uint32_t*)&Qs[base + 8 * 40 + 8];
    }

    float m0 = -1e30f, m1 = -1e30f, l0 = 0.0f, l1 = 0.0f;
    float oA[4][4];
    #pragma unroll
    for (int n = 0; n < 4; n++)
        #pragma unroll
        for (int c = 0; c < 4; c++) oA[n][c] = 0.0f;

    for (int c = 0; c < 8; c++) {
        float s[8][4];
        #pragma unroll
        for (int nt = 0; nt < 8; nt++)
            #pragma unroll
            for (int q = 0; q < 4; q++) s[nt][q] = 0.0f;
        #pragma unroll
        for (int nt = 0; nt < 8; nt++) {
            int kb = (c * 64 + nt * 8 + lq) * 40 + lr * 2;
            mma16816(s[nt], aq[0], *(const uint32_t*)&Ks[kb],
                                    *(const uint32_t*)&Ks[kb + 8]);
            mma16816(s[nt], aq[1], *(const uint32_t*)&Ks[kb + 16],
                                    *(const uint32_t*)&Ks[kb + 24]);
        }
        float mc0 = -1e30f, mc1 = -1e30f;
        #pragma unroll
        for (int nt = 0; nt < 8; nt++) {
            mc0 = fmaxf(mc0, fmaxf(s[nt][0], s[nt][1]));
            mc1 = fmaxf(mc1, fmaxf(s[nt][2], s[nt][3]));
        }
        mc0 = fmaxf(mc0, __shfl_xor_sync(0xffffffffu, mc0, 1));
        mc0 = fmaxf(mc0, __shfl_xor_sync(0xffffffffu, mc0, 2));
        mc1 = fmaxf(mc1, __shfl_xor_sync(0xffffffffu, mc1, 1));
        mc1 = fmaxf(mc1, __shfl_xor_sync(0xffffffffu, mc1, 2));
        float mn0 = fmaxf(m0, mc0), mn1 = fmaxf(m1, mc1);
        float cr0 = __expf(m0 - mn0), cr1 = __expf(m1 - mn1);
        m0 = mn0; m1 = mn1;
        float rs0 = 0.0f, rs1 = 0.0f;
        #pragma unroll
        for (int nt = 0; nt < 8; nt++) {
            s[nt][0] = __expf(s[nt][0] - m0); rs0 += s[nt][0];
            s[nt][1] = __expf(s[nt][1] - m0); rs0 += s[nt][1];
            s[nt][2] = __expf(s[nt][2] - m1); rs1 += s[nt][2];
            s[nt][3] = __expf(s[nt][3] - m1); rs1 += s[nt][3];
        }
        rs0 += __shfl_xor_sync(0xffffffffu, rs0, 1);
        rs0 += __shfl_xor_sync(0xffffffffu, rs0, 2);
        rs1 += __shfl_xor_sync(0xffffffffu, rs1, 1);
        rs1 += __shfl_xor_sync(0xffffffffu, rs1, 2);
        l0 = l0 * cr0 + rs0;
        l1 = l1 * cr1 + rs1;
        #pragma unroll
        for (int n = 0; n < 4; n++) {
            oA[n][0] *= cr0; oA[n][1] *= cr0;
            oA[n][2] *= cr1; oA[n][3] *= cr1;
        }
        #pragma unroll
        for (int kt = 0; kt < 4; kt++) {
            uint32_t a[4];
            a[0] = packh2(s[2 * kt][0],     s[2 * kt][1]);
            a[1] = packh2(s[2 * kt][2],     s[2 * kt][3]);
            a[2] = packh2(s[2 * kt + 1][0], s[2 * kt + 1][1]);
            a[3] = packh2(s[2 * kt + 1][2], s[2 * kt + 1][3]);
            #pragma unroll
            for (int nd = 0; nd < 4; nd++) {
                int vb = (nd * 8 + lq) * VTS + c * 64 + kt * 16 + lr * 2;
                mma16816(oA[nd], a, *(const uint32_t*)&Vt[vb],
                                     *(const uint32_t*)&Vt[vb + 8]);
            }
        }
    }

    float i0 = 1.0f / l0, i1 = 1.0f / l1;
    int row = qb * 64 + wq * 16 + lq;
    float* orow = o + (gb + row) * 128 + h * 32;
    #pragma unroll
    for (int nd = 0; nd < 4; nd++) {
        *(float2*)(orow + nd * 8 + lr * 2) =
            make_float2(oA[nd][0] * i0, oA[nd][1] * i0);
        *(float2*)(orow + 8 * 128 + nd * 8 + lr * 2) =
            make_float2(oA[nd][2] * i1, oA[nd][3] * i1);
    }
}

// ---------------------------------------------------------------------------
// Host launcher
// ---------------------------------------------------------------------------
extern "C" void kernel_launch(void* const* d_in, const int* in_sizes, int n_in,
                              void* d_out, int out_size)
{
    const float* x      = (const float*)d_in[0];
    const int*   eidx   = (const int*)  d_in[1];
    const float* ea     = (const float*)d_in[2];
    /* d_in[3] = batch (unused) */
    const float* gnn_g  = (const float*)d_in[4];
    const float* gnn_b  = (const float*)d_in[5];
    const float* msg_w1 = (const float*)d_in[6];
    const float* msg_b1 = (const float*)d_in[7];
    const float* msg_w2 = (const float*)d_in[8];
    const float* msg_b2 = (const float*)d_in[9];
    const float* upd_w1 = (const float*)d_in[10];
    const float* upd_b1 = (const float*)d_in[11];
    const float* upd_w2 = (const float*)d_in[12];
    const float* upd_b2 = (const float*)d_in[13];
    const float* in_w   = (const float*)d_in[14];
    const float* in_b   = (const float*)d_in[15];
    const float* out_w  = (const float*)d_in[16];
    const float* out_b  = (const float*)d_in[17];
    const float* ffn_w1 = (const float*)d_in[18];
    const float* ffn_b1 = (const float*)d_in[19];
    const float* ffn_w2 = (const float*)d_in[20];
    const float* ffn_b2 = (const float*)d_in[21];
    const float* n1_g   = (const float*)d_in[22];
    const float* n1_b   = (const float*)d_in[23];
    const float* n2_g   = (const float*)d_in[24];
    const float* n2_b   = (const float*)d_in[25];
    float* out = (float*)d_out;

    const int* srcp = eidx;
    const int* dstp = eidx + EV;

    float *xn, *aggrH, *t1, *obuf, *h1, *ffn, *deg, *uw, *b2u, *bcat;
    __half *pdps, *qkvh, *whpdps, *whuw, *whu2out, *whqkv, *whf1, *whf2, *whw1c;
    int *cnt, *offs, *cursor, *eperm, *ssrc, *sdst, *bsum;
    cudaGetSymbolAddress((void**)&xn,    g_xn);
    cudaGetSymbolAddress((void**)&pdps,  g_pdps);
    cudaGetSymbolAddress((void**)&aggrH, g_aggrH);
    cudaGetSymbolAddress((void**)&t1,    g_t1);
    cudaGetSymbolAddress((void**)&qkvh,  g_qkvh);
    cudaGetSymbolAddress((void**)&obuf,  g_obuf);
    cudaGetSymbolAddress((void**)&h1,    g_h1);
    cudaGetSymbolAddress((void**)&ffn,   g_ffn);
    cudaGetSymbolAddress((void**)&deg,   g_deg);
    cudaGetSymbolAddress((void**)&uw,    g_uw);
    cudaGetSymbolAddress((void**)&b2u,   g_b2u);
    cudaGetSymbolAddress((void**)&bcat,  g_bcat);
    cudaGetSymbolAddress((void**)&cnt,   g_cnt);
    cudaGetSymbolAddress((void**)&offs,  g_offs);
    cudaGetSymbolAddress((void**)&cursor,g_cursor);
    cudaGetSymbolAddress((void**)&eperm, g_eperm);
    cudaGetSymbolAddress((void**)&ssrc,  g_ssrc);
    cudaGetSymbolAddress((void**)&sdst,  g_sdst);
    cudaGetSymbolAddress((void**)&bsum,  g_bsum);
    cudaGetSymbolAddress((void**)&whpdps, g_wh_pdps);
    cudaGetSymbolAddress((void**)&whuw,   g_wh_uw);
    cudaGetSymbolAddress((void**)&whu2out,g_wh_u2out);
    cudaGetSymbolAddress((void**)&whqkv,  g_wh_qkv);
    cudaGetSymbolAddress((void**)&whf1,   g_wh_f1);
    cudaGetSymbolAddress((void**)&whf2,   g_wh_f2);
    cudaGetSymbolAddress((void**)&whw1c,  g_wh_w1c);

    cudaFuncSetAttribute(attn_flash_kernel,
                         cudaFuncAttributeMaxDynamicSharedMemorySize, 78976);
    cudaFuncSetAttribute(edge_fused_kernel,
                         cudaFuncAttributeMaxDynamicSharedMemorySize, 58112);
    cudaFuncSetAttribute(upd2_out_ln_kernel,
                         cudaFuncAttributeMaxDynamicSharedMemorySize, 67584);
    cudaFuncSetAttribute(ffn_ln_kernel,
                         cudaFuncAttributeMaxDynamicSharedMemorySize, 67584);

    // 0) independent memsets first (off the critical path)
    cudaMemsetAsync(aggrH, 0, (size_t)NV * 256 * sizeof(float), 0);
    cudaMemsetAsync(cnt, 0, NV * sizeof(int), 0);

    // 1) weight prep
    cudaMemcpyAsync(uw, upd_w1, 128 * 128 * sizeof(float),
                    cudaMemcpyDeviceToDevice, 0);
    gemm_kernel<<<dim3(2, 2), 256>>>(msg_w2, 128, upd_w1 + 128 * 128,
                                     uw + 128 * 128, 256, 128);
    prep_bias_kernel<<<1, 128>>>(msg_b2, upd_w1 + 128 * 128,
                                 upd_b2, out_b, b2u, bcat);
    convw_all_kernel<<<1056, 256>>>(
        msg_w1, uw, upd_w2, in_w, out_w, ffn_w1, ffn_w2,
        whpdps, whuw, whu2out, whqkv, whf1, whf2, whw1c);

    // 2) counting sort of edges by dst
    hist_kernel<<<EV / 256, 256>>>(dstp, cnt);
    scan_local_kernel<<<8, 1024>>>(cnt, offs, deg, bsum);
    scan_fix_kernel<<<16, 1024>>>(offs, cursor, bsum);
    scatter_kernel<<<EV / 256, 256>>>(dstp, srcp, cursor, eperm, ssrc, sdst);

    // 3) xn = LN(x)
    ln_kernel<<<NV / 8, 256>>>(x, gnn_g, gnn_b, xn);

    // 4) combined [Pd|Ps] table + qkv projection in ONE launch (fp16 out)
    pdps_qkv_kernel<<<dim3(NV / 128, 7), 256>>>(
        xn, whpdps, pdps, x, whqkv, in_b, qkvh);

    // 5) fused edge MLP + gelu + in-block segmented reduce -> aggrH
    edge_fused_kernel<<<EV / 64, 256, 58112>>>(
        ea, eperm, whw1c, msg_b1, pdps, sdst, ssrc, aggrH);

    // 6) flash attention (independent of edge path)
    attn_flash_kernel<<<1024, 128, 78976>>>(qkvh, obuf);

    // 7) fused update-MLP layer 1
    hgemm_kernel<true><<<dim3(NV / 128, 1), 256>>>(
        xn, 128, aggrH, 256, whuw, upd_b1, b2u, deg, t1, 128);

    // 8) fused: h1 = LN(x + [t1|obuf]@[U2;Wout] + bcat)  — single K=256 GEMM
    upd2_out_ln_kernel<<<NV / 128, 256, 67584>>>(
        t1, obuf, whu2out, bcat, x, n1_g, n1_b, h1);

    // 9) FFN layer 1
    hgemm_kernel<true><<<dim3(NV / 128, 2), 256>>>(
        h1, 128, nullptr, 0, whf1, ffn_b1, nullptr, nullptr, ffn, 256);

    // 10) fused: out = LN(h1 + ffn2(ffn))
    ffn_ln_kernel<<<NV / 128, 256, 67584>>>(
        ffn, whf2, ffn_b2, h1, n2_g, n2_b, out);
}

// round 14
// speedup vs baseline: 1.0194x; 1.0145x over previous
#include <cuda_runtime.h>
#include <cuda_fp16.h>
#include <math.h>
#include <cstdint>

// ---------------------------------------------------------------------------
// Problem constants
// ---------------------------------------------------------------------------
#define NV   16384      // nodes
#define DV   128        // node dim
#define EDV  32         // edge feat dim
#define EV   262144     // edges
#define GV   32         // graphs
#define SV   512        // seq per graph
#define HV   4          // heads
#define HDV  32         // head dim

// ---------------------------------------------------------------------------
// Scratch buffers (device globals; no runtime allocation allowed)
// ---------------------------------------------------------------------------
__device__ float  g_xn   [NV * DV];
__device__ __half g_pdps [NV * 512];    // [Pd | Ps] per node, fp16
__device__ float  g_aggrH[NV * 256];
__device__ float  g_t1   [NV * DV];
__device__ __half g_qkvh [NV * 3 * DV]; // qkv fp16
__device__ float  g_obuf [NV * DV];
__device__ float  g_h1   [NV * DV];
__device__ float  g_ffn  [NV * 2 * DV];
__device__ float  g_uw   [384 * 128];   // [U1a ; W2@U1b]
__device__ float  g_b2u  [128];         // msg_b2 @ U1b
__device__ float  g_bcat [128];         // upd_b2 + out_b
__device__ int    g_cnt   [NV];
__device__ int    g_offs  [NV + 1];
__device__ int    g_cursor[NV];
__device__ int    g_eperm [EV];
__device__ int    g_ssrc  [EV];
__device__ int    g_sdst  [EV];
__device__ float  g_deg   [NV];
__device__ int    g_bsum  [8];

// fp16 transposed weight tables [N][K]
__device__ __half g_wh_pdps [512 * 128];
__device__ __half g_wh_uw   [128 * 384];
__device__ __half g_wh_u2out[128 * 256];  // [n][k]: k<128 -> U2, k>=128 -> Wout
__device__ __half g_wh_qkv  [384 * 128];
__device__ __half g_wh_f1   [256 * 128];
__device__ __half g_wh_f2   [128 * 256];
__device__ __half g_wh_w1c  [256 * 32];   // W1c transposed [n][k] fp16

// ---------------------------------------------------------------------------
// f32x2 packed-math helpers
// ---------------------------------------------------------------------------
typedef unsigned long long u64;

__device__ __forceinline__ u64 dup2(float x) {
    u64 r; asm("mov.b64 %0, {%1, %1};" : "=l"(r) : "f"(x)); return r;
}
__device__ __forceinline__ float2 unpack2(u64 v) {
    float2 r; asm("mov.b64 {%0, %1}, %2;" : "=f"(r.x), "=f"(r.y) : "l"(v)); return r;
}
__device__ __forceinline__ void fma2(u64& d, u64 a, u64 b) {
    asm("fma.rn.f32x2 %0, %1, %2, %0;" : "+l"(d) : "l"(a), "l"(b));
}

__device__ __forceinline__ float gelu_f(float v) {
    return 0.5f * v * (1.0f + erff(v * 0.70710678118654752f));
}

__device__ __forceinline__ void mma16816(
    float* d, const uint32_t* a, uint32_t b0, uint32_t b1)
{
    asm volatile(
        "mma.sync.aligned.m16n8k16.row.col.f32.f16.f16.f32 "
        "{%0,%1,%2,%3}, {%4,%5,%6,%7}, {%8,%9}, {%0,%1,%2,%3};"
        : "+f"(d[0]), "+f"(d[1]), "+f"(d[2]), "+f"(d[3])
        : "r"(a[0]), "r"(a[1]), "r"(a[2]), "r"(a[3]), "r"(b0), "r"(b1));
}

__device__ __forceinline__ uint32_t packh2(float a, float b) {
    __half2 h = __floats2half2_rn(a, b);
    return *(uint32_t*)&h;
}

// ---------------------------------------------------------------------------
// Batched weight conversion: all tables in one launch (1056 blocks x 256).
// ---------------------------------------------------------------------------
__global__ __launch_bounds__(256) void convw_all_kernel(
    const float* msg_w1, const float* uw, const float* upd_w2,
    const float* in_w, const float* out_w,
    const float* ffn_w1, const float* ffn_w2,
    __half* whpdps, __half* whuw, __half* whu2out,
    __half* whqkv, __half* whf1, __half* whf2, __half* whw1c)
{
    int b = blockIdx.x;
    if (b < 256) {
        int idx = b * 256 + threadIdx.x;
        int n = idx >> 7, k = idx & 127;
        float w = (n < 256) ? msg_w1[k * 256 + n]
                            : msg_w1[(128 + k) * 256 + (n - 256)];
        whpdps[idx] = __float2half(w);
        return;
    }
    if (b < 448) {
        int idx = (b - 256) * 256 + threadIdx.x;
        int k = idx / 128, n = idx % 128;
        whuw[(size_t)n * 384 + k] = __float2half(uw[idx]);
        return;
    }
    if (b < 576) {
        int idx = (b - 448) * 256 + threadIdx.x;
        int n = idx >> 8, k = idx & 255;
        float w = (k < 128) ? upd_w2[k * 128 + n] : out_w[(k - 128) * 128 + n];
        whu2out[idx] = __float2half(w);
        return;
    }
    if (b < 768) {
        int idx = (b - 576) * 256 + threadIdx.x;
        int k = idx / 384, n = idx % 384;
        whqkv[(size_t)n * 128 + k] = __float2half(in_w[idx]);
        return;
    }
    if (b < 896) {
        int idx = (b - 768) * 256 + threadIdx.x;
        int k = idx / 256, n = idx % 256;
        whf1[(size_t)n * 128 + k] = __float2half(ffn_w1[idx]);
        return;
    }
    if (b < 1024) {
        int idx = (b - 896) * 256 + threadIdx.x;
        int k = idx / 128, n = idx % 128;
        whf2[(size_t)n * 256 + k] = __float2half(ffn_w2[idx]);
        return;
    }
    {
        int idx = (b - 1024) * 256 + threadIdx.x;
        int n = idx >> 5, k = idx & 31;
        whw1c[idx] = __float2half(msg_w1[(256 + k) * 256 + n]);
    }
}

// ---------------------------------------------------------------------------
// LayerNorm (standalone: only used for xn = LN(x)).
// ---------------------------------------------------------------------------
__global__ __launch_bounds__(256) void ln_kernel(
    const float* __restrict__ a, const float* __restrict__ g,
    const float* __restrict__ be, float* __restrict__ out)
{
    int row  = blockIdx.x * 8 + (threadIdx.x >> 5);
    int lane = threadIdx.x & 31;
    size_t off = (size_t)row * 128 + lane * 4;
    float4 v = *(const float4*)(a + off);
    float s  = v.x + v.y + v.z + v.w;
    float ss = v.x*v.x + v.y*v.y + v.z*v.z + v.w*v.w;
    #pragma unroll
    for (int o = 16; o > 0; o >>= 1) {
        s  += __shfl_xor_sync(0xffffffffu, s,  o);
        ss += __shfl_xor_sync(0xffffffffu, ss, o);
    }
    float mean = s * (1.0f / 128.0f);
    float var  = ss * (1.0f / 128.0f) - mean * mean;
    float rstd = rsqrtf(var + 1e-5f);
    float4 gg = *(const float4*)(g  + lane * 4);
    float4 bb = *(const float4*)(be + lane * 4);
    float4 o4;
    o4.x = (v.x - mean) * rstd * gg.x + bb.x;
    o4.y = (v.y - mean) * rstd * gg.y + bb.y;
    o4.z = (v.z - mean) * rstd * gg.z + bb.z;
    o4.w = (v.w - mean) * rstd * gg.w + bb.w;
    *(float4*)(out + off) = o4;
}

// ---------------------------------------------------------------------------
// Small fp32 GEMM (prep only): BM=128, BN=64, BK=16, 256 threads, FFMA2.
// ---------------------------------------------------------------------------
__global__ __launch_bounds__(256) void gemm_kernel(
    const float* __restrict__ A1, int K1,
    const float* __restrict__ B,
    float* __restrict__ C, int M, int NN)
{
    const int T = K1 >> 4;
    __shared__ float As[2][16 * 128];
    __shared__ float Bs[2][16 * 64];
    const int t  = threadIdx.x;
    const int m0 = blockIdx.x * 128;
    const int n0 = blockIdx.y * 64;
    const int mg = t >> 4;
    const int ng = t & 15;
    const int k4own = (t & 3) * 4;
    int rowA[2];
    #pragma unroll
    for (int i = 0; i < 2; i++) rowA[i] = m0 + ((t + i * 256) >> 2);

    float4 ra[2], rb;
    auto ldg_tile = [&](int kt) {
        int kb = kt * 16;
        #pragma unroll
        for (int i = 0; i < 2; i++)
            ra[i] = *(const float4*)(A1 + (size_t)rowA[i] * K1 + kb + k4own);
        int r = t >> 4, c4 = t & 15;
        rb = *(const float4*)(B + (size_t)(kb + r) * NN + n0 + c4 * 4);
    };
    auto sts_tile = [&](int buf) {
        #pragma unroll
        for (int i = 0; i < 2; i++) {
            int cc = t + i * 256;
            int m = cc >> 2, k4 = cc & 3;
            As[buf][(k4 * 4 + 0) * 128 + m] = ra[i].x;
            As[buf][(k4 * 4 + 1) * 128 + m] = ra[i].y;
            As[buf][(k4 * 4 + 2) * 128 + m] = ra[i].z;
            As[buf][(k4 * 4 + 3) * 128 + m] = ra[i].w;
        }
        int r = t >> 4, c4 = t & 15;
        *(float4*)&Bs[buf][r * 64 + c4 * 4] = rb;
    };

    u64 acc[4][4];
    #pragma unroll
    for (int i = 0; i < 4; i++)
        #pragma unroll
        for (int j = 0; j < 4; j++) acc[i][j] = 0ull;

    ldg_tile(0); sts_tile(0);
    for (int kt = 0; kt < T; kt++) {
        __syncthreads();
        if (kt + 1 < T) ldg_tile(kt + 1);
        const float* ap = As[kt & 1];
        const float* bp = Bs[kt & 1];
        #pragma unroll
        for (int k = 0; k < 16; k++) {
            ulonglong2 a01 = *(const ulonglong2*)(ap + k * 128 + mg * 8);
            ulonglong2 a23 = *(const ulonglong2*)(ap + k * 128 + mg * 8 + 4);
            float4 b = *(const float4*)(bp + k * 64 + ng * 4);
            u64 am[4] = {a01.x, a01.y, a23.x, a23.y};
            u64 bd[4] = {dup2(b.x), dup2(b.y), dup2(b.z), dup2(b.w)};
            #pragma unroll
            for (int i = 0; i < 4; i++)
                #pragma unroll
                for (int j = 0; j < 4; j++)
                    fma2(acc[i][j], am[i], bd[j]);
        }
        if (kt + 1 < T) sts_tile((kt + 1) & 1);
    }

    #pragma unroll
    for (int i = 0; i < 4; i++) {
        int r0 = m0 + mg * 8 + 2 * i;
        float2 v0 = unpack2(acc[i][0]);
        float2 v1 = unpack2(acc[i][1]);
        float2 v2 = unpack2(acc[i][2]);
        float2 v3 = unpack2(acc[i][3]);
        *(float4*)(C + (size_t)r0       * NN + n0 + ng * 4) = make_float4(v0.x, v1.x, v2.x, v3.x);
        *(float4*)(C + (size_t)(r0 + 1) * NN + n0 + ng * 4) = make_float4(v0.y, v1.y, v2.y, v3.y);
    }
}

// ---------------------------------------------------------------------------
// HMMA GEMM body with epilogue functor.
// ---------------------------------------------------------------------------
template<bool GELU, class Epi>
__device__ __forceinline__ void hgemm_body(
    const float* __restrict__ A1, int K1,
    const float* __restrict__ A2, int K2,
    const __half* __restrict__ Bh,
    const float* __restrict__ bias,
    const float* __restrict__ bias2,
    const float* __restrict__ rowscale,
    int m0, int n0, __half* Ah, __half* Bs, Epi epi)
{
    const int K = K1 + K2;
    const int T = K >> 5;
    const int t = threadIdx.x;

    const int arow = t >> 1, aseg = (t & 1) * 16;
    const int brow = t >> 1, bseg = (t & 1) * 16;

    float4 raf[4];
    uint4 rbu0, rbu1;
    auto ldg_tile = [&](int kb) {
        #pragma unroll
        for (int i = 0; i < 4; i++) {
            int gk = kb + aseg + i * 4;
            const float* src = (gk < K1)
                ? (A1 + (size_t)(m0 + arow) * K1 + gk)
                : (A2 + (size_t)(m0 + arow) * K2 + (gk - K1));
            raf[i] = *(const float4*)src;
        }
        const __half* bsrc = Bh + (size_t)(n0 + brow) * K + kb + bseg;
        rbu0 = *(const uint4*)bsrc;
        rbu1 = *(const uint4*)(bsrc + 8);
    };
    auto sts_tile = [&](int buf) {
        __half2* ad = (__half2*)&Ah[buf * 128 * 40 + arow * 40 + aseg];
        #pragma unroll
        for (int i = 0; i < 4; i++) {
            ad[i * 2]     = __floats2half2_rn(raf[i].x, raf[i].y);
            ad[i * 2 + 1] = __floats2half2_rn(raf[i].z, raf[i].w);
        }
        __half* bd = &Bs[buf * 128 * 40 + brow * 40 + bseg];
        *(uint4*)bd       = rbu0;
        *(uint4*)(bd + 8) = rbu1;
    };

    const int wid = t >> 5, lane = t & 31;
    const int wm = wid & 3;
    const int wn = wid >> 2;
    const int lq = lane >> 2;
    const int lr = lane & 3;

    float d[2][8][4];
    #pragma unroll
    for (int mt = 0; mt < 2; mt++)
        #pragma unroll
        for (int nt = 0; nt < 8; nt++)
            #pragma unroll
            for (int c = 0; c < 4; c++) d[mt][nt][c] = 0.0f;

    ldg_tile(0); sts_tile(0);
    for (int kt = 0; kt < T; kt++) {
        __syncthreads();
        if (kt + 1 < T) ldg_tile((kt + 1) * 32);
        const __half* ap = Ah + (kt & 1) * 128 * 40;
        const __half* bp = Bs + (kt & 1) * 128 * 40;

        uint32_t afr[2][2][4];
        #pragma unroll
        for (int mt = 0; mt < 2; mt++) {
            int r = wm * 32 + mt * 16 + lq;
            #pragma unroll
            for (int ks = 0; ks < 2; ks++) {
                int k = ks * 16 + lr * 2;
                afr[mt][ks][0] = *(const uint32_t*)&ap[r * 40 + k];
                afr[mt][ks][1] = *(const uint32_t*)&ap[(r + 8) * 40 + k];
                afr[mt][ks][2] = *(const uint32_t*)&ap[r * 40 + k + 8];
                afr[mt][ks][3] = *(const uint32_t*)&ap[(r + 8) * 40 + k + 8];
            }
        }
        #pragma unroll
        for (int nt = 0; nt < 8; nt++) {
            int n = wn * 64 + nt * 8 + lq;
            uint32_t b00 = *(const uint32_t*)&bp[n * 40 + lr * 2];
            uint32_t b10 = *(const uint32_t*)&bp[n * 40 + lr * 2 + 8];
            uint32_t b01 = *(const uint32_t*)&bp[n * 40 + 16 + lr * 2];
            uint32_t b11 = *(const uint32_t*)&bp[n * 40 + 16 + lr * 2 + 8];
            #pragma unroll
            for (int mt = 0; mt < 2; mt++) {
                mma16816(d[mt][nt], afr[mt][0], b00, b10);
                mma16816(d[mt][nt], afr[mt][1], b01, b11);
            }
        }
        if (kt + 1 < T) sts_tile((kt + 1) & 1);
    }

    #pragma unroll
    for (int mt = 0; mt < 2; mt++) {
        int row = m0 + wm * 32 + mt * 16 + lq;
        float rs0 = rowscale ? rowscale[row]     : 0.0f;
        float rs8 = rowscale ? rowscale[row + 8] : 0.0f;
        #pragma unroll
        for (int nt = 0; nt < 8; nt++) {
            int col = n0 + wn * 64 + nt * 8 + lr * 2;
            float b0v = bias ? bias[col]     : 0.0f;
            float b1v = bias ? bias[col + 1] : 0.0f;
            float c0  = bias2 ? bias2[col]     : 0.0f;
            float c1  = bias2 ? bias2[col + 1] : 0.0f;
            float v0 = d[mt][nt][0] + b0v + rs0 * c0;
            float v1 = d[mt][nt][1] + b1v + rs0 * c1;
            float v2 = d[mt][nt][2] + b0v + rs8 * c0;
            float v3 = d[mt][nt][3] + b1v + rs8 * c1;
            if (GELU) {
                v0 = gelu_f(v0); v1 = gelu_f(v1);
                v2 = gelu_f(v2); v3 = gelu_f(v3);
            }
            epi(row, col, v0, v1, v2, v3);
        }
    }
}

// fp32-out wrapper (upd1, ffn1)
template<bool GELU>
__global__ __launch_bounds__(256) void hgemm_kernel(
    const float* __restrict__ A1, int K1,
    const float* __restrict__ A2, int K2,
    const __half* __restrict__ Bh,
    const float* __restrict__ bias,
    const float* __restrict__ bias2,
    const float* __restrict__ rowscale,
    float* __restrict__ C, int NN)
{
    __shared__ __align__(16) __half Ah[2 * 128 * 40];
    __shared__ __align__(16) __half Bs[2 * 128 * 40];
    hgemm_body<GELU>(A1, K1, A2, K2, Bh, bias, bias2, rowscale,
        blockIdx.x * 128, blockIdx.y * 128, Ah, Bs,
        [&](int row, int col, float v0, float v1, float v2, float v3) {
            *(float2*)(C + (size_t)row       * NN + col) = make_float2(v0, v1);
            *(float2*)(C + (size_t)(row + 8) * NN + col) = make_float2(v2, v3);
        });
}

// Combined pdps (y<4) + qkv (y>=4) launch, both fp16-out.
__global__ __launch_bounds__(256) void pdps_qkv_kernel(
    const float* __restrict__ xn, const __half* __restrict__ whpdps,
    __half* __restrict__ pdps,
    const float* __restrict__ x, const __half* __restrict__ whqkv,
    const float* __restrict__ in_b, __half* __restrict__ qkvh)
{
    __shared__ __align__(16) __half Ah[2 * 128 * 40];
    __shared__ __align__(16) __half Bs[2 * 128 * 40];
    if (blockIdx.y < 4) {
        __half* C = pdps;
        hgemm_body<false>(xn, 128, nullptr, 0, whpdps, nullptr, nullptr,
            nullptr, blockIdx.x * 128, blockIdx.y * 128, Ah, Bs,
            [&](int row, int col, float v0, float v1, float v2, float v3) {
                *(__half2*)(C + (size_t)row       * 512 + col) = __floats2half2_rn(v0, v1);
                *(__half2*)(C + (size_t)(row + 8) * 512 + col) = __floats2half2_rn(v2, v3);
            });
    } else {
        __half* C = qkvh;
        hgemm_body<false>(x, 128, nullptr, 0, whqkv, in_b, nullptr,
            nullptr, blockIdx.x * 128, (blockIdx.y - 4) * 128, Ah, Bs,
            [&](int row, int col, float v0, float v1, float v2, float v3) {
                *(__half2*)(C + (size_t)row       * 384 + col) = __floats2half2_rn(v0, v1);
                *(__half2*)(C + (size_t)(row + 8) * 384 + col) = __floats2half2_rn(v2, v3);
            });
    }
}

// Fused: h1 = LN( x + [t1|obuf]@[U2;Wout] + (b2+bout) ) with n1 params.
__global__ __launch_bounds__(256) void upd2_out_ln_kernel(
    const float* __restrict__ t1, const float* __restrict__ obuf,
    const __half* __restrict__ whu2out, const float* __restrict__ bcat,
    const float* __restrict__ x,
    const float* __restrict__ n1_g, const float* __restrict__ n1_b,
    float* __restrict__ h1)
{
    __shared__ __align__(16) __half Ah[2 * 128 * 40];
    __shared__ __align__(16) __half Bs[2 * 128 * 40];
    extern __shared__ float Gs[];          // [128][132]
    const int m0 = blockIdx.x * 128;

    hgemm_body<false>(t1, 128, obuf, 128, whu2out, bcat, nullptr, nullptr,
        m0, 0, Ah, Bs,
        [&](int row, int col, float v0, float v1, float v2, float v3) {
            int rl = row - m0;
            float2 x0 = *(const float2*)(x + (size_t)row       * 128 + col);
            float2 x8 = *(const float2*)(x + (size_t)(row + 8) * 128 + col);
            Gs[rl * 132 + col]           = v0 + x0.x;
            Gs[rl * 132 + col + 1]       = v1 + x0.y;
            Gs[(rl + 8) * 132 + col]     = v2 + x8.x;
            Gs[(rl + 8) * 132 + col + 1] = v3 + x8.y;
        });
    __syncthreads();

    const int t = threadIdx.x, w = t >> 5, lane = t & 31;
    float4 gg = *(const float4*)(n1_g + lane * 4);
    float4 bb = *(const float4*)(n1_b + lane * 4);
    #pragma unroll 4
    for (int i = 0; i < 16; i++) {
        int r = w * 16 + i;
        float4 v = *(const float4*)&Gs[r * 132 + lane * 4];
        float s  = v.x + v.y + v.z + v.w;
        float ss = v.x*v.x + v.y*v.y + v.z*v.z + v.w*v.w;
        #pragma unroll
        for (int o = 16; o > 0; o >>= 1) {
            s  += __shfl_xor_sync(0xffffffffu, s,  o);
            ss += __shfl_xor_sync(0xffffffffu, ss, o);
        }
        float mean = s * (1.0f / 128.0f);
        float var  = ss * (1.0f / 128.0f) - mean * mean;
        float rstd = rsqrtf(var + 1e-5f);
        float4 o4;
        o4.x = (v.x - mean) * rstd * gg.x + bb.x;
        o4.y = (v.y - mean) * rstd * gg.y + bb.y;
        o4.z = (v.z - mean) * rstd * gg.z + bb.z;
        o4.w = (v.w - mean) * rstd * gg.w + bb.w;
        *(float4*)(h1 + (size_t)(m0 + r) * 128 + lane * 4) = o4;
    }
}

// Fused: out = LN( h1 + ffn@W2+b2 ) with n2 params.
__global__ __launch_bounds__(256) void ffn_ln_kernel(
    const float* __restrict__ ffnb, const __half* __restrict__ whf2,
    const float* __restrict__ ffn_b2,
    const float* __restrict__ h1,
    const float* __restrict__ n2_g, const float* __restrict__ n2_b,
    float* __restrict__ out)
{
    __shared__ __align__(16) __half Ah[2 * 128 * 40];
    __shared__ __align__(16) __half Bs[2 * 128 * 40];
    extern __shared__ float Gs[];          // [128][132]
    const int m0 = blockIdx.x * 128;

    hgemm_body<false>(ffnb, 256, nullptr, 0, whf2, ffn_b2, nullptr, nullptr,
        m0, 0, Ah, Bs,
        [&](int row, int col, float v0, float v1, float v2, float v3) {
            int rl = row - m0;
            float2 h0 = *(const float2*)(h1 + (size_t)row       * 128 + col);
            float2 h8 = *(const float2*)(h1 + (size_t)(row + 8) * 128 + col);
            Gs[rl * 132 + col]           = v0 + h0.x;
            Gs[rl * 132 + col + 1]       = v1 + h0.y;
            Gs[(rl + 8) * 132 + col]     = v2 + h8.x;
            Gs[(rl + 8) * 132 + col + 1] = v3 + h8.y;
        });
    __syncthreads();

    const int t = threadIdx.x, w = t >> 5, lane = t & 31;
    float4 gg = *(const float4*)(n2_g + lane * 4);
    float4 bb = *(const float4*)(n2_b + lane * 4);
    #pragma unroll 4
    for (int i = 0; i < 16; i++) {
        int r = w * 16 + i;
        float4 v = *(const float4*)&Gs[r * 132 + lane * 4];
        float s  = v.x + v.y + v.z + v.w;
        float ss = v.x*v.x + v.y*v.y + v.z*v.z + v.w*v.w;
        #pragma unroll
        for (int o = 16; o > 0; o >>= 1) {
            s  += __shfl_xor_sync(0xffffffffu, s,  o);
            ss += __shfl_xor_sync(0xffffffffu, ss, o);
        }
        float mean = s * (1.0f / 128.0f);
        float var  = ss * (1.0f / 128.0f) - mean * mean;
        float rstd = rsqrtf(var + 1e-5f);
        float4 o4;
        o4.x = (v.x - mean) * rstd * gg.x + bb.x;
        o4.y = (v.y - mean) * rstd * gg.y + bb.y;
        o4.z = (v.z - mean) * rstd * gg.z + bb.z;
        o4.w = (v.w - mean) * rstd * gg.w + bb.w;
        *(float4*)(out + (size_t)(m0 + r) * 128 + lane * 4) = o4;
    }
}

// ---------------------------------------------------------------------------
// Edge body: MLP + gelu + in-block segmented reduce. 256 threads.
// ---------------------------------------------------------------------------
__device__ __forceinline__ void edge_body(
    char* smraw, int eb,
    const float* __restrict__ ea, const int* __restrict__ eperm,
    const __half* __restrict__ whw1c, const float* __restrict__ b1,
    const __half* __restrict__ pdps,
    const int* __restrict__ sdst, const int* __restrict__ ssrc,
    float* __restrict__ aggrH)
{
    __half* Ws  = (__half*)smraw;                  // [256][36]
    __half* As  = Ws + 256 * 36;                   // [64][36]
    __half* Gsm = As + 64 * 36;                    // [64][264]
    float*  b1s = (float*)(Gsm + 64 * 264);        // [256]
    int*    ds  = (int*)(b1s + 256);               // [64]
    const int t  = threadIdx.x;
    const int e0 = eb * 64;

    {
        b1s[t] = b1[t];
        const uint4* wsrc = (const uint4*)whw1c;
        #pragma unroll
        for (int i = 0; i < 4; i++) {
            int u = t * 4 + i;
            int row = u >> 2, seg = (u & 3) * 8;
            uint4 v = wsrc[u];
            uint2* dst = (uint2*)&Ws[row * 36 + seg];   // 8B-aligned
            dst[0] = make_uint2(v.x, v.y);
            dst[1] = make_uint2(v.z, v.w);
        }
    }
    {
        int el = t >> 2, part = t & 3;
        int e = eperm[e0 + el];
        const float4* src = (const float4*)(ea + (size_t)e * 32 + part * 8);
        float4 v0 = src[0], v1 = src[1];
        __half2* dst = (__half2*)(As + el * 36 + part * 8);
        dst[0] = __floats2half2_rn(v0.x, v0.y);
        dst[1] = __floats2half2_rn(v0.z, v0.w);
        dst[2] = __floats2half2_rn(v1.x, v1.y);
        dst[3] = __floats2half2_rn(v1.z, v1.w);
    }
    if (t < 64) ds[t] = sdst[e0 + t];
    __syncthreads();

    const int wid = t >> 5, lane = t & 31;
    const int wm = wid >> 2;
    const int wn = wid & 3;
    const int lq = lane >> 2;
    const int lr = lane & 3;

    float d[2][8][4];
    #pragma unroll
    for (int mt = 0; mt < 2; mt++)
        #pragma unroll
        for (int nt = 0; nt < 8; nt++)
            #pragma unroll
            for (int c = 0; c < 4; c++) d[mt][nt][c] = 0.0f;

    uint32_t afr[2][2][4];
    #pragma unroll
    for (int mt = 0; mt < 2; mt++) {
        int r = wm * 32 + mt * 16 + lq;
        #pragma unroll
        for (int ks = 0; ks < 2; ks++) {
            int k = ks * 16 + lr * 2;
            afr[mt][ks][0] = *(const uint32_t*)&As[r * 36 + k];
            afr[mt][ks][1] = *(const uint32_t*)&As[(r + 8) * 36 + k];
            afr[mt][ks][2] = *(const uint32_t*)&As[r * 36 + k + 8];
            afr[mt][ks][3] = *(const uint32_t*)&As[(r + 8) * 36 + k + 8];
        }
    }

    #pragma unroll
    for (int nt = 0; nt < 8; nt++) {
        int n = wn * 64 + nt * 8 + lq;
        uint32_t b0k0 = *(const uint32_t*)&Ws[n * 36 + lr * 2];
        uint32_t b1k0 = *(const uint32_t*)&Ws[n * 36 + lr * 2 + 8];
        uint32_t b0k1 = *(const uint32_t*)&Ws[n * 36 + 16 + lr * 2];
        uint32_t b1k1 = *(const uint32_t*)&Ws[n * 36 + 16 + lr * 2 + 8];
        #pragma unroll
        for (int mt = 0; mt < 2; mt++) {
            mma16816(d[mt][nt], afr[mt][0], b0k0, b1k0);
            mma16816(d[mt][nt], afr[mt][1], b0k1, b1k1);
        }
    }

    #pragma unroll
    for (int mt = 0; mt < 2; mt++) {
        int l0 = wm * 32 + mt * 16 + lq;
        int l8 = l0 + 8;
        int j0 = e0 + l0, j8 = e0 + l8;
        const __half* pd0 = pdps + (size_t)sdst[j0] * 512;
        const __half* ps0 = pdps + (size_t)ssrc[j0] * 512 + 256;
        const __half* pd8 = pdps + (size_t)sdst[j8] * 512;
        const __half* ps8 = pdps + (size_t)ssrc[j8] * 512 + 256;
        #pragma unroll
        for (int nt = 0; nt < 8; nt++) {
            int col = wn * 64 + nt * 8 + lr * 2;
            float2 a0 = __half22float2(*(const __half2*)(pd0 + col));
            float2 s0 = __half22float2(*(const __half2*)(ps0 + col));
            float2 a8 = __half22float2(*(const __half2*)(pd8 + col));
            float2 s8 = __half22float2(*(const __half2*)(ps8 + col));
            float bx = b1s[col], by = b1s[col + 1];
            float v0 = gelu_f(d[mt][nt][0] + bx + a0.x + s0.x);
            float v1 = gelu_f(d[mt][nt][1] + by + a0.y + s0.y);
            float v2 = gelu_f(d[mt][nt][2] + bx + a8.x + s8.x);
            float v3 = gelu_f(d[mt][nt][3] + by + a8.y + s8.y);
            *(__half2*)(Gsm + l0 * 264 + col) = __floats2half2_rn(v0, v1);
            *(__half2*)(Gsm + l8 * 264 + col) = __floats2half2_rn(v2, v3);
        }
    }
    __syncthreads();

    {
        int c = t;
        float acc = 0.0f;
        int prev = ds[0];
        #pragma unroll 8
        for (int r = 0; r < 64; r++) {
            int nd = ds[r];
            if (nd != prev) {
                atomicAdd(&aggrH[(size_t)prev * 256 + c], acc);
                acc = 0.0f;
                prev = nd;
            }
            acc += __half2float(Gsm[r * 264 + c]);
        }
        atomicAdd(&aggrH[(size_t)prev * 256 + c], acc);
    }
}

// ---------------------------------------------------------------------------
// Attention body (256-thread loads; warps 0-3 compute). Ks/Qs stride 36.
// smem: Ks[512*36] + Vt[32*514] + Qs[64*36] = 37184 halfs = 74368 B.
// ---------------------------------------------------------------------------
#define VTS 514
__device__ __forceinline__ void attn_body(
    char* smraw, int ab,
    const __half* __restrict__ qkv, float* __restrict__ o)
{
    __half* Ks = (__half*)smraw;            // [512][36]
    __half* Vt = Ks + 512 * 36;             // [32][VTS]
    __half* Qs = Vt + 32 * VTS;             // [64][36]
    const int t  = threadIdx.x;
    const int g  = ab >> 5;
    const int h  = (ab >> 3) & 3;
    const int qb = ab & 7;
    const size_t gb = (size_t)g * 512;
    const float scale = 0.17677669529663687f;

    // loads with 256 threads
    #pragma unroll
    for (int i = 0; i < 16; i++) {
        int task = t + i * 256;
        int row = task >> 3, seg = task & 7;
        uint2 v = *(const uint2*)(qkv + (gb + row) * 384 + 128 + h * 32 + seg * 4);
        *(uint2*)&Ks[row * 36 + seg * 4] = v;
    }
    #pragma unroll
    for (int i = 0; i < 16; i++) {
        int task = t + i * 256;
        int row = task >> 3, seg = task & 7;
        const __half* src = qkv + (gb + row) * 384 + 256 + h * 32 + seg * 4;
        int d0 = seg * 4;
        Vt[(d0 + 0) * VTS + row] = src[0];
        Vt[(d0 + 1) * VTS + row] = src[1];
        Vt[(d0 + 2) * VTS + row] = src[2];
        Vt[(d0 + 3) * VTS + row] = src[3];
    }
    #pragma unroll
    for (int i = 0; i < 2; i++) {
        int task = t + i * 256;
        int row = task >> 3, seg = task & 7;
        const __half2* src = (const __half2*)(qkv + (gb + qb * 64 + row) * 384 + h * 32 + seg * 4);
        float2 v0 = __half22float2(src[0]);
        float2 v1 = __half22float2(src[1]);
        __half2* d = (__half2*)&Qs[row * 36 + seg * 4];
        d[0] = __floats2half2_rn(v0.x * scale, v0.y * scale);
        d[1] = __floats2half2_rn(v1.x * scale, v1.y * scale);
    }
    __syncthreads();

    if (t >= 128) return;   // warps 4-7 done (no further barriers)

    const int wq = t >> 5, lane = t & 31;
    const int lq = lane >> 2, lr = lane & 3;

    uint32_t aq[2][4];
    #pragma unroll
    for (int ks = 0; ks < 2; ks++) {
        int base = (wq * 16 + lq) * 36 + ks * 16 + lr * 2;
        aq[ks][0] = *(const uint32_t*)&Qs[base];
        aq[ks][1] = *(const uint32_t*)&Qs[base + 8 * 36];
        aq[ks][2] = *(const uint32_t*)&Qs[base + 8];
        aq[ks][3] = *(const uint32_t*)&Qs[base + 8 * 36 + 8];
    }

    float m0 = -1e30f, m1 = -1e30f, l0 = 0.0f, l1 = 0.0f;
    float oA[4][4];
    #pragma unroll
    for (int n = 0; n < 4; n++)
        #pragma unroll
        for (int c = 0; c < 4; c++) oA[n][c] = 0.0f;

    for (int c = 0; c < 8; c++) {
        float s[8][4];
        #pragma unroll
        for (int nt = 0; nt < 8; nt++)
            #pragma unroll
            for (int q = 0; q < 4; q++) s[nt][q] = 0.0f;
        #pragma unroll
        for (int nt = 0; nt < 8; nt++) {
            int kb = (c * 64 + nt * 8 + lq) * 36 + lr * 2;
            mma16816(s[nt], aq[0], *(const uint32_t*)&Ks[kb],
                                    *(const uint32_t*)&Ks[kb + 8]);
            mma16816(s[nt], aq[1], *(const uint32_t*)&Ks[kb + 16],
                                    *(const uint32_t*)&Ks[kb + 24]);
        }
        float mc0 = -1e30f, mc1 = -1e30f;
        #pragma unroll
        for (int nt = 0; nt < 8; nt++) {
            mc0 = fmaxf(mc0, fmaxf(s[nt][0], s[nt][1]));
            mc1 = fmaxf(mc1, fmaxf(s[nt][2], s[nt][3]));
        }
        mc0 = fmaxf(mc0, __shfl_xor_sync(0xffffffffu, mc0, 1));
        mc0 = fmaxf(mc0, __shfl_xor_sync(0xffffffffu, mc0, 2));
        mc1 = fmaxf(mc1, __shfl_xor_sync(0xffffffffu, mc1, 1));
        mc1 = fmaxf(mc1, __shfl_xor_sync(0xffffffffu, mc1, 2));
        float mn0 = fmaxf(m0, mc0), mn1 = fmaxf(m1, mc1);
        float cr0 = __expf(m0 - mn0), cr1 = __expf(m1 - mn1);
        m0 = mn0; m1 = mn1;
        float rs0 = 0.0f, rs1 = 0.0f;
        #pragma unroll
        for (int nt = 0; nt < 8; nt++) {
            s[nt][0] = __expf(s[nt][0] - m0); rs0 += s[nt][0];
            s[nt][1] = __expf(s[nt][1] - m0); rs0 += s[nt][1];
            s[nt][2] = __expf(s[nt][2] - m1); rs1 += s[nt][2];
            s[nt][3] = __expf(s[nt][3] - m1); rs1 += s[nt][3];
        }
        rs0 += __shfl_xor_sync(0xffffffffu, rs0, 1);
        rs0 += __shfl_xor_sync(0xffffffffu, rs0, 2);
        rs1 += __shfl_xor_sync(0xffffffffu, rs1, 1);
        rs1 += __shfl_xor_sync(0xffffffffu, rs1, 2);
        l0 = l0 * cr0 + rs0;
        l1 = l1 * cr1 + rs1;
        #pragma unroll
        for (int n = 0; n < 4; n++) {
            oA[n][0] *= cr0; oA[n][1] *= cr0;
            oA[n][2] *= cr1; oA[n][3] *= cr1;
        }
        #pragma unroll
        for (int kt = 0; kt < 4; kt++) {
            uint32_t a[4];
            a[0] = packh2(s[2 * kt][0],     s[2 * kt][1]);
            a[1] = packh2(s[2 * kt][2],     s[2 * kt][3]);
            a[2] = packh2(s[2 * kt + 1][0], s[2 * kt + 1][1]);
            a[3] = packh2(s[2 * kt + 1][2], s[2 * kt + 1][3]);
            #pragma unroll
            for (int nd = 0; nd < 4; nd++) {
                int vb = (nd * 8 + lq) * VTS + c * 64 + kt * 16 + lr * 2;
                mma16816(oA[nd], a, *(const uint32_t*)&Vt[vb],
                                     *(const uint32_t*)&Vt[vb + 8]);
            }
        }
    }

    float i0 = 1.0f / l0, i1 = 1.0f / l1;
    int row = qb * 64 + wq * 16 + lq;
    float* orow = o + (gb + row) * 128 + h * 32;
    #pragma unroll
    for (int nd = 0; nd < 4; nd++) {
        *(float2*)(orow + nd * 8 + lr * 2) =
            make_float2(oA[nd][0] * i0, oA[nd][1] * i0);
        *(float2*)(orow + 8 * 128 + nd * 8 + lr * 2) =
            make_float2(oA[nd][2] * i1, oA[nd][3] * i1);
    }
}

// ---------------------------------------------------------------------------
// Merged launch: blocks [0,1024) = attention, [1024, 5120) = edge.
// Dynamic smem = 74368 B (attention's requirement; edge uses 58112 of it).
// ---------------------------------------------------------------------------
__global__ __launch_bounds__(256) void edge_attn_kernel(
    const __half* __restrict__ qkvh, float* __restrict__ obuf,
    const float* __restrict__ ea, const int* __restrict__ eperm,
    const __half* __restrict__ whw1c, const float* __restrict__ b1,
    const __half* __restrict__ pdps,
    const int* __restrict__ sdst, const int* __restrict__ ssrc,
    float* __restrict__ aggrH)
{
    extern __shared__ __align__(16) char smraw[];
    int b = blockIdx.x;
    if (b < 1024)
        attn_body(smraw, b, qkvh, obuf);
    else
        edge_body(smraw, b - 1024, ea, eperm, whw1c, b1, pdps, sdst, ssrc, aggrH);
}

// ---------------------------------------------------------------------------
// Prep biases: b2u = msg_b2 @ U1b ; bcat = upd_b2 + out_b
// ---------------------------------------------------------------------------
__global__ __launch_bounds__(128) void prep_bias_kernel(
    const float* __restrict__ b2, const float* __restrict__ U1b,
    const float* __restrict__ upd_b2, const float* __restrict__ out_b,
    float* __restrict__ b2u, float* __restrict__ bcat)
{
    int n = threadIdx.x;
    float s = 0.0f;
    for (int k = 0; k < 128; k++) s = fmaf(b2[k], U1b[k * 128 + n], s);
    b2u[n]  = s;
    bcat[n] = upd_b2[n] + out_b[n];
}

// ---------------------------------------------------------------------------
// Counting sort of edges by dst
// ---------------------------------------------------------------------------
__global__ __launch_bounds__(256) void hist_kernel(
    const int* __restrict__ dstp, int* __restrict__ cnt)
{
    int e = blockIdx.x * 256 + threadIdx.x;
    atomicAdd(&cnt[dstp[e]], 1);
}

__global__ __launch_bounds__(1024) void scan_local_kernel(
    const int* __restrict__ cnt, int* __restrict__ offs,
    float* __restrict__ degf, int* __restrict__ bsum)
{
    __shared__ int wsum[32];
    int t = threadIdx.x;
    int i0 = blockIdx.x * 2048 + t * 2;
    int c0 = cnt[i0], c1 = cnt[i0 + 1];
    int s = c0 + c1;
    int lane = t & 31, wid = t >> 5;
    int v = s;
    #pragma unroll
    for (int o = 1; o < 32; o <<= 1) {
        int u = __shfl_up_sync(0xffffffffu, v, o);
        if (lane >= o) v += u;
    }
    if (lane == 31) wsum[wid] = v;
    __syncthreads();
    if (wid == 0) {
        int w = wsum[lane];
        #pragma unroll
        for (int o = 1; o < 32; o <<= 1) {
            int u = __shfl_up_sync(0xffffffffu, w, o);
            if (lane >= o) w += u;
        }
        wsum[lane] = w;
    }
    __syncthreads();
    int ex = (wid ? wsum[wid - 1] : 0) + (v - s);
    offs[i0]     = ex;
    offs[i0 + 1] = ex + c0;
    degf[i0]     = (float)c0;
    degf[i0 + 1] = (float)c1;
    if (t == 0) bsum[blockIdx.x] = wsum[31];
}

__global__ __launch_bounds__(1024) void scan_fix_kernel(
    int* __restrict__ offs, int* __restrict__ cursor,
    const int* __restrict__ bsum)
{
    int i = blockIdx.x * 1024 + threadIdx.x;
    int b = i >> 11;
    int add = 0;
    #pragma unroll
    for (int k = 0; k < 8; k++) if (k < b) add += bsum[k];
    int v = offs[i] + add;
    offs[i] = v;
    cursor[i] = v;
    if (i == 0) offs[NV] = EV;
}

__global__ __launch_bounds__(256) void scatter_kernel(
    const int* __restrict__ dstp, const int* __restrict__ srcp,
    int* __restrict__ cursor, int* __restrict__ eperm,
    int* __restrict__ ssrc, int* __restrict__ sdst)
{
    int e = blockIdx.x * 256 + threadIdx.x;
    int d = dstp[e];
    int pos = atomicAdd(&cursor[d], 1);
    eperm[pos] = e;
    ssrc[pos]  = srcp[e];
    sdst[pos]  = d;
}

// ---------------------------------------------------------------------------
// Host launcher
// ---------------------------------------------------------------------------
extern "C" void kernel_launch(void* const* d_in, const int* in_sizes, int n_in,
                              void* d_out, int out_size)
{
    const float* x      = (const float*)d_in[0];
    const int*   eidx   = (const int*)  d_in[1];
    const float* ea     = (const float*)d_in[2];
    /* d_in[3] = batch (unused) */
    const float* gnn_g  = (const float*)d_in[4];
    const float* gnn_b  = (const float*)d_in[5];
    const float* msg_w1 = (const float*)d_in[6];
    const float* msg_b1 = (const float*)d_in[7];
    const float* msg_w2 = (const float*)d_in[8];
    const float* msg_b2 = (const float*)d_in[9];
    const float* upd_w1 = (const float*)d_in[10];
    const float* upd_b1 = (const float*)d_in[11];
    const float* upd_w2 = (const float*)d_in[12];
    const float* upd_b2 = (const float*)d_in[13];
    const float* in_w   = (const float*)d_in[14];
    const float* in_b   = (const float*)d_in[15];
    const float* out_w  = (const float*)d_in[16];
    const float* out_b  = (const float*)d_in[17];
    const float* ffn_w1 = (const float*)d_in[18];
    const float* ffn_b1 = (const float*)d_in[19];
    const float* ffn_w2 = (const float*)d_in[20];
    const float* ffn_b2 = (const float*)d_in[21];
    const float* n1_g   = (const float*)d_in[22];
    const float* n1_b   = (const float*)d_in[23];
    const float* n2_g   = (const float*)d_in[24];
    const float* n2_b   = (const float*)d_in[25];
    float* out = (float*)d_out;

    const int* srcp = eidx;
    const int* dstp = eidx + EV;

    float *xn, *aggrH, *t1, *obuf, *h1, *ffn, *deg, *uw, *b2u, *bcat;
    __half *pdps, *qkvh, *whpdps, *whuw, *whu2out, *whqkv, *whf1, *whf2, *whw1c;
    int *cnt, *offs, *cursor, *eperm, *ssrc, *sdst, *bsum;
    cudaGetSymbolAddress((void**)&xn,    g_xn);
    cudaGetSymbolAddress((void**)&pdps,  g_pdps);
    cudaGetSymbolAddress((void**)&aggrH, g_aggrH);
    cudaGetSymbolAddress((void**)&t1,    g_t1);
    cudaGetSymbolAddress((void**)&qkvh,  g_qkvh);
    cudaGetSymbolAddress((void**)&obuf,  g_obuf);
    cudaGetSymbolAddress((void**)&h1,    g_h1);
    cudaGetSymbolAddress((void**)&ffn,   g_ffn);
    cudaGetSymbolAddress((void**)&deg,   g_deg);
    cudaGetSymbolAddress((void**)&uw,    g_uw);
    cudaGetSymbolAddress((void**)&b2u,   g_b2u);
    cudaGetSymbolAddress((void**)&bcat,  g_bcat);
    cudaGetSymbolAddress((void**)&cnt,   g_cnt);
    cudaGetSymbolAddress((void**)&offs,  g_offs);
    cudaGetSymbolAddress((void**)&cursor,g_cursor);
    cudaGetSymbolAddress((void**)&eperm, g_eperm);
    cudaGetSymbolAddress((void**)&ssrc,  g_ssrc);
    cudaGetSymbolAddress((void**)&sdst,  g_sdst);
    cudaGetSymbolAddress((void**)&bsum,  g_bsum);
    cudaGetSymbolAddress((void**)&whpdps, g_wh_pdps);
    cudaGetSymbolAddress((void**)&whuw,   g_wh_uw);
    cudaGetSymbolAddress((void**)&whu2out,g_wh_u2out);
    cudaGetSymbolAddress((void**)&whqkv,  g_wh_qkv);
    cudaGetSymbolAddress((void**)&whf1,   g_wh_f1);
    cudaGetSymbolAddress((void**)&whf2,   g_wh_f2);
    cudaGetSymbolAddress((void**)&whw1c,  g_wh_w1c);

    cudaFuncSetAttribute(edge_attn_kernel,
                         cudaFuncAttributeMaxDynamicSharedMemorySize, 74368);
    cudaFuncSetAttribute(upd2_out_ln_kernel,
                         cudaFuncAttributeMaxDynamicSharedMemorySize, 67584);
    cudaFuncSetAttribute(ffn_ln_kernel,
                         cudaFuncAttributeMaxDynamicSharedMemorySize, 67584);

    // 0) independent memsets first (off the critical path)
    cudaMemsetAsync(aggrH, 0, (size_t)NV * 256 * sizeof(float), 0);
    cudaMemsetAsync(cnt, 0, NV * sizeof(int), 0);

    // 1) weight prep
    cudaMemcpyAsync(uw, upd_w1, 128 * 128 * sizeof(float),
                    cudaMemcpyDeviceToDevice, 0);
    gemm_kernel<<<dim3(2, 2), 256>>>(msg_w2, 128, upd_w1 + 128 * 128,
                                     uw + 128 * 128, 256, 128);
    prep_bias_kernel<<<1, 128>>>(msg_b2, upd_w1 + 128 * 128,
                                 upd_b2, out_b, b2u, bcat);
    convw_all_kernel<<<1056, 256>>>(
        msg_w1, uw, upd_w2, in_w, out_w, ffn_w1, ffn_w2,
        whpdps, whuw, whu2out, whqkv, whf1, whf2, whw1c);

    // 2) counting sort of edges by dst
    hist_kernel<<<EV / 256, 256>>>(dstp, cnt);
    scan_local_kernel<<<8, 1024>>>(cnt, offs, deg, bsum);
    scan_fix_kernel<<<16, 1024>>>(offs, cursor, bsum);
    scatter_kernel<<<EV / 256, 256>>>(dstp, srcp, cursor, eperm, ssrc, sdst);

    // 3) xn = LN(x)
    ln_kernel<<<NV / 8, 256>>>(x, gnn_g, gnn_b, xn);

    // 4) combined [Pd|Ps] table + qkv projection in ONE launch (fp16 out)
    pdps_qkv_kernel<<<dim3(NV / 128, 7), 256>>>(
        xn, whpdps, pdps, x, whqkv, in_b, qkvh);

    // 5) MERGED: flash attention (blocks 0..1023) + fused edge MLP/reduce
    edge_attn_kernel<<<1024 + EV / 64, 256, 74368>>>(
        qkvh, obuf, ea, eperm, whw1c, msg_b1, pdps, sdst, ssrc, aggrH);

    // 6) fused update-MLP layer 1
    hgemm_kernel<true><<<dim3(NV / 128, 1), 256>>>(
        xn, 128, aggrH, 256, whuw, upd_b1, b2u, deg, t1, 128);

    // 7) fused: h1 = LN(x + [t1|obuf]@[U2;Wout] + bcat)
    upd2_out_ln_kernel<<<NV / 128, 256, 67584>>>(
        t1, obuf, whu2out, bcat, x, n1_g, n1_b, h1);

    // 8) FFN layer 1
    hgemm_kernel<true><<<dim3(NV / 128, 2), 256>>>(
        h1, 128, nullptr, 0, whf1, ffn_b1, nullptr, nullptr, ffn, 256);

    // 9) fused: out = LN(h1 + ffn2(ffn))
    ffn_ln_kernel<<<NV / 128, 256, 67584>>>(
        ffn, whf2, ffn_b2, h1, n2_g, n2_b, out);
}

// round 15
// speedup vs baseline: 1.0870x; 1.0664x over previous
#include <cuda_runtime.h>
#include <cuda_fp16.h>
#include <math.h>
#include <cstdint>

// ---------------------------------------------------------------------------
// Problem constants
// ---------------------------------------------------------------------------
#define NV   16384      // nodes
#define DV   128        // node dim
#define EDV  32         // edge feat dim
#define EV   262144     // edges
#define GV   32         // graphs
#define SV   512        // seq per graph
#define HV   4          // heads
#define HDV  32         // head dim

// ---------------------------------------------------------------------------
// Scratch buffers (device globals; no runtime allocation allowed)
// ---------------------------------------------------------------------------
__device__ float  g_xn   [NV * DV];
__device__ __half g_pdps [NV * 512];
__device__ float  g_aggrH[NV * 256];
__device__ float  g_t1   [NV * DV];
__device__ __half g_qkvh [NV * 3 * DV];
__device__ float  g_obuf [NV * DV];
__device__ float  g_h1   [NV * DV];
__device__ float  g_ffn  [NV * 2 * DV];
__device__ float  g_uwp  [256 * 128];   // msg_w2 @ U1b
__device__ float  g_b2u  [128];
__device__ float  g_bcat [128];
__device__ int    g_cnt   [NV];
__device__ int    g_offs  [NV + 1];
__device__ int    g_cursor[NV];
__device__ int    g_eperm [EV];
__device__ int    g_ssrc  [EV];
__device__ int    g_sdst  [EV];
__device__ float  g_deg   [NV];
__device__ int    g_bsum  [8];

// fp16 transposed weight tables [N][K]
__device__ __half g_wh_pdps [512 * 128];
__device__ __half g_wh_uw   [128 * 384];
__device__ __half g_wh_u2out[128 * 256];
__device__ __half g_wh_qkv  [384 * 128];
__device__ __half g_wh_f1   [256 * 128];
__device__ __half g_wh_f2   [128 * 256];
__device__ __half g_wh_w1c  [256 * 32];

// ---------------------------------------------------------------------------
// helpers
// ---------------------------------------------------------------------------
typedef unsigned long long u64;

__device__ __forceinline__ u64 dup2(float x) {
    u64 r; asm("mov.b64 %0, {%1, %1};" : "=l"(r) : "f"(x)); return r;
}
__device__ __forceinline__ float2 unpack2(u64 v) {
    float2 r; asm("mov.b64 {%0, %1}, %2;" : "=f"(r.x), "=f"(r.y) : "l"(v)); return r;
}
__device__ __forceinline__ void fma2(u64& d, u64 a, u64 b) {
    asm("fma.rn.f32x2 %0, %1, %2, %0;" : "+l"(d) : "l"(a), "l"(b));
}

__device__ __forceinline__ float gelu_f(float v) {
    return 0.5f * v * (1.0f + erff(v * 0.70710678118654752f));
}

__device__ __forceinline__ void mma16816(
    float* d, const uint32_t* a, uint32_t b0, uint32_t b1)
{
    asm volatile(
        "mma.sync.aligned.m16n8k16.row.col.f32.f16.f16.f32 "
        "{%0,%1,%2,%3}, {%4,%5,%6,%7}, {%8,%9}, {%0,%1,%2,%3};"
        : "+f"(d[0]), "+f"(d[1]), "+f"(d[2]), "+f"(d[3])
        : "r"(a[0]), "r"(a[1]), "r"(a[2]), "r"(a[3]), "r"(b0), "r"(b1));
}

__device__ __forceinline__ uint32_t packh2(float a, float b) {
    __half2 h = __floats2half2_rn(a, b);
    return *(uint32_t*)&h;
}

// ---------------------------------------------------------------------------
// LN body: one block = 8 rows (8 warps), 256 threads.
// ---------------------------------------------------------------------------
__device__ __forceinline__ void ln_body(
    int blk, const float* __restrict__ a, const float* __restrict__ g,
    const float* __restrict__ be, float* __restrict__ out)
{
    int row  = blk * 8 + (threadIdx.x >> 5);
    int lane = threadIdx.x & 31;
    size_t off = (size_t)row * 128 + lane * 4;
    float4 v = *(const float4*)(a + off);
    float s  = v.x + v.y + v.z + v.w;
    float ss = v.x*v.x + v.y*v.y + v.z*v.z + v.w*v.w;
    #pragma unroll
    for (int o = 16; o > 0; o >>= 1) {
        s  += __shfl_xor_sync(0xffffffffu, s,  o);
        ss += __shfl_xor_sync(0xffffffffu, ss, o);
    }
    float mean = s * (1.0f / 128.0f);
    float var  = ss * (1.0f / 128.0f) - mean * mean;
    float rstd = rsqrtf(var + 1e-5f);
    float4 gg = *(const float4*)(g  + lane * 4);
    float4 bb = *(const float4*)(be + lane * 4);
    float4 o4;
    o4.x = (v.x - mean) * rstd * gg.x + bb.x;
    o4.y = (v.y - mean) * rstd * gg.y + bb.y;
    o4.z = (v.z - mean) * rstd * gg.z + bb.z;
    o4.w = (v.w - mean) * rstd * gg.w + bb.w;
    *(float4*)(out + off) = o4;
}

// ---------------------------------------------------------------------------
// Prep fp32 GEMM body: uwp[256,128] = msg_w2[256,128] @ U1b[128,128].
// 4 blocks (b: m-half x n-half), 256 threads. FFMA2.
// ---------------------------------------------------------------------------
__device__ void gemm_prep_body(
    int blk, const float* __restrict__ A1, const float* __restrict__ B,
    float* __restrict__ C)
{
    const int K1 = 128, NN = 128, T = 8;
    __shared__ float As[2][16 * 128];
    __shared__ float Bs[2][16 * 64];
    const int t  = threadIdx.x;
    const int m0 = (blk & 1) * 128;
    const int n0 = (blk >> 1) * 64;
    const int mg = t >> 4;
    const int ng = t & 15;
    const int k4own = (t & 3) * 4;
    int rowA[2];
    #pragma unroll
    for (int i = 0; i < 2; i++) rowA[i] = m0 + ((t + i * 256) >> 2);

    float4 ra[2], rb;
    auto ldg_tile = [&](int kt) {
        int kb = kt * 16;
        #pragma unroll
        for (int i = 0; i < 2; i++)
            ra[i] = *(const float4*)(A1 + (size_t)rowA[i] * K1 + kb + k4own);
        int r = t >> 4, c4 = t & 15;
        rb = *(const float4*)(B + (size_t)(kb + r) * NN + n0 + c4 * 4);
    };
    auto sts_tile = [&](int buf) {
        #pragma unroll
        for (int i = 0; i < 2; i++) {
            int cc = t + i * 256;
            int m = cc >> 2, k4 = cc & 3;
            As[buf][(k4 * 4 + 0) * 128 + m] = ra[i].x;
            As[buf][(k4 * 4 + 1) * 128 + m] = ra[i].y;
            As[buf][(k4 * 4 + 2) * 128 + m] = ra[i].z;
            As[buf][(k4 * 4 + 3) * 128 + m] = ra[i].w;
        }
        int r = t >> 4, c4 = t & 15;
        *(float4*)&Bs[buf][r * 64 + c4 * 4] = rb;
    };

    u64 acc[4][4];
    #pragma unroll
    for (int i = 0; i < 4; i++)
        #pragma unroll
        for (int j = 0; j < 4; j++) acc[i][j] = 0ull;

    ldg_tile(0); sts_tile(0);
    for (int kt = 0; kt < T; kt++) {
        __syncthreads();
        if (kt + 1 < T) ldg_tile(kt + 1);
        const float* ap = As[kt & 1];
        const float* bp = Bs[kt & 1];
        #pragma unroll
        for (int k = 0; k < 16; k++) {
            ulonglong2 a01 = *(const ulonglong2*)(ap + k * 128 + mg * 8);
            ulonglong2 a23 = *(const ulonglong2*)(ap + k * 128 + mg * 8 + 4);
            float4 b = *(const float4*)(bp + k * 64 + ng * 4);
            u64 am[4] = {a01.x, a01.y, a23.x, a23.y};
            u64 bd[4] = {dup2(b.x), dup2(b.y), dup2(b.z), dup2(b.w)};
            #pragma unroll
            for (int i = 0; i < 4; i++)
                #pragma unroll
                for (int j = 0; j < 4; j++)
                    fma2(acc[i][j], am[i], bd[j]);
        }
        if (kt + 1 < T) sts_tile((kt + 1) & 1);
    }

    #pragma unroll
    for (int i = 0; i < 4; i++) {
        int r0 = m0 + mg * 8 + 2 * i;
        float2 v0 = unpack2(acc[i][0]);
        float2 v1 = unpack2(acc[i][1]);
        float2 v2 = unpack2(acc[i][2]);
        float2 v3 = unpack2(acc[i][3]);
        *(float4*)(C + (size_t)r0       * NN + n0 + ng * 4) = make_float4(v0.x, v1.x, v2.x, v3.x);
        *(float4*)(C + (size_t)(r0 + 1) * NN + n0 + ng * 4) = make_float4(v0.y, v1.y, v2.y, v3.y);
    }
}

// ---------------------------------------------------------------------------
// P1: prep-GEMM(4) | aggrH zero(512) | prep_bias(1) | hist(1024) | LN(2048)
// = 3589 blocks, 256 threads.
// ---------------------------------------------------------------------------
__global__ __launch_bounds__(256) void prep1_kernel(
    const float* __restrict__ msg_w2, const float* __restrict__ U1b,
    float* __restrict__ uwp,
    const float* __restrict__ msg_b2, const float* __restrict__ upd_b2,
    const float* __restrict__ out_b,
    float* __restrict__ b2u, float* __restrict__ bcat,
    const int* __restrict__ dstp, int* __restrict__ cnt,
    const float* __restrict__ x, const float* __restrict__ gnn_g,
    const float* __restrict__ gnn_b, float* __restrict__ xn,
    float* __restrict__ aggrH)
{
    int b = blockIdx.x;
    if (b < 4) { gemm_prep_body(b, msg_w2, U1b, uwp); return; }
    if (b < 516) {
        float4 z = make_float4(0.f, 0.f, 0.f, 0.f);
        float4* p = (float4*)(aggrH + (size_t)(b - 4) * 8192);
        #pragma unroll
        for (int i = 0; i < 8; i++) p[threadIdx.x + i * 256] = z;
        return;
    }
    if (b == 516) {
        int n = threadIdx.x;
        if (n < 128) {
            float s = 0.0f;
            for (int k = 0; k < 128; k++) s = fmaf(msg_b2[k], U1b[k * 128 + n], s);
            b2u[n]  = s;
            bcat[n] = upd_b2[n] + out_b[n];
        }
        return;
    }
    if (b < 1541) {
        int e = (b - 517) * 256 + threadIdx.x;
        atomicAdd(&cnt[dstp[e]], 1);
        return;
    }
    ln_body(b - 1541, x, gnn_g, gnn_b, xn);
}

// ---------------------------------------------------------------------------
// P2: convw(1056) | scan_local(8, 256-thread version) = 1064 blocks.
// ---------------------------------------------------------------------------
__device__ __forceinline__ void scan_local_body(
    int blk, const int* __restrict__ cnt, int* __restrict__ offs,
    float* __restrict__ degf, int* __restrict__ bsum)
{
    __shared__ int wsum[8];
    int t = threadIdx.x;
    int base = blk * 2048 + t * 8;
    int c[8]; int s = 0;
    #pragma unroll
    for (int i = 0; i < 8; i++) { c[i] = cnt[base + i]; s += c[i]; }
    int lane = t & 31, wid = t >> 5;
    int v = s;
    #pragma unroll
    for (int o = 1; o < 32; o <<= 1) {
        int u = __shfl_up_sync(0xffffffffu, v, o);
        if (lane >= o) v += u;
    }
    if (lane == 31) wsum[wid] = v;
    __syncthreads();
    if (t < 32) {
        int w = (lane < 8) ? wsum[lane] : 0;
        #pragma unroll
        for (int o = 1; o < 8; o <<= 1) {
            int u = __shfl_up_sync(0xffffffffu, w, o);
            if (lane >= o) w += u;
        }
        if (lane < 8) wsum[lane] = w;
    }
    __syncthreads();
    int ex = (wid ? wsum[wid - 1] : 0) + (v - s);
    #pragma unroll
    for (int i = 0; i < 8; i++) {
        offs[base + i] = ex;
        degf[base + i] = (float)c[i];
        ex += c[i];
    }
    if (t == 255) bsum[blk] = wsum[7];
}

__global__ __launch_bounds__(256) void prep2_kernel(
    const float* __restrict__ msg_w1, const float* __restrict__ upd_w1,
    const float* __restrict__ uwp, const float* __restrict__ upd_w2,
    const float* __restrict__ in_w, const float* __restrict__ out_w,
    const float* __restrict__ ffn_w1, const float* __restrict__ ffn_w2,
    __half* __restrict__ whpdps, __half* __restrict__ whuw,
    __half* __restrict__ whu2out, __half* __restrict__ whqkv,
    __half* __restrict__ whf1, __half* __restrict__ whf2,
    __half* __restrict__ whw1c,
    const int* __restrict__ cnt, int* __restrict__ offs,
    float* __restrict__ degf, int* __restrict__ bsum)
{
    int b = blockIdx.x;
    if (b >= 1056) { scan_local_body(b - 1056, cnt, offs, degf, bsum); return; }
    if (b < 256) {
        int idx = b * 256 + threadIdx.x;
        int n = idx >> 7, k = idx & 127;
        float w = (n < 256) ? msg_w1[k * 256 + n]
                            : msg_w1[(128 + k) * 256 + (n - 256)];
        whpdps[idx] = __float2half(w);
        return;
    }
    if (b < 448) {
        int idx = (b - 256) * 256 + threadIdx.x;
        int k = idx / 128, n = idx % 128;
        float w = (k < 128) ? upd_w1[k * 128 + n] : uwp[(size_t)(k - 128) * 128 + n];
        whuw[(size_t)n * 384 + k] = __float2half(w);
        return;
    }
    if (b < 576) {
        int idx = (b - 448) * 256 + threadIdx.x;
        int n = idx >> 8, k = idx & 255;
        float w = (k < 128) ? upd_w2[k * 128 + n] : out_w[(k - 128) * 128 + n];
        whu2out[idx] = __float2half(w);
        return;
    }
    if (b < 768) {
        int idx = (b - 576) * 256 + threadIdx.x;
        int k = idx / 384, n = idx % 384;
        whqkv[(size_t)n * 128 + k] = __float2half(in_w[idx]);
        return;
    }
    if (b < 896) {
        int idx = (b - 768) * 256 + threadIdx.x;
        int k = idx / 256, n = idx % 256;
        whf1[(size_t)n * 128 + k] = __float2half(ffn_w1[idx]);
        return;
    }
    if (b < 1024) {
        int idx = (b - 896) * 256 + threadIdx.x;
        int k = idx / 128, n = idx % 128;
        whf2[(size_t)n * 256 + k] = __float2half(ffn_w2[idx]);
        return;
    }
    {
        int idx = (b - 1024) * 256 + threadIdx.x;
        int n = idx >> 5, k = idx & 31;
        whw1c[idx] = __float2half(msg_w1[(256 + k) * 256 + n]);
    }
}

// ---------------------------------------------------------------------------
// HMMA GEMM body with epilogue functor.
// ---------------------------------------------------------------------------
template<bool GELU, class Epi>
__device__ __forceinline__ void hgemm_body(
    const float* __restrict__ A1, int K1,
    const float* __restrict__ A2, int K2,
    const __half* __restrict__ Bh,
    const float* __restrict__ bias,
    const float* __restrict__ bias2,
    const float* __restrict__ rowscale,
    int m0, int n0, __half* Ah, __half* Bs, Epi epi)
{
    const int K = K1 + K2;
    const int T = K >> 5;
    const int t = threadIdx.x;

    const int arow = t >> 1, aseg = (t & 1) * 16;
    const int brow = t >> 1, bseg = (t & 1) * 16;

    float4 raf[4];
    uint4 rbu0, rbu1;
    auto ldg_tile = [&](int kb) {
        #pragma unroll
        for (int i = 0; i < 4; i++) {
            int gk = kb + aseg + i * 4;
            const float* src = (gk < K1)
                ? (A1 + (size_t)(m0 + arow) * K1 + gk)
                : (A2 + (size_t)(m0 + arow) * K2 + (gk - K1));
            raf[i] = *(const float4*)src;
        }
        const __half* bsrc = Bh + (size_t)(n0 + brow) * K + kb + bseg;
        rbu0 = *(const uint4*)bsrc;
        rbu1 = *(const uint4*)(bsrc + 8);
    };
    auto sts_tile = [&](int buf) {
        __half2* ad = (__half2*)&Ah[buf * 128 * 40 + arow * 40 + aseg];
        #pragma unroll
        for (int i = 0; i < 4; i++) {
            ad[i * 2]     = __floats2half2_rn(raf[i].x, raf[i].y);
            ad[i * 2 + 1] = __floats2half2_rn(raf[i].z, raf[i].w);
        }
        __half* bd = &Bs[buf * 128 * 40 + brow * 40 + bseg];
        *(uint4*)bd       = rbu0;
        *(uint4*)(bd + 8) = rbu1;
    };

    const int wid = t >> 5, lane = t & 31;
    const int wm = wid & 3;
    const int wn = wid >> 2;
    const int lq = lane >> 2;
    const int lr = lane & 3;

    float d[2][8][4];
    #pragma unroll
    for (int mt = 0; mt < 2; mt++)
        #pragma unroll
        for (int nt = 0; nt < 8; nt++)
            #pragma unroll
            for (int c = 0; c < 4; c++) d[mt][nt][c] = 0.0f;

    ldg_tile(0); sts_tile(0);
    for (int kt = 0; kt < T; kt++) {
        __syncthreads();
        if (kt + 1 < T) ldg_tile((kt + 1) * 32);
        const __half* ap = Ah + (kt & 1) * 128 * 40;
        const __half* bp = Bs + (kt & 1) * 128 * 40;

        uint32_t afr[2][2][4];
        #pragma unroll
        for (int mt = 0; mt < 2; mt++) {
            int r = wm * 32 + mt * 16 + lq;
            #pragma unroll
            for (int ks = 0; ks < 2; ks++) {
                int k = ks * 16 + lr * 2;
                afr[mt][ks][0] = *(const uint32_t*)&ap[r * 40 + k];
                afr[mt][ks][1] = *(const uint32_t*)&ap[(r + 8) * 40 + k];
                afr[mt][ks][2] = *(const uint32_t*)&ap[r * 40 + k + 8];
                afr[mt][ks][3] = *(const uint32_t*)&ap[(r + 8) * 40 + k + 8];
            }
        }
        #pragma unroll
        for (int nt = 0; nt < 8; nt++) {
            int n = wn * 64 + nt * 8 + lq;
            uint32_t b00 = *(const uint32_t*)&bp[n * 40 + lr * 2];
            uint32_t b10 = *(const uint32_t*)&bp[n * 40 + lr * 2 + 8];
            uint32_t b01 = *(const uint32_t*)&bp[n * 40 + 16 + lr * 2];
            uint32_t b11 = *(const uint32_t*)&bp[n * 40 + 16 + lr * 2 + 8];
            #pragma unroll
            for (int mt = 0; mt < 2; mt++) {
                mma16816(d[mt][nt], afr[mt][0], b00, b10);
                mma16816(d[mt][nt], afr[mt][1], b01, b11);
            }
        }
        if (kt + 1 < T) sts_tile((kt + 1) & 1);
    }

    #pragma unroll
    for (int mt = 0; mt < 2; mt++) {
        int row = m0 + wm * 32 + mt * 16 + lq;
        float rs0 = rowscale ? rowscale[row]     : 0.0f;
        float rs8 = rowscale ? rowscale[row + 8] : 0.0f;
        #pragma unroll
        for (int nt = 0; nt < 8; nt++) {
            int col = n0 + wn * 64 + nt * 8 + lr * 2;
            float b0v = bias ? bias[col]     : 0.0f;
            float b1v = bias ? bias[col + 1] : 0.0f;
            float c0  = bias2 ? bias2[col]     : 0.0f;
            float c1  = bias2 ? bias2[col + 1] : 0.0f;
            float v0 = d[mt][nt][0] + b0v + rs0 * c0;
            float v1 = d[mt][nt][1] + b1v + rs0 * c1;
            float v2 = d[mt][nt][2] + b0v + rs8 * c0;
            float v3 = d[mt][nt][3] + b1v + rs8 * c1;
            if (GELU) {
                v0 = gelu_f(v0); v1 = gelu_f(v1);
                v2 = gelu_f(v2); v3 = gelu_f(v3);
            }
            epi(row, col, v0, v1, v2, v3);
        }
    }
}

// fp32-out wrapper (upd1, ffn1)
template<bool GELU>
__global__ __launch_bounds__(256) void hgemm_kernel(
    const float* __restrict__ A1, int K1,
    const float* __restrict__ A2, int K2,
    const __half* __restrict__ Bh,
    const float* __restrict__ bias,
    const float* __restrict__ bias2,
    const float* __restrict__ rowscale,
    float* __restrict__ C, int NN)
{
    __shared__ __align__(16) __half Ah[2 * 128 * 40];
    __shared__ __align__(16) __half Bs[2 * 128 * 40];
    hgemm_body<GELU>(A1, K1, A2, K2, Bh, bias, bias2, rowscale,
        blockIdx.x * 128, blockIdx.y * 128, Ah, Bs,
        [&](int row, int col, float v0, float v1, float v2, float v3) {
            *(float2*)(C + (size_t)row       * NN + col) = make_float2(v0, v1);
            *(float2*)(C + (size_t)(row + 8) * NN + col) = make_float2(v2, v3);
        });
}

// P3: pdps(512 cols)+qkv(384 cols) GEMMs (896 blocks) | scan_fix (64 blocks)
__global__ __launch_bounds__(256) void prep3_kernel(
    const float* __restrict__ xn, const __half* __restrict__ whpdps,
    __half* __restrict__ pdps,
    const float* __restrict__ x, const __half* __restrict__ whqkv,
    const float* __restrict__ in_b, __half* __restrict__ qkvh,
    int* __restrict__ offs, int* __restrict__ cursor,
    const int* __restrict__ bsum)
{
    int b = blockIdx.x;
    if (b >= 896) {
        int i = (b - 896) * 256 + threadIdx.x;   // 0..16383
        int b8 = i >> 11;
        int add = 0;
        #pragma unroll
        for (int k = 0; k < 8; k++) if (k < b8) add += bsum[k];
        int v = offs[i] + add;
        offs[i] = v;
        cursor[i] = v;
        if (i == 0) offs[NV] = EV;
        return;
    }
    __shared__ __align__(16) __half Ah[2 * 128 * 40];
    __shared__ __align__(16) __half Bs[2 * 128 * 40];
    int bx = b & 127, by = b >> 7;
    if (by < 4) {
        __half* C = pdps;
        hgemm_body<false>(xn, 128, nullptr, 0, whpdps, nullptr, nullptr,
            nullptr, bx * 128, by * 128, Ah, Bs,
            [&](int row, int col, float v0, float v1, float v2, float v3) {
                *(__half2*)(C + (size_t)row       * 512 + col) = __floats2half2_rn(v0, v1);
                *(__half2*)(C + (size_t)(row + 8) * 512 + col) = __floats2half2_rn(v2, v3);
            });
    } else {
        __half* C = qkvh;
        hgemm_body<false>(x, 128, nullptr, 0, whqkv, in_b, nullptr,
            nullptr, bx * 128, (by - 4) * 128, Ah, Bs,
            [&](int row, int col, float v0, float v1, float v2, float v3) {
                *(__half2*)(C + (size_t)row       * 384 + col) = __floats2half2_rn(v0, v1);
                *(__half2*)(C + (size_t)(row + 8) * 384 + col) = __floats2half2_rn(v2, v3);
            });
    }
}

// P4: scatter
__global__ __launch_bounds__(256) void scatter_kernel(
    const int* __restrict__ dstp, const int* __restrict__ srcp,
    int* __restrict__ cursor, int* __restrict__ eperm,
    int* __restrict__ ssrc, int* __restrict__ sdst)
{
    int e = blockIdx.x * 256 + threadIdx.x;
    int d = dstp[e];
    int pos = atomicAdd(&cursor[d], 1);
    eperm[pos] = e;
    ssrc[pos]  = srcp[e];
    sdst[pos]  = d;
}

// Fused: h1 = LN( x + [t1|obuf]@[U2;Wout] + (b2+bout) ) with n1 params.
__global__ __launch_bounds__(256) void upd2_out_ln_kernel(
    const float* __restrict__ t1, const float* __restrict__ obuf,
    const __half* __restrict__ whu2out, const float* __restrict__ bcat,
    const float* __restrict__ x,
    const float* __restrict__ n1_g, const float* __restrict__ n1_b,
    float* __restrict__ h1)
{
    __shared__ __align__(16) __half Ah[2 * 128 * 40];
    __shared__ __align__(16) __half Bs[2 * 128 * 40];
    extern __shared__ float Gs[];          // [128][132]
    const int m0 = blockIdx.x * 128;

    hgemm_body<false>(t1, 128, obuf, 128, whu2out, bcat, nullptr, nullptr,
        m0, 0, Ah, Bs,
        [&](int row, int col, float v0, float v1, float v2, float v3) {
            int rl = row - m0;
            float2 x0 = *(const float2*)(x + (size_t)row       * 128 + col);
            float2 x8 = *(const float2*)(x + (size_t)(row + 8) * 128 + col);
            Gs[rl * 132 + col]           = v0 + x0.x;
            Gs[rl * 132 + col + 1]       = v1 + x0.y;
            Gs[(rl + 8) * 132 + col]     = v2 + x8.x;
            Gs[(rl + 8) * 132 + col + 1] = v3 + x8.y;
        });
    __syncthreads();

    const int t = threadIdx.x, w = t >> 5, lane = t & 31;
    float4 gg = *(const float4*)(n1_g + lane * 4);
    float4 bb = *(const float4*)(n1_b + lane * 4);
    #pragma unroll 4
    for (int i = 0; i < 16; i++) {
        int r = w * 16 + i;
        float4 v = *(const float4*)&Gs[r * 132 + lane * 4];
        float s  = v.x + v.y + v.z + v.w;
        float ss = v.x*v.x + v.y*v.y + v.z*v.z + v.w*v.w;
        #pragma unroll
        for (int o = 16; o > 0; o >>= 1) {
            s  += __shfl_xor_sync(0xffffffffu, s,  o);
            ss += __shfl_xor_sync(0xffffffffu, ss, o);
        }
        float mean = s * (1.0f / 128.0f);
        float var  = ss * (1.0f / 128.0f) - mean * mean;
        float rstd = rsqrtf(var + 1e-5f);
        float4 o4;
        o4.x = (v.x - mean) * rstd * gg.x + bb.x;
        o4.y = (v.y - mean) * rstd * gg.y + bb.y;
        o4.z = (v.z - mean) * rstd * gg.z + bb.z;
        o4.w = (v.w - mean) * rstd * gg.w + bb.w;
        *(float4*)(h1 + (size_t)(m0 + r) * 128 + lane * 4) = o4;
    }
}

// Fused: out = LN( h1 + ffn@W2+b2 ) with n2 params.
__global__ __launch_bounds__(256) void ffn_ln_kernel(
    const float* __restrict__ ffnb, const __half* __restrict__ whf2,
    const float* __restrict__ ffn_b2,
    const float* __restrict__ h1,
    const float* __restrict__ n2_g, const float* __restrict__ n2_b,
    float* __restrict__ out)
{
    __shared__ __align__(16) __half Ah[2 * 128 * 40];
    __shared__ __align__(16) __half Bs[2 * 128 * 40];
    extern __shared__ float Gs[];          // [128][132]
    const int m0 = blockIdx.x * 128;

    hgemm_body<false>(ffnb, 256, nullptr, 0, whf2, ffn_b2, nullptr, nullptr,
        m0, 0, Ah, Bs,
        [&](int row, int col, float v0, float v1, float v2, float v3) {
            int rl = row - m0;
            float2 h0 = *(const float2*)(h1 + (size_t)row       * 128 + col);
            float2 h8 = *(const float2*)(h1 + (size_t)(row + 8) * 128 + col);
            Gs[rl * 132 + col]           = v0 + h0.x;
            Gs[rl * 132 + col + 1]       = v1 + h0.y;
            Gs[(rl + 8) * 132 + col]     = v2 + h8.x;
            Gs[(rl + 8) * 132 + col + 1] = v3 + h8.y;
        });
    __syncthreads();

    const int t = threadIdx.x, w = t >> 5, lane = t & 31;
    float4 gg = *(const float4*)(n2_g + lane * 4);
    float4 bb = *(const float4*)(n2_b + lane * 4);
    #pragma unroll 4
    for (int i = 0; i < 16; i++) {
        int r = w * 16 + i;
        float4 v = *(const float4*)&Gs[r * 132 + lane * 4];
        float s  = v.x + v.y + v.z + v.w;
        float ss = v.x*v.x + v.y*v.y + v.z*v.z + v.w*v.w;
        #pragma unroll
        for (int o = 16; o > 0; o >>= 1) {
            s  += __shfl_xor_sync(0xffffffffu, s,  o);
            ss += __shfl_xor_sync(0xffffffffu, ss, o);
        }
        float mean = s * (1.0f / 128.0f);
        float var  = ss * (1.0f / 128.0f) - mean * mean;
        float rstd = rsqrtf(var + 1e-5f);
        float4 o4;
        o4.x = (v.x - mean) * rstd * gg.x + bb.x;
        o4.y = (v.y - mean) * rstd * gg.y + bb.y;
        o4.z = (v.z - mean) * rstd * gg.z + bb.z;
        o4.w = (v.w - mean) * rstd * gg.w + bb.w;
        *(float4*)(out + (size_t)(m0 + r) * 128 + lane * 4) = o4;
    }
}

// ---------------------------------------------------------------------------
// Edge body: MLP + gelu + in-block segmented reduce. 256 threads.
// ---------------------------------------------------------------------------
__device__ __forceinline__ void edge_body(
    char* smraw, int eb,
    const float* __restrict__ ea, const int* __restrict__ eperm,
    const __half* __restrict__ whw1c, const float* __restrict__ b1,
    const __half* __restrict__ pdps,
    const int* __restrict__ sdst, const int* __restrict__ ssrc,
    float* __restrict__ aggrH)
{
    __half* Ws  = (__half*)smraw;                  // [256][36]
    __half* As  = Ws + 256 * 36;                   // [64][36]
    __half* Gsm = As + 64 * 36;                    // [64][264]
    float*  b1s = (float*)(Gsm + 64 * 264);        // [256]
    int*    ds  = (int*)(b1s + 256);               // [64]
    const int t  = threadIdx.x;
    const int e0 = eb * 64;

    {
        b1s[t] = b1[t];
        const uint4* wsrc = (const uint4*)whw1c;
        #pragma unroll
        for (int i = 0; i < 4; i++) {
            int u = t * 4 + i;
            int row = u >> 2, seg = (u & 3) * 8;
            uint4 v = wsrc[u];
            uint2* dst = (uint2*)&Ws[row * 36 + seg];
            dst[0] = make_uint2(v.x, v.y);
            dst[1] = make_uint2(v.z, v.w);
        }
    }
    {
        int el = t >> 2, part = t & 3;
        int e = eperm[e0 + el];
        const float4* src = (const float4*)(ea + (size_t)e * 32 + part * 8);
        float4 v0 = src[0], v1 = src[1];
        __half2* dst = (__half2*)(As + el * 36 + part * 8);
        dst[0] = __floats2half2_rn(v0.x, v0.y);
        dst[1] = __floats2half2_rn(v0.z, v0.w);
        dst[2] = __floats2half2_rn(v1.x, v1.y);
        dst[3] = __floats2half2_rn(v1.z, v1.w);
    }
    if (t < 64) ds[t] = sdst[e0 + t];
    __syncthreads();

    const int wid = t >> 5, lane = t & 31;
    const int wm = wid >> 2;
    const int wn = wid & 3;
    const int lq = lane >> 2;
    const int lr = lane & 3;

    float d[2][8][4];
    #pragma unroll
    for (int mt = 0; mt < 2; mt++)
        #pragma unroll
        for (int nt = 0; nt < 8; nt++)
            #pragma unroll
            for (int c = 0; c < 4; c++) d[mt][nt][c] = 0.0f;

    uint32_t afr[2][2][4];
    #pragma unroll
    for (int mt = 0; mt < 2; mt++) {
        int r = wm * 32 + mt * 16 + lq;
        #pragma unroll
        for (int ks = 0; ks < 2; ks++) {
            int k = ks * 16 + lr * 2;
            afr[mt][ks][0] = *(const uint32_t*)&As[r * 36 + k];
            afr[mt][ks][1] = *(const uint32_t*)&As[(r + 8) * 36 + k];
            afr[mt][ks][2] = *(const uint32_t*)&As[r * 36 + k + 8];
            afr[mt][ks][3] = *(const uint32_t*)&As[(r + 8) * 36 + k + 8];
        }
    }

    #pragma unroll
    for (int nt = 0; nt < 8; nt++) {
        int n = wn * 64 + nt * 8 + lq;
        uint32_t b0k0 = *(const uint32_t*)&Ws[n * 36 + lr * 2];
        uint32_t b1k0 = *(const uint32_t*)&Ws[n * 36 + lr * 2 + 8];
        uint32_t b0k1 = *(const uint32_t*)&Ws[n * 36 + 16 + lr * 2];
        uint32_t b1k1 = *(const uint32_t*)&Ws[n * 36 + 16 + lr * 2 + 8];
        #pragma unroll
        for (int mt = 0; mt < 2; mt++) {
            mma16816(d[mt][nt], afr[mt][0], b0k0, b1k0);
            mma16816(d[mt][nt], afr[mt][1], b0k1, b1k1);
        }
    }

    #pragma unroll
    for (int mt = 0; mt < 2; mt++) {
        int l0 = wm * 32 + mt * 16 + lq;
        int l8 = l0 + 8;
        int j0 = e0 + l0, j8 = e0 + l8;
        const __half* pd0 = pdps + (size_t)sdst[j0] * 512;
        const __half* ps0 = pdps + (size_t)ssrc[j0] * 512 + 256;
        const __half* pd8 = pdps + (size_t)sdst[j8] * 512;
        const __half* ps8 = pdps + (size_t)ssrc[j8] * 512 + 256;
        #pragma unroll
        for (int nt = 0; nt < 8; nt++) {
            int col = wn * 64 + nt * 8 + lr * 2;
            float2 a0 = __half22float2(*(const __half2*)(pd0 + col));
            float2 s0 = __half22float2(*(const __half2*)(ps0 + col));
            float2 a8 = __half22float2(*(const __half2*)(pd8 + col));
            float2 s8 = __half22float2(*(const __half2*)(ps8 + col));
            float bx = b1s[col], by = b1s[col + 1];
            float v0 = gelu_f(d[mt][nt][0] + bx + a0.x + s0.x);
            float v1 = gelu_f(d[mt][nt][1] + by + a0.y + s0.y);
            float v2 = gelu_f(d[mt][nt][2] + bx + a8.x + s8.x);
            float v3 = gelu_f(d[mt][nt][3] + by + a8.y + s8.y);
            *(__half2*)(Gsm + l0 * 264 + col) = __floats2half2_rn(v0, v1);
            *(__half2*)(Gsm + l8 * 264 + col) = __floats2half2_rn(v2, v3);
        }
    }
    __syncthreads();

    {
        int c = t;
        float acc = 0.0f;
        int prev = ds[0];
        #pragma unroll 8
        for (int r = 0; r < 64; r++) {
            int nd = ds[r];
            if (nd != prev) {
                atomicAdd(&aggrH[(size_t)prev * 256 + c], acc);
                acc = 0.0f;
                prev = nd;
            }
            acc += __half2float(Gsm[r * 264 + c]);
        }
        atomicAdd(&aggrH[(size_t)prev * 256 + c], acc);
    }
}

// ---------------------------------------------------------------------------
// Attention body (256-thread loads; warps 0-3 compute). Ks/Qs stride 36.
// ---------------------------------------------------------------------------
#define VTS 514
__device__ __forceinline__ void attn_body(
    char* smraw, int ab,
    const __half* __restrict__ qkv, float* __restrict__ o)
{
    __half* Ks = (__half*)smraw;            // [512][36]
    __half* Vt = Ks + 512 * 36;             // [32][VTS]
    __half* Qs = Vt + 32 * VTS;             // [64][36]
    const int t  = threadIdx.x;
    const int g  = ab >> 5;
    const int h  = (ab >> 3) & 3;
    const int qb = ab & 7;
    const size_t gb = (size_t)g * 512;
    const float scale = 0.17677669529663687f;

    #pragma unroll
    for (int i = 0; i < 16; i++) {
        int task = t + i * 256;
        int row = task >> 3, seg = task & 7;
        uint2 v = *(const uint2*)(qkv + (gb + row) * 384 + 128 + h * 32 + seg * 4);
        *(uint2*)&Ks[row * 36 + seg * 4] = v;
    }
    #pragma unroll
    for (int i = 0; i < 16; i++) {
        int task = t + i * 256;
        int row = task >> 3, seg = task & 7;
        const __half* src = qkv + (gb + row) * 384 + 256 + h * 32 + seg * 4;
        int d0 = seg * 4;
        Vt[(d0 + 0) * VTS + row] = src[0];
        Vt[(d0 + 1) * VTS + row] = src[1];
        Vt[(d0 + 2) * VTS + row] = src[2];
        Vt[(d0 + 3) * VTS + row] = src[3];
    }
    #pragma unroll
    for (int i = 0; i < 2; i++) {
        int task = t + i * 256;
        int row = task >> 3, seg = task & 7;
        const __half2* src = (const __half2*)(qkv + (gb + qb * 64 + row) * 384 + h * 32 + seg * 4);
        float2 v0 = __half22float2(src[0]);
        float2 v1 = __half22float2(src[1]);
        __half2* d = (__half2*)&Qs[row * 36 + seg * 4];
        d[0] = __floats2half2_rn(v0.x * scale, v0.y * scale);
        d[1] = __floats2half2_rn(v1.x * scale, v1.y * scale);
    }
    __syncthreads();

    if (t >= 128) return;

    const int wq = t >> 5, lane = t & 31;
    const int lq = lane >> 2, lr = lane & 3;

    uint32_t aq[2][4];
    #pragma unroll
    for (int ks = 0; ks < 2; ks++) {
        int base = (wq * 16 + lq) * 36 + ks * 16 + lr * 2;
        aq[ks][0] = *(const uint32_t*)&Qs[base];
        aq[ks][1] = *(const uint32_t*)&Qs[base + 8 * 36];
        aq[ks][2] = *(const uint32_t*)&Qs[base + 8];
        aq[ks][3] = *(const uint32_t*)&Qs[base + 8 * 36 + 8];
    }

    float m0 = -1e30f, m1 = -1e30f, l0 = 0.0f, l1 = 0.0f;
    float oA[4][4];
    #pragma unroll
    for (int n = 0; n < 4; n++)
        #pragma unroll
        for (int c = 0; c < 4; c++) oA[n][c] = 0.0f;

    for (int c = 0; c < 8; c++) {
        float s[8][4];
        #pragma unroll
        for (int nt = 0; nt < 8; nt++)
            #pragma unroll
            for (int q = 0; q < 4; q++) s[nt][q] = 0.0f;
        #pragma unroll
        for (int nt = 0; nt < 8; nt++) {
            int kb = (c * 64 + nt * 8 + lq) * 36 + lr * 2;
            mma16816(s[nt], aq[0], *(const uint32_t*)&Ks[kb],
                                    *(const uint32_t*)&Ks[kb + 8]);
            mma16816(s[nt], aq[1], *(const uint32_t*)&Ks[kb + 16],
                                    *(const uint32_t*)&Ks[kb + 24]);
        }
        float mc0 = -1e30f, mc1 = -1e30f;
        #pragma unroll
        for (int nt = 0; nt < 8; nt++) {
            mc0 = fmaxf(mc0, fmaxf(s[nt][0], s[nt][1]));
            mc1 = fmaxf(mc1, fmaxf(s[nt][2], s[nt][3]));
        }
        mc0 = fmaxf(mc0, __shfl_xor_sync(0xffffffffu, mc0, 1));
        mc0 = fmaxf(mc0, __shfl_xor_sync(0xffffffffu, mc0, 2));
        mc1 = fmaxf(mc1, __shfl_xor_sync(0xffffffffu, mc1, 1));
        mc1 = fmaxf(mc1, __shfl_xor_sync(0xffffffffu, mc1, 2));
        float mn0 = fmaxf(m0, mc0), mn1 = fmaxf(m1, mc1);
        float cr0 = __expf(m0 - mn0), cr1 = __expf(m1 - mn1);
        m0 = mn0; m1 = mn1;
        float rs0 = 0.0f, rs1 = 0.0f;
        #pragma unroll
        for (int nt = 0; nt < 8; nt++) {
            s[nt][0] = __expf(s[nt][0] - m0); rs0 += s[nt][0];
            s[nt][1] = __expf(s[nt][1] - m0); rs0 += s[nt][1];
            s[nt][2] = __expf(s[nt][2] - m1); rs1 += s[nt][2];
            s[nt][3] = __expf(s[nt][3] - m1); rs1 += s[nt][3];
        }
        rs0 += __shfl_xor_sync(0xffffffffu, rs0, 1);
        rs0 += __shfl_xor_sync(0xffffffffu, rs0, 2);
        rs1 += __shfl_xor_sync(0xffffffffu, rs1, 1);
        rs1 += __shfl_xor_sync(0xffffffffu, rs1, 2);
        l0 = l0 * cr0 + rs0;
        l1 = l1 * cr1 + rs1;
        #pragma unroll
        for (int n = 0; n < 4; n++) {
            oA[n][0] *= cr0; oA[n][1] *= cr0;
            oA[n][2] *= cr1; oA[n][3] *= cr1;
        }
        #pragma unroll
        for (int kt = 0; kt < 4; kt++) {
            uint32_t a[4];
            a[0] = packh2(s[2 * kt][0],     s[2 * kt][1]);
            a[1] = packh2(s[2 * kt][2],     s[2 * kt][3]);
            a[2] = packh2(s[2 * kt + 1][0], s[2 * kt + 1][1]);
            a[3] = packh2(s[2 * kt + 1][2], s[2 * kt + 1][3]);
            #pragma unroll
            for (int nd = 0; nd < 4; nd++) {
                int vb = (nd * 8 + lq) * VTS + c * 64 + kt * 16 + lr * 2;
                mma16816(oA[nd], a, *(const uint32_t*)&Vt[vb],
                                     *(const uint32_t*)&Vt[vb + 8]);
            }
        }
    }

    float i0 = 1.0f / l0, i1 = 1.0f / l1;
    int row = qb * 64 + wq * 16 + lq;
    float* orow = o + (gb + row) * 128 + h * 32;
    #pragma unroll
    for (int nd = 0; nd < 4; nd++) {
        *(float2*)(orow + nd * 8 + lr * 2) =
            make_float2(oA[nd][0] * i0, oA[nd][1] * i0);
        *(float2*)(orow + 8 * 128 + nd * 8 + lr * 2) =
            make_float2(oA[nd][2] * i1, oA[nd][3] * i1);
    }
}

// P5: merged attention (blocks 0..1023) + edge (1024..5119)
__global__ __launch_bounds__(256) void edge_attn_kernel(
    const __half* __restrict__ qkvh, float* __restrict__ obuf,
    const float* __restrict__ ea, const int* __restrict__ eperm,
    const __half* __restrict__ whw1c, const float* __restrict__ b1,
    const __half* __restrict__ pdps,
    const int* __restrict__ sdst, const int* __restrict__ ssrc,
    float* __restrict__ aggrH)
{
    extern __shared__ __align__(16) char smraw[];
    int b = blockIdx.x;
    if (b < 1024)
        attn_body(smraw, b, qkvh, obuf);
    else
        edge_body(smraw, b - 1024, ea, eperm, whw1c, b1, pdps, sdst, ssrc, aggrH);
}

// ---------------------------------------------------------------------------
// Host launcher
// ---------------------------------------------------------------------------
extern "C" void kernel_launch(void* const* d_in, const int* in_sizes, int n_in,
                              void* d_out, int out_size)
{
    const float* x      = (const float*)d_in[0];
    const int*   eidx   = (const int*)  d_in[1];
    const float* ea     = (const float*)d_in[2];
    /* d_in[3] = batch (unused) */
    const float* gnn_g  = (const float*)d_in[4];
    const float* gnn_b  = (const float*)d_in[5];
    const float* msg_w1 = (const float*)d_in[6];
    const float* msg_b1 = (const float*)d_in[7];
    const float* msg_w2 = (const float*)d_in[8];
    const float* msg_b2 = (const float*)d_in[9];
    const float* upd_w1 = (const float*)d_in[10];
    const float* upd_b1 = (const float*)d_in[11];
    const float* upd_w2 = (const float*)d_in[12];
    const float* upd_b2 = (const float*)d_in[13];
    const float* in_w   = (const float*)d_in[14];
    const float* in_b   = (const float*)d_in[15];
    const float* out_w  = (const float*)d_in[16];
    const float* out_b  = (const float*)d_in[17];
    const float* ffn_w1 = (const float*)d_in[18];
    const float* ffn_b1 = (const float*)d_in[19];
    const float* ffn_w2 = (const float*)d_in[20];
    const float* ffn_b2 = (const float*)d_in[21];
    const float* n1_g   = (const float*)d_in[22];
    const float* n1_b   = (const float*)d_in[23];
    const float* n2_g   = (const float*)d_in[24];
    const float* n2_b   = (const float*)d_in[25];
    float* out = (float*)d_out;

    const int* srcp = eidx;
    const int* dstp = eidx + EV;

    float *xn, *aggrH, *t1, *obuf, *h1, *ffn, *deg, *uwp, *b2u, *bcat;
    __half *pdps, *qkvh, *whpdps, *whuw, *whu2out, *whqkv, *whf1, *whf2, *whw1c;
    int *cnt, *offs, *cursor, *eperm, *ssrc, *sdst, *bsum;
    cudaGetSymbolAddress((void**)&xn,    g_xn);
    cudaGetSymbolAddress((void**)&pdps,  g_pdps);
    cudaGetSymbolAddress((void**)&aggrH, g_aggrH);
    cudaGetSymbolAddress((void**)&t1,    g_t1);
    cudaGetSymbolAddress((void**)&qkvh,  g_qkvh);
    cudaGetSymbolAddress((void**)&obuf,  g_obuf);
    cudaGetSymbolAddress((void**)&h1,    g_h1);
    cudaGetSymbolAddress((void**)&ffn,   g_ffn);
    cudaGetSymbolAddress((void**)&deg,   g_deg);
    cudaGetSymbolAddress((void**)&uwp,   g_uwp);
    cudaGetSymbolAddress((void**)&b2u,   g_b2u);
    cudaGetSymbolAddress((void**)&bcat,  g_bcat);
    cudaGetSymbolAddress((void**)&cnt,   g_cnt);
    cudaGetSymbolAddress((void**)&offs,  g_offs);
    cudaGetSymbolAddress((void**)&cursor,g_cursor);
    cudaGetSymbolAddress((void**)&eperm, g_eperm);
    cudaGetSymbolAddress((void**)&ssrc,  g_ssrc);
    cudaGetSymbolAddress((void**)&sdst,  g_sdst);
    cudaGetSymbolAddress((void**)&bsum,  g_bsum);
    cudaGetSymbolAddress((void**)&whpdps, g_wh_pdps);
    cudaGetSymbolAddress((void**)&whuw,   g_wh_uw);
    cudaGetSymbolAddress((void**)&whu2out,g_wh_u2out);
    cudaGetSymbolAddress((void**)&whqkv,  g_wh_qkv);
    cudaGetSymbolAddress((void**)&whf1,   g_wh_f1);
    cudaGetSymbolAddress((void**)&whf2,   g_wh_f2);
    cudaGetSymbolAddress((void**)&whw1c,  g_wh_w1c);

    cudaFuncSetAttribute(edge_attn_kernel,
                         cudaFuncAttributeMaxDynamicSharedMemorySize, 74368);
    cudaFuncSetAttribute(upd2_out_ln_kernel,
                         cudaFuncAttributeMaxDynamicSharedMemorySize, 67584);
    cudaFuncSetAttribute(ffn_ln_kernel,
                         cudaFuncAttributeMaxDynamicSharedMemorySize, 67584);

    // 0) cnt zero (must precede P1's hist)
    cudaMemsetAsync(cnt, 0, NV * sizeof(int), 0);

    // P1: prep-GEMM | aggrH zero | prep_bias | hist | LN(x)
    prep1_kernel<<<3589, 256>>>(
        msg_w2, upd_w1 + 128 * 128, uwp,
        msg_b2, upd_b2, out_b, b2u, bcat,
        dstp, cnt, x, gnn_g, gnn_b, xn, aggrH);

    // P2: convw (all fp16 tables) | scan_local
    prep2_kernel<<<1064, 256>>>(
        msg_w1, upd_w1, uwp, upd_w2, in_w, out_w, ffn_w1, ffn_w2,
        whpdps, whuw, whu2out, whqkv, whf1, whf2, whw1c,
        cnt, offs, deg, bsum);

    // P3: pdps+qkv GEMMs | scan_fix
    prep3_kernel<<<960, 256>>>(
        xn, whpdps, pdps, x, whqkv, in_b, qkvh, offs, cursor, bsum);

    // P4: scatter
    scatter_kernel<<<EV / 256, 256>>>(dstp, srcp, cursor, eperm, ssrc, sdst);

    // P5: merged flash attention + edge MLP/reduce
    edge_attn_kernel<<<1024 + EV / 64, 256, 74368>>>(
        qkvh, obuf, ea, eperm, whw1c, msg_b1, pdps, sdst, ssrc, aggrH);

    // tail: upd1 -> upd2+out+LN -> ffn1 -> ffn2+LN
    hgemm_kernel<true><<<dim3(NV / 128, 1), 256>>>(
        xn, 128, aggrH, 256, whuw, upd_b1, b2u, deg, t1, 128);
    upd2_out_ln_kernel<<<NV / 128, 256, 67584>>>(
        t1, obuf, whu2out, bcat, x, n1_g, n1_b, h1);
    hgemm_kernel<true><<<dim3(NV / 128, 2), 256>>>(
        h1, 128, nullptr, 0, whf1, ffn_b1, nullptr, nullptr, ffn, 256);
    ffn_ln_kernel<<<NV / 128, 256, 67584>>>(
        ffn, whf2, ffn_b2, h1, n2_g, n2_b, out);
}

// round 16
// speedup vs baseline: 1.0953x; 1.0076x over previous
#include <cuda_runtime.h>
#include <cuda_fp16.h>
#include <math.h>
#include <cstdint>

// ---------------------------------------------------------------------------
// Problem constants
// ---------------------------------------------------------------------------
#define NV   16384      // nodes
#define DV   128        // node dim
#define EDV  32         // edge feat dim
#define EV   262144     // edges
#define GV   32         // graphs
#define SV   512        // seq per graph
#define HV   4          // heads
#define HDV  32         // head dim

// ---------------------------------------------------------------------------
// Scratch buffers (device globals; no runtime allocation allowed)
// ---------------------------------------------------------------------------
__device__ float  g_xn   [NV * DV];
__device__ __half g_pdps [NV * 512];
__device__ float  g_aggrH[NV * 256];
__device__ float  g_t1   [NV * DV];
__device__ __half g_qkvh [NV * 3 * DV];
__device__ float  g_obuf [NV * DV];
__device__ float  g_h1   [NV * DV];
__device__ float  g_uwp  [256 * 128];   // msg_w2 @ U1b
__device__ float  g_b2u  [128];
__device__ float  g_bcat [128];
__device__ int    g_cnt   [NV];
__device__ int    g_offs  [NV + 1];
__device__ int    g_cursor[NV];
__device__ int    g_eperm [EV];
__device__ int    g_ssrc  [EV];
__device__ int    g_sdst  [EV];
__device__ float  g_deg   [NV];
__device__ int    g_bsum  [8];

// fp16 transposed weight tables [N][K]
__device__ __half g_wh_pdps [512 * 128];
__device__ __half g_wh_uw   [128 * 384];
__device__ __half g_wh_u2out[128 * 256];
__device__ __half g_wh_qkv  [384 * 128];
__device__ __half g_wh_f1   [256 * 128];
__device__ __half g_wh_f2   [128 * 256];
__device__ __half g_wh_w1c  [256 * 32];

// ---------------------------------------------------------------------------
// helpers
// ---------------------------------------------------------------------------
typedef unsigned long long u64;

__device__ __forceinline__ u64 dup2(float x) {
    u64 r; asm("mov.b64 %0, {%1, %1};" : "=l"(r) : "f"(x)); return r;
}
__device__ __forceinline__ float2 unpack2(u64 v) {
    float2 r; asm("mov.b64 {%0, %1}, %2;" : "=f"(r.x), "=f"(r.y) : "l"(v)); return r;
}
__device__ __forceinline__ void fma2(u64& d, u64 a, u64 b) {
    asm("fma.rn.f32x2 %0, %1, %2, %0;" : "+l"(d) : "l"(a), "l"(b));
}

__device__ __forceinline__ float gelu_f(float v) {
    return 0.5f * v * (1.0f + erff(v * 0.70710678118654752f));
}

__device__ __forceinline__ void mma16816(
    float* d, const uint32_t* a, uint32_t b0, uint32_t b1)
{
    asm volatile(
        "mma.sync.aligned.m16n8k16.row.col.f32.f16.f16.f32 "
        "{%0,%1,%2,%3}, {%4,%5,%6,%7}, {%8,%9}, {%0,%1,%2,%3};"
        : "+f"(d[0]), "+f"(d[1]), "+f"(d[2]), "+f"(d[3])
        : "r"(a[0]), "r"(a[1]), "r"(a[2]), "r"(a[3]), "r"(b0), "r"(b1));
}

__device__ __forceinline__ uint32_t packh2(float a, float b) {
    __half2 h = __floats2half2_rn(a, b);
    return *(uint32_t*)&h;
}

// ---------------------------------------------------------------------------
// LN body: one block = 8 rows (8 warps), 256 threads.
// ---------------------------------------------------------------------------
__device__ __forceinline__ void ln_body(
    int blk, const float* __restrict__ a, const float* __restrict__ g,
    const float* __restrict__ be, float* __restrict__ out)
{
    int row  = blk * 8 + (threadIdx.x >> 5);
    int lane = threadIdx.x & 31;
    size_t off = (size_t)row * 128 + lane * 4;
    float4 v = *(const float4*)(a + off);
    float s  = v.x + v.y + v.z + v.w;
    float ss = v.x*v.x + v.y*v.y + v.z*v.z + v.w*v.w;
    #pragma unroll
    for (int o = 16; o > 0; o >>= 1) {
        s  += __shfl_xor_sync(0xffffffffu, s,  o);
        ss += __shfl_xor_sync(0xffffffffu, ss, o);
    }
    float mean = s * (1.0f / 128.0f);
    float var  = ss * (1.0f / 128.0f) - mean * mean;
    float rstd = rsqrtf(var + 1e-5f);
    float4 gg = *(const float4*)(g  + lane * 4);
    float4 bb = *(const float4*)(be + lane * 4);
    float4 o4;
    o4.x = (v.x - mean) * rstd * gg.x + bb.x;
    o4.y = (v.y - mean) * rstd * gg.y + bb.y;
    o4.z = (v.z - mean) * rstd * gg.z + bb.z;
    o4.w = (v.w - mean) * rstd * gg.w + bb.w;
    *(float4*)(out + off) = o4;
}

// ---------------------------------------------------------------------------
// Prep fp32 GEMM body: uwp[256,128] = msg_w2[256,128] @ U1b[128,128].
// ---------------------------------------------------------------------------
__device__ void gemm_prep_body(
    int blk, const float* __restrict__ A1, const float* __restrict__ B,
    float* __restrict__ C)
{
    const int K1 = 128, NN = 128, T = 8;
    __shared__ float As[2][16 * 128];
    __shared__ float Bs[2][16 * 64];
    const int t  = threadIdx.x;
    const int m0 = (blk & 1) * 128;
    const int n0 = (blk >> 1) * 64;
    const int mg = t >> 4;
    const int ng = t & 15;
    const int k4own = (t & 3) * 4;
    int rowA[2];
    #pragma unroll
    for (int i = 0; i < 2; i++) rowA[i] = m0 + ((t + i * 256) >> 2);

    float4 ra[2], rb;
    auto ldg_tile = [&](int kt) {
        int kb = kt * 16;
        #pragma unroll
        for (int i = 0; i < 2; i++)
            ra[i] = *(const float4*)(A1 + (size_t)rowA[i] * K1 + kb + k4own);
        int r = t >> 4, c4 = t & 15;
        rb = *(const float4*)(B + (size_t)(kb + r) * NN + n0 + c4 * 4);
    };
    auto sts_tile = [&](int buf) {
        #pragma unroll
        for (int i = 0; i < 2; i++) {
            int cc = t + i * 256;
            int m = cc >> 2, k4 = cc & 3;
            As[buf][(k4 * 4 + 0) * 128 + m] = ra[i].x;
            As[buf][(k4 * 4 + 1) * 128 + m] = ra[i].y;
            As[buf][(k4 * 4 + 2) * 128 + m] = ra[i].z;
            As[buf][(k4 * 4 + 3) * 128 + m] = ra[i].w;
        }
        int r = t >> 4, c4 = t & 15;
        *(float4*)&Bs[buf][r * 64 + c4 * 4] = rb;
    };

    u64 acc[4][4];
    #pragma unroll
    for (int i = 0; i < 4; i++)
        #pragma unroll
        for (int j = 0; j < 4; j++) acc[i][j] = 0ull;

    ldg_tile(0); sts_tile(0);
    for (int kt = 0; kt < T; kt++) {
        __syncthreads();
        if (kt + 1 < T) ldg_tile(kt + 1);
        const float* ap = As[kt & 1];
        const float* bp = Bs[kt & 1];
        #pragma unroll
        for (int k = 0; k < 16; k++) {
            ulonglong2 a01 = *(const ulonglong2*)(ap + k * 128 + mg * 8);
            ulonglong2 a23 = *(const ulonglong2*)(ap + k * 128 + mg * 8 + 4);
            float4 b = *(const float4*)(bp + k * 64 + ng * 4);
            u64 am[4] = {a01.x, a01.y, a23.x, a23.y};
            u64 bd[4] = {dup2(b.x), dup2(b.y), dup2(b.z), dup2(b.w)};
            #pragma unroll
            for (int i = 0; i < 4; i++)
                #pragma unroll
                for (int j = 0; j < 4; j++)
                    fma2(acc[i][j], am[i], bd[j]);
        }
        if (kt + 1 < T) sts_tile((kt + 1) & 1);
    }

    #pragma unroll
    for (int i = 0; i < 4; i++) {
        int r0 = m0 + mg * 8 + 2 * i;
        float2 v0 = unpack2(acc[i][0]);
        float2 v1 = unpack2(acc[i][1]);
        float2 v2 = unpack2(acc[i][2]);
        float2 v3 = unpack2(acc[i][3]);
        *(float4*)(C + (size_t)r0       * NN + n0 + ng * 4) = make_float4(v0.x, v1.x, v2.x, v3.x);
        *(float4*)(C + (size_t)(r0 + 1) * NN + n0 + ng * 4) = make_float4(v0.y, v1.y, v2.y, v3.y);
    }
}

// ---------------------------------------------------------------------------
// P1: prep-GEMM(4) | aggrH zero(512) | prep_bias(1) | hist(1024) | LN(2048)
// ---------------------------------------------------------------------------
__global__ __launch_bounds__(256) void prep1_kernel(
    const float* __restrict__ msg_w2, const float* __restrict__ U1b,
    float* __restrict__ uwp,
    const float* __restrict__ msg_b2, const float* __restrict__ upd_b2,
    const float* __restrict__ out_b,
    float* __restrict__ b2u, float* __restrict__ bcat,
    const int* __restrict__ dstp, int* __restrict__ cnt,
    const float* __restrict__ x, const float* __restrict__ gnn_g,
    const float* __restrict__ gnn_b, float* __restrict__ xn,
    float* __restrict__ aggrH)
{
    int b = blockIdx.x;
    if (b < 4) { gemm_prep_body(b, msg_w2, U1b, uwp); return; }
    if (b < 516) {
        float4 z = make_float4(0.f, 0.f, 0.f, 0.f);
        float4* p = (float4*)(aggrH + (size_t)(b - 4) * 8192);
        #pragma unroll
        for (int i = 0; i < 8; i++) p[threadIdx.x + i * 256] = z;
        return;
    }
    if (b == 516) {
        int n = threadIdx.x;
        if (n < 128) {
            float s = 0.0f;
            for (int k = 0; k < 128; k++) s = fmaf(msg_b2[k], U1b[k * 128 + n], s);
            b2u[n]  = s;
            bcat[n] = upd_b2[n] + out_b[n];
        }
        return;
    }
    if (b < 1541) {
        int e = (b - 517) * 256 + threadIdx.x;
        atomicAdd(&cnt[dstp[e]], 1);
        return;
    }
    ln_body(b - 1541, x, gnn_g, gnn_b, xn);
}

// ---------------------------------------------------------------------------
// P2: convw(1056) | scan_local(8) = 1064 blocks.
// ---------------------------------------------------------------------------
__device__ __forceinline__ void scan_local_body(
    int blk, const int* __restrict__ cnt, int* __restrict__ offs,
    float* __restrict__ degf, int* __restrict__ bsum)
{
    __shared__ int wsum[8];
    int t = threadIdx.x;
    int base = blk * 2048 + t * 8;
    int c[8]; int s = 0;
    #pragma unroll
    for (int i = 0; i < 8; i++) { c[i] = cnt[base + i]; s += c[i]; }
    int lane = t & 31, wid = t >> 5;
    int v = s;
    #pragma unroll
    for (int o = 1; o < 32; o <<= 1) {
        int u = __shfl_up_sync(0xffffffffu, v, o);
        if (lane >= o) v += u;
    }
    if (lane == 31) wsum[wid] = v;
    __syncthreads();
    if (t < 32) {
        int w = (lane < 8) ? wsum[lane] : 0;
        #pragma unroll
        for (int o = 1; o < 8; o <<= 1) {
            int u = __shfl_up_sync(0xffffffffu, w, o);
            if (lane >= o) w += u;
        }
        if (lane < 8) wsum[lane] = w;
    }
    __syncthreads();
    int ex = (wid ? wsum[wid - 1] : 0) + (v - s);
    #pragma unroll
    for (int i = 0; i < 8; i++) {
        offs[base + i] = ex;
        degf[base + i] = (float)c[i];
        ex += c[i];
    }
    if (t == 255) bsum[blk] = wsum[7];
}

__global__ __launch_bounds__(256) void prep2_kernel(
    const float* __restrict__ msg_w1, const float* __restrict__ upd_w1,
    const float* __restrict__ uwp, const float* __restrict__ upd_w2,
    const float* __restrict__ in_w, const float* __restrict__ out_w,
    const float* __restrict__ ffn_w1, const float* __restrict__ ffn_w2,
    __half* __restrict__ whpdps, __half* __restrict__ whuw,
    __half* __restrict__ whu2out, __half* __restrict__ whqkv,
    __half* __restrict__ whf1, __half* __restrict__ whf2,
    __half* __restrict__ whw1c,
    const int* __restrict__ cnt, int* __restrict__ offs,
    float* __restrict__ degf, int* __restrict__ bsum)
{
    int b = blockIdx.x;
    if (b >= 1056) { scan_local_body(b - 1056, cnt, offs, degf, bsum); return; }
    if (b < 256) {
        int idx = b * 256 + threadIdx.x;
        int n = idx >> 7, k = idx & 127;
        float w = (n < 256) ? msg_w1[k * 256 + n]
                            : msg_w1[(128 + k) * 256 + (n - 256)];
        whpdps[idx] = __float2half(w);
        return;
    }
    if (b < 448) {
        int idx = (b - 256) * 256 + threadIdx.x;
        int k = idx / 128, n = idx % 128;
        float w = (k < 128) ? upd_w1[k * 128 + n] : uwp[(size_t)(k - 128) * 128 + n];
        whuw[(size_t)n * 384 + k] = __float2half(w);
        return;
    }
    if (b < 576) {
        int idx = (b - 448) * 256 + threadIdx.x;
        int n = idx >> 8, k = idx & 255;
        float w = (k < 128) ? upd_w2[k * 128 + n] : out_w[(k - 128) * 128 + n];
        whu2out[idx] = __float2half(w);
        return;
    }
    if (b < 768) {
        int idx = (b - 576) * 256 + threadIdx.x;
        int k = idx / 384, n = idx % 384;
        whqkv[(size_t)n * 128 + k] = __float2half(in_w[idx]);
        return;
    }
    if (b < 896) {
        int idx = (b - 768) * 256 + threadIdx.x;
        int k = idx / 256, n = idx % 256;
        whf1[(size_t)n * 128 + k] = __float2half(ffn_w1[idx]);
        return;
    }
    if (b < 1024) {
        int idx = (b - 896) * 256 + threadIdx.x;
        int k = idx / 128, n = idx % 128;
        whf2[(size_t)n * 256 + k] = __float2half(ffn_w2[idx]);
        return;
    }
    {
        int idx = (b - 1024) * 256 + threadIdx.x;
        int n = idx >> 5, k = idx & 31;
        whw1c[idx] = __float2half(msg_w1[(256 + k) * 256 + n]);
    }
}

// ---------------------------------------------------------------------------
// HMMA GEMM body with epilogue functor.
// ---------------------------------------------------------------------------
template<bool GELU, class Epi>
__device__ __forceinline__ void hgemm_body(
    const float* __restrict__ A1, int K1,
    const float* __restrict__ A2, int K2,
    const __half* __restrict__ Bh,
    const float* __restrict__ bias,
    const float* __restrict__ bias2,
    const float* __restrict__ rowscale,
    int m0, int n0, __half* Ah, __half* Bs, Epi epi)
{
    const int K = K1 + K2;
    const int T = K >> 5;
    const int t = threadIdx.x;

    const int arow = t >> 1, aseg = (t & 1) * 16;
    const int brow = t >> 1, bseg = (t & 1) * 16;

    float4 raf[4];
    uint4 rbu0, rbu1;
    auto ldg_tile = [&](int kb) {
        #pragma unroll
        for (int i = 0; i < 4; i++) {
            int gk = kb + aseg + i * 4;
            const float* src = (gk < K1)
                ? (A1 + (size_t)(m0 + arow) * K1 + gk)
                : (A2 + (size_t)(m0 + arow) * K2 + (gk - K1));
            raf[i] = *(const float4*)src;
        }
        const __half* bsrc = Bh + (size_t)(n0 + brow) * K + kb + bseg;
        rbu0 = *(const uint4*)bsrc;
        rbu1 = *(const uint4*)(bsrc + 8);
    };
    auto sts_tile = [&](int buf) {
        __half2* ad = (__half2*)&Ah[buf * 128 * 40 + arow * 40 + aseg];
        #pragma unroll
        for (int i = 0; i < 4; i++) {
            ad[i * 2]     = __floats2half2_rn(raf[i].x, raf[i].y);
            ad[i * 2 + 1] = __floats2half2_rn(raf[i].z, raf[i].w);
        }
        __half* bd = &Bs[buf * 128 * 40 + brow * 40 + bseg];
        *(uint4*)bd       = rbu0;
        *(uint4*)(bd + 8) = rbu1;
    };

    const int wid = t >> 5, lane = t & 31;
    const int wm = wid & 3;
    const int wn = wid >> 2;
    const int lq = lane >> 2;
    const int lr = lane & 3;

    float d[2][8][4];
    #pragma unroll
    for (int mt = 0; mt < 2; mt++)
        #pragma unroll
        for (int nt = 0; nt < 8; nt++)
            #pragma unroll
            for (int c = 0; c < 4; c++) d[mt][nt][c] = 0.0f;

    ldg_tile(0); sts_tile(0);
    for (int kt = 0; kt < T; kt++) {
        __syncthreads();
        if (kt + 1 < T) ldg_tile((kt + 1) * 32);
        const __half* ap = Ah + (kt & 1) * 128 * 40;
        const __half* bp = Bs + (kt & 1) * 128 * 40;

        uint32_t afr[2][2][4];
        #pragma unroll
        for (int mt = 0; mt < 2; mt++) {
            int r = wm * 32 + mt * 16 + lq;
            #pragma unroll
            for (int ks = 0; ks < 2; ks++) {
                int k = ks * 16 + lr * 2;
                afr[mt][ks][0] = *(const uint32_t*)&ap[r * 40 + k];
                afr[mt][ks][1] = *(const uint32_t*)&ap[(r + 8) * 40 + k];
                afr[mt][ks][2] = *(const uint32_t*)&ap[r * 40 + k + 8];
                afr[mt][ks][3] = *(const uint32_t*)&ap[(r + 8) * 40 + k + 8];
            }
        }
        #pragma unroll
        for (int nt = 0; nt < 8; nt++) {
            int n = wn * 64 + nt * 8 + lq;
            uint32_t b00 = *(const uint32_t*)&bp[n * 40 + lr * 2];
            uint32_t b10 = *(const uint32_t*)&bp[n * 40 + lr * 2 + 8];
            uint32_t b01 = *(const uint32_t*)&bp[n * 40 + 16 + lr * 2];
            uint32_t b11 = *(const uint32_t*)&bp[n * 40 + 16 + lr * 2 + 8];
            #pragma unroll
            for (int mt = 0; mt < 2; mt++) {
                mma16816(d[mt][nt], afr[mt][0], b00, b10);
                mma16816(d[mt][nt], afr[mt][1], b01, b11);
            }
        }
        if (kt + 1 < T) sts_tile((kt + 1) & 1);
    }

    #pragma unroll
    for (int mt = 0; mt < 2; mt++) {
        int row = m0 + wm * 32 + mt * 16 + lq;
        float rs0 = rowscale ? rowscale[row]     : 0.0f;
        float rs8 = rowscale ? rowscale[row + 8] : 0.0f;
        #pragma unroll
        for (int nt = 0; nt < 8; nt++) {
            int col = n0 + wn * 64 + nt * 8 + lr * 2;
            float b0v = bias ? bias[col]     : 0.0f;
            float b1v = bias ? bias[col + 1] : 0.0f;
            float c0  = bias2 ? bias2[col]     : 0.0f;
            float c1  = bias2 ? bias2[col + 1] : 0.0f;
            float v0 = d[mt][nt][0] + b0v + rs0 * c0;
            float v1 = d[mt][nt][1] + b1v + rs0 * c1;
            float v2 = d[mt][nt][2] + b0v + rs8 * c0;
            float v3 = d[mt][nt][3] + b1v + rs8 * c1;
            if (GELU) {
                v0 = gelu_f(v0); v1 = gelu_f(v1);
                v2 = gelu_f(v2); v3 = gelu_f(v3);
            }
            epi(row, col, v0, v1, v2, v3);
        }
    }
}

// fp32-out wrapper (upd1)
template<bool GELU>
__global__ __launch_bounds__(256) void hgemm_kernel(
    const float* __restrict__ A1, int K1,
    const float* __restrict__ A2, int K2,
    const __half* __restrict__ Bh,
    const float* __restrict__ bias,
    const float* __restrict__ bias2,
    const float* __restrict__ rowscale,
    float* __restrict__ C, int NN)
{
    __shared__ __align__(16) __half Ah[2 * 128 * 40];
    __shared__ __align__(16) __half Bs[2 * 128 * 40];
    hgemm_body<GELU>(A1, K1, A2, K2, Bh, bias, bias2, rowscale,
        blockIdx.x * 128, blockIdx.y * 128, Ah, Bs,
        [&](int row, int col, float v0, float v1, float v2, float v3) {
            *(float2*)(C + (size_t)row       * NN + col) = make_float2(v0, v1);
            *(float2*)(C + (size_t)(row + 8) * NN + col) = make_float2(v2, v3);
        });
}

// P3: pdps(512)+qkv(384) GEMMs (896 blocks) | scan_fix (64 blocks)
__global__ __launch_bounds__(256) void prep3_kernel(
    const float* __restrict__ xn, const __half* __restrict__ whpdps,
    __half* __restrict__ pdps,
    const float* __restrict__ x, const __half* __restrict__ whqkv,
    const float* __restrict__ in_b, __half* __restrict__ qkvh,
    int* __restrict__ offs, int* __restrict__ cursor,
    const int* __restrict__ bsum)
{
    int b = blockIdx.x;
    if (b >= 896) {
        int i = (b - 896) * 256 + threadIdx.x;
        int b8 = i >> 11;
        int add = 0;
        #pragma unroll
        for (int k = 0; k < 8; k++) if (k < b8) add += bsum[k];
        int v = offs[i] + add;
        offs[i] = v;
        cursor[i] = v;
        if (i == 0) offs[NV] = EV;
        return;
    }
    __shared__ __align__(16) __half Ah[2 * 128 * 40];
    __shared__ __align__(16) __half Bs[2 * 128 * 40];
    int bx = b & 127, by = b >> 7;
    if (by < 4) {
        __half* C = pdps;
        hgemm_body<false>(xn, 128, nullptr, 0, whpdps, nullptr, nullptr,
            nullptr, bx * 128, by * 128, Ah, Bs,
            [&](int row, int col, float v0, float v1, float v2, float v3) {
                *(__half2*)(C + (size_t)row       * 512 + col) = __floats2half2_rn(v0, v1);
                *(__half2*)(C + (size_t)(row + 8) * 512 + col) = __floats2half2_rn(v2, v3);
            });
    } else {
        __half* C = qkvh;
        hgemm_body<false>(x, 128, nullptr, 0, whqkv, in_b, nullptr,
            nullptr, bx * 128, (by - 4) * 128, Ah, Bs,
            [&](int row, int col, float v0, float v1, float v2, float v3) {
                *(__half2*)(C + (size_t)row       * 384 + col) = __floats2half2_rn(v0, v1);
                *(__half2*)(C + (size_t)(row + 8) * 384 + col) = __floats2half2_rn(v2, v3);
            });
    }
}

// P4: scatter, 2 edges/thread (MLP=2 on the L2-atomic chain)
__global__ __launch_bounds__(256) void scatter_kernel(
    const int* __restrict__ dstp, const int* __restrict__ srcp,
    int* __restrict__ cursor, int* __restrict__ eperm,
    int* __restrict__ ssrc, int* __restrict__ sdst)
{
    int e0 = blockIdx.x * 512 + threadIdx.x;
    int e1 = e0 + 256;
    int d0 = dstp[e0], d1 = dstp[e1];
    int s0 = srcp[e0], s1 = srcp[e1];
    int p0 = atomicAdd(&cursor[d0], 1);
    int p1 = atomicAdd(&cursor[d1], 1);
    eperm[p0] = e0; ssrc[p0] = s0; sdst[p0] = d0;
    eperm[p1] = e1; ssrc[p1] = s1; sdst[p1] = d1;
}

// Fused: h1 = LN( x + [t1|obuf]@[U2;Wout] + (b2+bout) ) with n1 params.
__global__ __launch_bounds__(256) void upd2_out_ln_kernel(
    const float* __restrict__ t1, const float* __restrict__ obuf,
    const __half* __restrict__ whu2out, const float* __restrict__ bcat,
    const float* __restrict__ x,
    const float* __restrict__ n1_g, const float* __restrict__ n1_b,
    float* __restrict__ h1)
{
    __shared__ __align__(16) __half Ah[2 * 128 * 40];
    __shared__ __align__(16) __half Bs[2 * 128 * 40];
    extern __shared__ float Gs[];          // [128][132]
    const int m0 = blockIdx.x * 128;

    hgemm_body<false>(t1, 128, obuf, 128, whu2out, bcat, nullptr, nullptr,
        m0, 0, Ah, Bs,
        [&](int row, int col, float v0, float v1, float v2, float v3) {
            int rl = row - m0;
            float2 x0 = *(const float2*)(x + (size_t)row       * 128 + col);
            float2 x8 = *(const float2*)(x + (size_t)(row + 8) * 128 + col);
            Gs[rl * 132 + col]           = v0 + x0.x;
            Gs[rl * 132 + col + 1]       = v1 + x0.y;
            Gs[(rl + 8) * 132 + col]     = v2 + x8.x;
            Gs[(rl + 8) * 132 + col + 1] = v3 + x8.y;
        });
    __syncthreads();

    const int t = threadIdx.x, w = t >> 5, lane = t & 31;
    float4 gg = *(const float4*)(n1_g + lane * 4);
    float4 bb = *(const float4*)(n1_b + lane * 4);
    #pragma unroll 4
    for (int i = 0; i < 16; i++) {
        int r = w * 16 + i;
        float4 v = *(const float4*)&Gs[r * 132 + lane * 4];
        float s  = v.x + v.y + v.z + v.w;
        float ss = v.x*v.x + v.y*v.y + v.z*v.z + v.w*v.w;
        #pragma unroll
        for (int o = 16; o > 0; o >>= 1) {
            s  += __shfl_xor_sync(0xffffffffu, s,  o);
            ss += __shfl_xor_sync(0xffffffffu, ss, o);
        }
        float mean = s * (1.0f / 128.0f);
        float var  = ss * (1.0f / 128.0f) - mean * mean;
        float rstd = rsqrtf(var + 1e-5f);
        float4 o4;
        o4.x = (v.x - mean) * rstd * gg.x + bb.x;
        o4.y = (v.y - mean) * rstd * gg.y + bb.y;
        o4.z = (v.z - mean) * rstd * gg.z + bb.z;
        o4.w = (v.w - mean) * rstd * gg.w + bb.w;
        *(float4*)(h1 + (size_t)(m0 + r) * 128 + lane * 4) = o4;
    }
}

// ---------------------------------------------------------------------------
// Fused FFN: out = LN( h1 + ffn2(gelu(ffn1(h1))) )  — one block per 128 rows.
// Phase 1: two hgemm passes -> fp16 smem tile F[128][264].
// Phase 2: GEMM2 (K=256) with A straight from F, B double-buffered.
// Phase 3: residual + LN from Gs.
// extern smem: F (67584 B) + Gs (67584 B) = 135168 B; static Ah/Bs 40960 B.
// ---------------------------------------------------------------------------
__global__ __launch_bounds__(256) void ffn_fused_kernel(
    const float* __restrict__ h1,
    const __half* __restrict__ whf1, const float* __restrict__ ffn_b1,
    const __half* __restrict__ whf2, const float* __restrict__ ffn_b2,
    const float* __restrict__ n2_g, const float* __restrict__ n2_b,
    float* __restrict__ out)
{
    __shared__ __align__(16) __half Ah[2 * 128 * 40];
    __shared__ __align__(16) __half Bs[2 * 128 * 40];
    extern __shared__ __align__(16) char smraw[];
    __half* F  = (__half*)smraw;               // [128][264]
    float*  Gs = (float*)(F + 128 * 264);      // [128][132]
    const int m0 = blockIdx.x * 128;
    const int t  = threadIdx.x;

    // Phase 1: F = fp16( gelu(h1 @ whf1 + b1) ), two 128-col passes
    #pragma unroll 1
    for (int pass = 0; pass < 2; pass++) {
        hgemm_body<true>(h1, 128, nullptr, 0, whf1, ffn_b1, nullptr, nullptr,
            m0, pass * 128, Ah, Bs,
            [&](int row, int col, float v0, float v1, float v2, float v3) {
                int rl = row - m0;
                *(__half2*)&F[rl * 264 + col]       = __floats2half2_rn(v0, v1);
                *(__half2*)&F[(rl + 8) * 264 + col] = __floats2half2_rn(v2, v3);
            });
        __syncthreads();
    }

    // Phase 2: d = F @ whf2^T  (K=256, N=128); A fragments direct from F.
    const int wid = t >> 5, lane = t & 31;
    const int wm = wid & 3;
    const int wn = wid >> 2;
    const int lq = lane >> 2;
    const int lr = lane & 3;

    float d[2][8][4];
    #pragma unroll
    for (int mt = 0; mt < 2; mt++)
        #pragma unroll
        for (int nt = 0; nt < 8; nt++)
            #pragma unroll
            for (int c = 0; c < 4; c++) d[mt][nt][c] = 0.0f;

    const int brow = t >> 1, bseg = (t & 1) * 16;
    uint4 rbu0, rbu1;
    auto ldgB = [&](int kb) {
        const __half* bsrc = whf2 + (size_t)brow * 256 + kb + bseg;
        rbu0 = *(const uint4*)bsrc;
        rbu1 = *(const uint4*)(bsrc + 8);
    };
    auto stsB = [&](int buf) {
        __half* bd = &Bs[buf * 128 * 40 + brow * 40 + bseg];
        *(uint4*)bd       = rbu0;
        *(uint4*)(bd + 8) = rbu1;
    };

    ldgB(0); stsB(0);
    for (int kt = 0; kt < 8; kt++) {
        __syncthreads();
        if (kt + 1 < 8) ldgB((kt + 1) * 32);
        const __half* bp = Bs + (kt & 1) * 128 * 40;

        uint32_t afr[2][2][4];
        #pragma unroll
        for (int mt = 0; mt < 2; mt++) {
            int r = wm * 32 + mt * 16 + lq;
            #pragma unroll
            for (int ks = 0; ks < 2; ks++) {
                int k = kt * 32 + ks * 16 + lr * 2;
                afr[mt][ks][0] = *(const uint32_t*)&F[r * 264 + k];
                afr[mt][ks][1] = *(const uint32_t*)&F[(r + 8) * 264 + k];
                afr[mt][ks][2] = *(const uint32_t*)&F[r * 264 + k + 8];
                afr[mt][ks][3] = *(const uint32_t*)&F[(r + 8) * 264 + k + 8];
            }
        }
        #pragma unroll
        for (int nt = 0; nt < 8; nt++) {
            int n = wn * 64 + nt * 8 + lq;
            uint32_t b00 = *(const uint32_t*)&bp[n * 40 + lr * 2];
            uint32_t b10 = *(const uint32_t*)&bp[n * 40 + lr * 2 + 8];
            uint32_t b01 = *(const uint32_t*)&bp[n * 40 + 16 + lr * 2];
            uint32_t b11 = *(const uint32_t*)&bp[n * 40 + 16 + lr * 2 + 8];
            #pragma unroll
            for (int mt = 0; mt < 2; mt++) {
                mma16816(d[mt][nt], afr[mt][0], b00, b10);
                mma16816(d[mt][nt], afr[mt][1], b01, b11);
            }
        }
        if (kt + 1 < 8) stsB((kt + 1) & 1);
    }

    // epilogue: + bias + h1 residual -> Gs
    #pragma unroll
    for (int mt = 0; mt < 2; mt++) {
        int row = m0 + wm * 32 + mt * 16 + lq;
        int rl  = row - m0;
        #pragma unroll
        for (int nt = 0; nt < 8; nt++) {
            int col = wn * 64 + nt * 8 + lr * 2;
            float b0v = ffn_b2[col], b1v = ffn_b2[col + 1];
            float2 h0 = *(const float2*)(h1 + (size_t)row       * 128 + col);
            float2 h8 = *(const float2*)(h1 + (size_t)(row + 8) * 128 + col);
            Gs[rl * 132 + col]           = d[mt][nt][0] + b0v + h0.x;
            Gs[rl * 132 + col + 1]       = d[mt][nt][1] + b1v + h0.y;
            Gs[(rl + 8) * 132 + col]     = d[mt][nt][2] + b0v + h8.x;
            Gs[(rl + 8) * 132 + col + 1] = d[mt][nt][3] + b1v + h8.y;
        }
    }
    __syncthreads();

    // Phase 3: LN
    const int w = t >> 5;
    float4 gg = *(const float4*)(n2_g + lane * 4);
    float4 bb = *(const float4*)(n2_b + lane * 4);
    #pragma unroll 4
    for (int i = 0; i < 16; i++) {
        int r = w * 16 + i;
        float4 v = *(const float4*)&Gs[r * 132 + lane * 4];
        float s  = v.x + v.y + v.z + v.w;
        float ss = v.x*v.x + v.y*v.y + v.z*v.z + v.w*v.w;
        #pragma unroll
        for (int o = 16; o > 0; o >>= 1) {
            s  += __shfl_xor_sync(0xffffffffu, s,  o);
            ss += __shfl_xor_sync(0xffffffffu, ss, o);
        }
        float mean = s * (1.0f / 128.0f);
        float var  = ss * (1.0f / 128.0f) - mean * mean;
        float rstd = rsqrtf(var + 1e-5f);
        float4 o4;
        o4.x = (v.x - mean) * rstd * gg.x + bb.x;
        o4.y = (v.y - mean) * rstd * gg.y + bb.y;
        o4.z = (v.z - mean) * rstd * gg.z + bb.z;
        o4.w = (v.w - mean) * rstd * gg.w + bb.w;
        *(float4*)(out + (size_t)(m0 + r) * 128 + lane * 4) = o4;
    }
}

// ---------------------------------------------------------------------------
// Edge body: MLP + gelu + in-block segmented reduce. 256 threads.
// ---------------------------------------------------------------------------
__device__ __forceinline__ void edge_body(
    char* smraw, int eb,
    const float* __restrict__ ea, const int* __restrict__ eperm,
    const __half* __restrict__ whw1c, const float* __restrict__ b1,
    const __half* __restrict__ pdps,
    const int* __restrict__ sdst, const int* __restrict__ ssrc,
    float* __restrict__ aggrH)
{
    __half* Ws  = (__half*)smraw;                  // [256][36]
    __half* As  = Ws + 256 * 36;                   // [64][36]
    __half* Gsm = As + 64 * 36;                    // [64][264]
    float*  b1s = (float*)(Gsm + 64 * 264);        // [256]
    int*    ds  = (int*)(b1s + 256);               // [64]
    const int t  = threadIdx.x;
    const int e0 = eb * 64;

    {
        b1s[t] = b1[t];
        const uint4* wsrc = (const uint4*)whw1c;
        #pragma unroll
        for (int i = 0; i < 4; i++) {
            int u = t * 4 + i;
            int row = u >> 2, seg = (u & 3) * 8;
            uint4 v = wsrc[u];
            uint2* dst = (uint2*)&Ws[row * 36 + seg];
            dst[0] = make_uint2(v.x, v.y);
            dst[1] = make_uint2(v.z, v.w);
        }
    }
    {
        int el = t >> 2, part = t & 3;
        int e = eperm[e0 + el];
        const float4* src = (const float4*)(ea + (size_t)e * 32 + part * 8);
        float4 v0 = src[0], v1 = src[1];
        __half2* dst = (__half2*)(As + el * 36 + part * 8);
        dst[0] = __floats2half2_rn(v0.x, v0.y);
        dst[1] = __floats2half2_rn(v0.z, v0.w);
        dst[2] = __floats2half2_rn(v1.x, v1.y);
        dst[3] = __floats2half2_rn(v1.z, v1.w);
    }
    if (t < 64) ds[t] = sdst[e0 + t];
    __syncthreads();

    const int wid = t >> 5, lane = t & 31;
    const int wm = wid >> 2;
    const int wn = wid & 3;
    const int lq = lane >> 2;
    const int lr = lane & 3;

    float d[2][8][4];
    #pragma unroll
    for (int mt = 0; mt < 2; mt++)
        #pragma unroll
        for (int nt = 0; nt < 8; nt++)
            #pragma unroll
            for (int c = 0; c < 4; c++) d[mt][nt][c] = 0.0f;

    uint32_t afr[2][2][4];
    #pragma unroll
    for (int mt = 0; mt < 2; mt++) {
        int r = wm * 32 + mt * 16 + lq;
        #pragma unroll
        for (int ks = 0; ks < 2; ks++) {
            int k = ks * 16 + lr * 2;
            afr[mt][ks][0] = *(const uint32_t*)&As[r * 36 + k];
            afr[mt][ks][1] = *(const uint32_t*)&As[(r + 8) * 36 + k];
            afr[mt][ks][2] = *(const uint32_t*)&As[r * 36 + k + 8];
            afr[mt][ks][3] = *(const uint32_t*)&As[(r + 8) * 36 + k + 8];
        }
    }

    #pragma unroll
    for (int nt = 0; nt < 8; nt++) {
        int n = wn * 64 + nt * 8 + lq;
        uint32_t b0k0 = *(const uint32_t*)&Ws[n * 36 + lr * 2];
        uint32_t b1k0 = *(const uint32_t*)&Ws[n * 36 + lr * 2 + 8];
        uint32_t b0k1 = *(const uint32_t*)&Ws[n * 36 + 16 + lr * 2];
        uint32_t b1k1 = *(const uint32_t*)&Ws[n * 36 + 16 + lr * 2 + 8];
        #pragma unroll
        for (int mt = 0; mt < 2; mt++) {
            mma16816(d[mt][nt], afr[mt][0], b0k0, b1k0);
            mma16816(d[mt][nt], afr[mt][1], b0k1, b1k1);
        }
    }

    #pragma unroll
    for (int mt = 0; mt < 2; mt++) {
        int l0 = wm * 32 + mt * 16 + lq;
        int l8 = l0 + 8;
        int j0 = e0 + l0, j8 = e0 + l8;
        const __half* pd0 = pdps + (size_t)sdst[j0] * 512;
        const __half* ps0 = pdps + (size_t)ssrc[j0] * 512 + 256;
        const __half* pd8 = pdps + (size_t)sdst[j8] * 512;
        const __half* ps8 = pdps + (size_t)ssrc[j8] * 512 + 256;
        #pragma unroll
        for (int nt = 0; nt < 8; nt++) {
            int col = wn * 64 + nt * 8 + lr * 2;
            float2 a0 = __half22float2(*(const __half2*)(pd0 + col));
            float2 s0 = __half22float2(*(const __half2*)(ps0 + col));
            float2 a8 = __half22float2(*(const __half2*)(pd8 + col));
            float2 s8 = __half22float2(*(const __half2*)(ps8 + col));
            float bx = b1s[col], by = b1s[col + 1];
            float v0 = gelu_f(d[mt][nt][0] + bx + a0.x + s0.x);
            float v1 = gelu_f(d[mt][nt][1] + by + a0.y + s0.y);
            float v2 = gelu_f(d[mt][nt][2] + bx + a8.x + s8.x);
            float v3 = gelu_f(d[mt][nt][3] + by + a8.y + s8.y);
            *(__half2*)(Gsm + l0 * 264 + col) = __floats2half2_rn(v0, v1);
            *(__half2*)(Gsm + l8 * 264 + col) = __floats2half2_rn(v2, v3);
        }
    }
    __syncthreads();

    {
        int c = t;
        float acc = 0.0f;
        int prev = ds[0];
        #pragma unroll 8
        for (int r = 0; r < 64; r++) {
            int nd = ds[r];
            if (nd != prev) {
                atomicAdd(&aggrH[(size_t)prev * 256 + c], acc);
                acc = 0.0f;
                prev = nd;
            }
            acc += __half2float(Gsm[r * 264 + c]);
        }
        atomicAdd(&aggrH[(size_t)prev * 256 + c], acc);
    }
}

// ---------------------------------------------------------------------------
// Attention body (256-thread loads; warps 0-3 compute). Ks/Qs stride 36.
// ---------------------------------------------------------------------------
#define VTS 514
__device__ __forceinline__ void attn_body(
    char* smraw, int ab,
    const __half* __restrict__ qkv, float* __restrict__ o)
{
    __half* Ks = (__half*)smraw;            // [512][36]
    __half* Vt = Ks + 512 * 36;             // [32][VTS]
    __half* Qs = Vt + 32 * VTS;             // [64][36]
    const int t  = threadIdx.x;
    const int g  = ab >> 5;
    const int h  = (ab >> 3) & 3;
    const int qb = ab & 7;
    const size_t gb = (size_t)g * 512;
    const float scale = 0.17677669529663687f;

    #pragma unroll
    for (int i = 0; i < 16; i++) {
        int task = t + i * 256;
        int row = task >> 3, seg = task & 7;
        uint2 v = *(const uint2*)(qkv + (gb + row) * 384 + 128 + h * 32 + seg * 4);
        *(uint2*)&Ks[row * 36 + seg * 4] = v;
    }
    #pragma unroll
    for (int i = 0; i < 16; i++) {
        int task = t + i * 256;
        int row = task >> 3, seg = task & 7;
        const __half* src = qkv + (gb + row) * 384 + 256 + h * 32 + seg * 4;
        int d0 = seg * 4;
        Vt[(d0 + 0) * VTS + row] = src[0];
        Vt[(d0 + 1) * VTS + row] = src[1];
        Vt[(d0 + 2) * VTS + row] = src[2];
        Vt[(d0 + 3) * VTS + row] = src[3];
    }
    #pragma unroll
    for (int i = 0; i < 2; i++) {
        int task = t + i * 256;
        int row = task >> 3, seg = task & 7;
        const __half2* src = (const __half2*)(qkv + (gb + qb * 64 + row) * 384 + h * 32 + seg * 4);
        float2 v0 = __half22float2(src[0]);
        float2 v1 = __half22float2(src[1]);
        __half2* d = (__half2*)&Qs[row * 36 + seg * 4];
        d[0] = __floats2half2_rn(v0.x * scale, v0.y * scale);
        d[1] = __floats2half2_rn(v1.x * scale, v1.y * scale);
    }
    __syncthreads();

    if (t >= 128) return;

    const int wq = t >> 5, lane = t & 31;
    const int lq = lane >> 2, lr = lane & 3;

    uint32_t aq[2][4];
    #pragma unroll
    for (int ks = 0; ks < 2; ks++) {
        int base = (wq * 16 + lq) * 36 + ks * 16 + lr * 2;
        aq[ks][0] = *(const uint32_t*)&Qs[base];
        aq[ks][1] = *(const uint32_t*)&Qs[base + 8 * 36];
        aq[ks][2] = *(const uint32_t*)&Qs[base + 8];
        aq[ks][3] = *(const uint32_t*)&Qs[base + 8 * 36 + 8];
    }

    float m0 = -1e30f, m1 = -1e30f, l0 = 0.0f, l1 = 0.0f;
    float oA[4][4];
    #pragma unroll
    for (int n = 0; n < 4; n++)
        #pragma unroll
        for (int c = 0; c < 4; c++) oA[n][c] = 0.0f;

    for (int c = 0; c < 8; c++) {
        float s[8][4];
        #pragma unroll
        for (int nt = 0; nt < 8; nt++)
            #pragma unroll
            for (int q = 0; q < 4; q++) s[nt][q] = 0.0f;
        #pragma unroll
        for (int nt = 0; nt < 8; nt++) {
            int kb = (c * 64 + nt * 8 + lq) * 36 + lr * 2;
            mma16816(s[nt], aq[0], *(const uint32_t*)&Ks[kb],
                                    *(const uint32_t*)&Ks[kb + 8]);
            mma16816(s[nt], aq[1], *(const uint32_t*)&Ks[kb + 16],
                                    *(const uint32_t*)&Ks[kb + 24]);
        }
        float mc0 = -1e30f, mc1 = -1e30f;
        #pragma unroll
        for (int nt = 0; nt < 8; nt++) {
            mc0 = fmaxf(mc0, fmaxf(s[nt][0], s[nt][1]));
            mc1 = fmaxf(mc1, fmaxf(s[nt][2], s[nt][3]));
        }
        mc0 = fmaxf(mc0, __shfl_xor_sync(0xffffffffu, mc0, 1));
        mc0 = fmaxf(mc0, __shfl_xor_sync(0xffffffffu, mc0, 2));
        mc1 = fmaxf(mc1, __shfl_xor_sync(0xffffffffu, mc1, 1));
        mc1 = fmaxf(mc1, __shfl_xor_sync(0xffffffffu, mc1, 2));
        float mn0 = fmaxf(m0, mc0), mn1 = fmaxf(m1, mc1);
        float cr0 = __expf(m0 - mn0), cr1 = __expf(m1 - mn1);
        m0 = mn0; m1 = mn1;
        float rs0 = 0.0f, rs1 = 0.0f;
        #pragma unroll
        for (int nt = 0; nt < 8; nt++) {
            s[nt][0] = __expf(s[nt][0] - m0); rs0 += s[nt][0];
            s[nt][1] = __expf(s[nt][1] - m0); rs0 += s[nt][1];
            s[nt][2] = __expf(s[nt][2] - m1); rs1 += s[nt][2];
            s[nt][3] = __expf(s[nt][3] - m1); rs1 += s[nt][3];
        }
        rs0 += __shfl_xor_sync(0xffffffffu, rs0, 1);
        rs0 += __shfl_xor_sync(0xffffffffu, rs0, 2);
        rs1 += __shfl_xor_sync(0xffffffffu, rs1, 1);
        rs1 += __shfl_xor_sync(0xffffffffu, rs1, 2);
        l0 = l0 * cr0 + rs0;
        l1 = l1 * cr1 + rs1;
        #pragma unroll
        for (int n = 0; n < 4; n++) {
            oA[n][0] *= cr0; oA[n][1] *= cr0;
            oA[n][2] *= cr1; oA[n][3] *= cr1;
        }
        #pragma unroll
        for (int kt = 0; kt < 4; kt++) {
            uint32_t a[4];
            a[0] = packh2(s[2 * kt][0],     s[2 * kt][1]);
            a[1] = packh2(s[2 * kt][2],     s[2 * kt][3]);
            a[2] = packh2(s[2 * kt + 1][0], s[2 * kt + 1][1]);
            a[3] = packh2(s[2 * kt + 1][2], s[2 * kt + 1][3]);
            #pragma unroll
            for (int nd = 0; nd < 4; nd++) {
                int vb = (nd * 8 + lq) * VTS + c * 64 + kt * 16 + lr * 2;
                mma16816(oA[nd], a, *(const uint32_t*)&Vt[vb],
                                     *(const uint32_t*)&Vt[vb + 8]);
            }
        }
    }

    float i0 = 1.0f / l0, i1 = 1.0f / l1;
    int row = qb * 64 + wq * 16 + lq;
    float* orow = o + (gb + row) * 128 + h * 32;
    #pragma unroll
    for (int nd = 0; nd < 4; nd++) {
        *(float2*)(orow + nd * 8 + lr * 2) =
            make_float2(oA[nd][0] * i0, oA[nd][1] * i0);
        *(float2*)(orow + 8 * 128 + nd * 8 + lr * 2) =
            make_float2(oA[nd][2] * i1, oA[nd][3] * i1);
    }
}

// P5: merged attention (blocks 0..1023) + edge (1024..5119)
__global__ __launch_bounds__(256) void edge_attn_kernel(
    const __half* __restrict__ qkvh, float* __restrict__ obuf,
    const float* __restrict__ ea, const int* __restrict__ eperm,
    const __half* __restrict__ whw1c, const float* __restrict__ b1,
    const __half* __restrict__ pdps,
    const int* __restrict__ sdst, const int* __restrict__ ssrc,
    float* __restrict__ aggrH)
{
    extern __shared__ __align__(16) char smraw[];
    int b = blockIdx.x;
    if (b < 1024)
        attn_body(smraw, b, qkvh, obuf);
    else
        edge_body(smraw, b - 1024, ea, eperm, whw1c, b1, pdps, sdst, ssrc, aggrH);
}

// ---------------------------------------------------------------------------
// Host launcher
// ---------------------------------------------------------------------------
extern "C" void kernel_launch(void* const* d_in, const int* in_sizes, int n_in,
                              void* d_out, int out_size)
{
    const float* x      = (const float*)d_in[0];
    const int*   eidx   = (const int*)  d_in[1];
    const float* ea     = (const float*)d_in[2];
    /* d_in[3] = batch (unused) */
    const float* gnn_g  = (const float*)d_in[4];
    const float* gnn_b  = (const float*)d_in[5];
    const float* msg_w1 = (const float*)d_in[6];
    const float* msg_b1 = (const float*)d_in[7];
    const float* msg_w2 = (const float*)d_in[8];
    const float* msg_b2 = (const float*)d_in[9];
    const float* upd_w1 = (const float*)d_in[10];
    const float* upd_b1 = (const float*)d_in[11];
    const float* upd_w2 = (const float*)d_in[12];
    const float* upd_b2 = (const float*)d_in[13];
    const float* in_w   = (const float*)d_in[14];
    const float* in_b   = (const float*)d_in[15];
    const float* out_w  = (const float*)d_in[16];
    const float* out_b  = (const float*)d_in[17];
    const float* ffn_w1 = (const float*)d_in[18];
    const float* ffn_b1 = (const float*)d_in[19];
    const float* ffn_w2 = (const float*)d_in[20];
    const float* ffn_b2 = (const float*)d_in[21];
    const float* n1_g   = (const float*)d_in[22];
    const float* n1_b   = (const float*)d_in[23];
    const float* n2_g   = (const float*)d_in[24];
    const float* n2_b   = (const float*)d_in[25];
    float* out = (float*)d_out;

    const int* srcp = eidx;
    const int* dstp = eidx + EV;

    float *xn, *aggrH, *t1, *obuf, *h1, *deg, *uwp, *b2u, *bcat;
    __half *pdps, *qkvh, *whpdps, *whuw, *whu2out, *whqkv, *whf1, *whf2, *whw1c;
    int *cnt, *offs, *cursor, *eperm, *ssrc, *sdst, *bsum;
    cudaGetSymbolAddress((void**)&xn,    g_xn);
    cudaGetSymbolAddress((void**)&pdps,  g_pdps);
    cudaGetSymbolAddress((void**)&aggrH, g_aggrH);
    cudaGetSymbolAddress((void**)&t1,    g_t1);
    cudaGetSymbolAddress((void**)&qkvh,  g_qkvh);
    cudaGetSymbolAddress((void**)&obuf,  g_obuf);
    cudaGetSymbolAddress((void**)&h1,    g_h1);
    cudaGetSymbolAddress((void**)&deg,   g_deg);
    cudaGetSymbolAddress((void**)&uwp,   g_uwp);
    cudaGetSymbolAddress((void**)&b2u,   g_b2u);
    cudaGetSymbolAddress((void**)&bcat,  g_bcat);
    cudaGetSymbolAddress((void**)&cnt,   g_cnt);
    cudaGetSymbolAddress((void**)&offs,  g_offs);
    cudaGetSymbolAddress((void**)&cursor,g_cursor);
    cudaGetSymbolAddress((void**)&eperm, g_eperm);
    cudaGetSymbolAddress((void**)&ssrc,  g_ssrc);
    cudaGetSymbolAddress((void**)&sdst,  g_sdst);
    cudaGetSymbolAddress((void**)&bsum,  g_bsum);
    cudaGetSymbolAddress((void**)&whpdps, g_wh_pdps);
    cudaGetSymbolAddress((void**)&whuw,   g_wh_uw);
    cudaGetSymbolAddress((void**)&whu2out,g_wh_u2out);
    cudaGetSymbolAddress((void**)&whqkv,  g_wh_qkv);
    cudaGetSymbolAddress((void**)&whf1,   g_wh_f1);
    cudaGetSymbolAddress((void**)&whf2,   g_wh_f2);
    cudaGetSymbolAddress((void**)&whw1c,  g_wh_w1c);

    cudaFuncSetAttribute(edge_attn_kernel,
                         cudaFuncAttributeMaxDynamicSharedMemorySize, 74368);
    cudaFuncSetAttribute(upd2_out_ln_kernel,
                         cudaFuncAttributeMaxDynamicSharedMemorySize, 67584);
    cudaFuncSetAttribute(ffn_fused_kernel,
                         cudaFuncAttributeMaxDynamicSharedMemorySize, 135168);

    // 0) cnt zero (must precede P1's hist)
    cudaMemsetAsync(cnt, 0, NV * sizeof(int), 0);

    // P1: prep-GEMM | aggrH zero | prep_bias | hist | LN(x)
    prep1_kernel<<<3589, 256>>>(
        msg_w2, upd_w1 + 128 * 128, uwp,
        msg_b2, upd_b2, out_b, b2u, bcat,
        dstp, cnt, x, gnn_g, gnn_b, xn, aggrH);

    // P2: convw (all fp16 tables) | scan_local
    prep2_kernel<<<1064, 256>>>(
        msg_w1, upd_w1, uwp, upd_w2, in_w, out_w, ffn_w1, ffn_w2,
        whpdps, whuw, whu2out, whqkv, whf1, whf2, whw1c,
        cnt, offs, deg, bsum);

    // P3: pdps+qkv GEMMs | scan_fix
    prep3_kernel<<<960, 256>>>(
        xn, whpdps, pdps, x, whqkv, in_b, qkvh, offs, cursor, bsum);

    // P4: scatter (2 edges/thread)
    scatter_kernel<<<EV / 512, 256>>>(dstp, srcp, cursor, eperm, ssrc, sdst);

    // P5: merged flash attention + edge MLP/reduce
    edge_attn_kernel<<<1024 + EV / 64, 256, 74368>>>(
        qkvh, obuf, ea, eperm, whw1c, msg_b1, pdps, sdst, ssrc, aggrH);

    // tail: upd1 -> upd2+out+LN -> fused FFN+LN
    hgemm_kernel<true><<<dim3(NV / 128, 1), 256>>>(
        xn, 128, aggrH, 256, whuw, upd_b1, b2u, deg, t1, 128);
    upd2_out_ln_kernel<<<NV / 128, 256, 67584>>>(
        t1, obuf, whu2out, bcat, x, n1_g, n1_b, h1);
    ffn_fused_kernel<<<NV / 128, 256, 135168>>>(
        h1, whf1, ffn_b1, whf2, ffn_b2, n2_g, n2_b, out);
}

// round 17
// speedup vs baseline: 1.1022x; 1.0063x over previous
#include <cuda_runtime.h>
#include <cuda_fp16.h>
#include <math.h>
#include <cstdint>

// ---------------------------------------------------------------------------
// Problem constants
// ---------------------------------------------------------------------------
#define NV   16384      // nodes
#define DV   128        // node dim
#define EDV  32         // edge feat dim
#define EV   262144     // edges
#define GV   32         // graphs
#define SV   512        // seq per graph
#define HV   4          // heads
#define HDV  32         // head dim

// ---------------------------------------------------------------------------
// Scratch buffers (device globals; no runtime allocation allowed)
// ---------------------------------------------------------------------------
__device__ float  g_xn   [NV * DV];
__device__ __half g_pdps [NV * 512];
__device__ float  g_aggrH[NV * 256];
__device__ float  g_t1   [NV * DV];
__device__ __half g_qkvh [NV * 3 * DV];
__device__ float  g_obuf [NV * DV];
__device__ float  g_h1   [NV * DV];
__device__ float  g_uwp  [256 * 128];   // msg_w2 @ U1b
__device__ float  g_b2u  [128];
__device__ float  g_bcat [128];
__device__ int    g_cnt   [NV];
__device__ int    g_cursor[NV];         // block-LOCAL exclusive offsets
__device__ int    g_eperm [EV];
__device__ int    g_ssrc  [EV];
__device__ int    g_sdst  [EV];
__device__ float  g_deg   [NV];
__device__ int    g_bsum  [8];

// fp16 transposed weight tables [N][K]
__device__ __half g_wh_pdps [512 * 128];
__device__ __half g_wh_uw   [128 * 384];
__device__ __half g_wh_u2out[128 * 256];
__device__ __half g_wh_qkv  [384 * 128];
__device__ __half g_wh_f1   [256 * 128];
__device__ __half g_wh_f2   [128 * 256];
__device__ __half g_wh_w1c  [256 * 32];

// ---------------------------------------------------------------------------
// helpers
// ---------------------------------------------------------------------------
typedef unsigned long long u64;

__device__ __forceinline__ u64 dup2(float x) {
    u64 r; asm("mov.b64 %0, {%1, %1};" : "=l"(r) : "f"(x)); return r;
}
__device__ __forceinline__ float2 unpack2(u64 v) {
    float2 r; asm("mov.b64 {%0, %1}, %2;" : "=f"(r.x), "=f"(r.y) : "l"(v)); return r;
}
__device__ __forceinline__ void fma2(u64& d, u64 a, u64 b) {
    asm("fma.rn.f32x2 %0, %1, %2, %0;" : "+l"(d) : "l"(a), "l"(b));
}

__device__ __forceinline__ float gelu_f(float v) {
    return 0.5f * v * (1.0f + erff(v * 0.70710678118654752f));
}

__device__ __forceinline__ void mma16816(
    float* d, const uint32_t* a, uint32_t b0, uint32_t b1)
{
    asm volatile(
        "mma.sync.aligned.m16n8k16.row.col.f32.f16.f16.f32 "
        "{%0,%1,%2,%3}, {%4,%5,%6,%7}, {%8,%9}, {%0,%1,%2,%3};"
        : "+f"(d[0]), "+f"(d[1]), "+f"(d[2]), "+f"(d[3])
        : "r"(a[0]), "r"(a[1]), "r"(a[2]), "r"(a[3]), "r"(b0), "r"(b1));
}

__device__ __forceinline__ uint32_t packh2(float a, float b) {
    __half2 h = __floats2half2_rn(a, b);
    return *(uint32_t*)&h;
}

// ---------------------------------------------------------------------------
// LN body: one block = 8 rows (8 warps), 256 threads.
// ---------------------------------------------------------------------------
__device__ __forceinline__ void ln_body(
    int blk, const float* __restrict__ a, const float* __restrict__ g,
    const float* __restrict__ be, float* __restrict__ out)
{
    int row  = blk * 8 + (threadIdx.x >> 5);
    int lane = threadIdx.x & 31;
    size_t off = (size_t)row * 128 + lane * 4;
    float4 v = *(const float4*)(a + off);
    float s  = v.x + v.y + v.z + v.w;
    float ss = v.x*v.x + v.y*v.y + v.z*v.z + v.w*v.w;
    #pragma unroll
    for (int o = 16; o > 0; o >>= 1) {
        s  += __shfl_xor_sync(0xffffffffu, s,  o);
        ss += __shfl_xor_sync(0xffffffffu, ss, o);
    }
    float mean = s * (1.0f / 128.0f);
    float var  = ss * (1.0f / 128.0f) - mean * mean;
    float rstd = rsqrtf(var + 1e-5f);
    float4 gg = *(const float4*)(g  + lane * 4);
    float4 bb = *(const float4*)(be + lane * 4);
    float4 o4;
    o4.x = (v.x - mean) * rstd * gg.x + bb.x;
    o4.y = (v.y - mean) * rstd * gg.y + bb.y;
    o4.z = (v.z - mean) * rstd * gg.z + bb.z;
    o4.w = (v.w - mean) * rstd * gg.w + bb.w;
    *(float4*)(out + off) = o4;
}

// ---------------------------------------------------------------------------
// Prep fp32 GEMM body: uwp[256,128] = msg_w2[256,128] @ U1b[128,128].
// ---------------------------------------------------------------------------
__device__ void gemm_prep_body(
    int blk, const float* __restrict__ A1, const float* __restrict__ B,
    float* __restrict__ C)
{
    const int K1 = 128, NN = 128, T = 8;
    __shared__ float As[2][16 * 128];
    __shared__ float Bs[2][16 * 64];
    const int t  = threadIdx.x;
    const int m0 = (blk & 1) * 128;
    const int n0 = (blk >> 1) * 64;
    const int mg = t >> 4;
    const int ng = t & 15;
    const int k4own = (t & 3) * 4;
    int rowA[2];
    #pragma unroll
    for (int i = 0; i < 2; i++) rowA[i] = m0 + ((t + i * 256) >> 2);

    float4 ra[2], rb;
    auto ldg_tile = [&](int kt) {
        int kb = kt * 16;
        #pragma unroll
        for (int i = 0; i < 2; i++)
            ra[i] = *(const float4*)(A1 + (size_t)rowA[i] * K1 + kb + k4own);
        int r = t >> 4, c4 = t & 15;
        rb = *(const float4*)(B + (size_t)(kb + r) * NN + n0 + c4 * 4);
    };
    auto sts_tile = [&](int buf) {
        #pragma unroll
        for (int i = 0; i < 2; i++) {
            int cc = t + i * 256;
            int m = cc >> 2, k4 = cc & 3;
            As[buf][(k4 * 4 + 0) * 128 + m] = ra[i].x;
            As[buf][(k4 * 4 + 1) * 128 + m] = ra[i].y;
            As[buf][(k4 * 4 + 2) * 128 + m] = ra[i].z;
            As[buf][(k4 * 4 + 3) * 128 + m] = ra[i].w;
        }
        int r = t >> 4, c4 = t & 15;
        *(float4*)&Bs[buf][r * 64 + c4 * 4] = rb;
    };

    u64 acc[4][4];
    #pragma unroll
    for (int i = 0; i < 4; i++)
        #pragma unroll
        for (int j = 0; j < 4; j++) acc[i][j] = 0ull;

    ldg_tile(0); sts_tile(0);
    for (int kt = 0; kt < T; kt++) {
        __syncthreads();
        if (kt + 1 < T) ldg_tile(kt + 1);
        const float* ap = As[kt & 1];
        const float* bp = Bs[kt & 1];
        #pragma unroll
        for (int k = 0; k < 16; k++) {
            ulonglong2 a01 = *(const ulonglong2*)(ap + k * 128 + mg * 8);
            ulonglong2 a23 = *(const ulonglong2*)(ap + k * 128 + mg * 8 + 4);
            float4 b = *(const float4*)(bp + k * 64 + ng * 4);
            u64 am[4] = {a01.x, a01.y, a23.x, a23.y};
            u64 bd[4] = {dup2(b.x), dup2(b.y), dup2(b.z), dup2(b.w)};
            #pragma unroll
            for (int i = 0; i < 4; i++)
                #pragma unroll
                for (int j = 0; j < 4; j++)
                    fma2(acc[i][j], am[i], bd[j]);
        }
        if (kt + 1 < T) sts_tile((kt + 1) & 1);
    }

    #pragma unroll
    for (int i = 0; i < 4; i++) {
        int r0 = m0 + mg * 8 + 2 * i;
        float2 v0 = unpack2(acc[i][0]);
        float2 v1 = unpack2(acc[i][1]);
        float2 v2 = unpack2(acc[i][2]);
        float2 v3 = unpack2(acc[i][3]);
        *(float4*)(C + (size_t)r0       * NN + n0 + ng * 4) = make_float4(v0.x, v1.x, v2.x, v3.x);
        *(float4*)(C + (size_t)(r0 + 1) * NN + n0 + ng * 4) = make_float4(v0.y, v1.y, v2.y, v3.y);
    }
}

// ---------------------------------------------------------------------------
// P1: prep-GEMM(4) | aggrH zero(512) | prep_bias(1) | hist(1024) | LN(2048)
// ---------------------------------------------------------------------------
__global__ __launch_bounds__(256) void prep1_kernel(
    const float* __restrict__ msg_w2, const float* __restrict__ U1b,
    float* __restrict__ uwp,
    const float* __restrict__ msg_b2, const float* __restrict__ upd_b2,
    const float* __restrict__ out_b,
    float* __restrict__ b2u, float* __restrict__ bcat,
    const int* __restrict__ dstp, int* __restrict__ cnt,
    const float* __restrict__ x, const float* __restrict__ gnn_g,
    const float* __restrict__ gnn_b, float* __restrict__ xn,
    float* __restrict__ aggrH)
{
    int b = blockIdx.x;
    if (b < 4) { gemm_prep_body(b, msg_w2, U1b, uwp); return; }
    if (b < 516) {
        float4 z = make_float4(0.f, 0.f, 0.f, 0.f);
        float4* p = (float4*)(aggrH + (size_t)(b - 4) * 8192);
        #pragma unroll
        for (int i = 0; i < 8; i++) p[threadIdx.x + i * 256] = z;
        return;
    }
    if (b == 516) {
        int n = threadIdx.x;
        if (n < 128) {
            float s = 0.0f;
            for (int k = 0; k < 128; k++) s = fmaf(msg_b2[k], U1b[k * 128 + n], s);
            b2u[n]  = s;
            bcat[n] = upd_b2[n] + out_b[n];
        }
        return;
    }
    if (b < 1541) {
        int e = (b - 517) * 256 + threadIdx.x;
        atomicAdd(&cnt[dstp[e]], 1);
        return;
    }
    ln_body(b - 1541, x, gnn_g, gnn_b, xn);
}

// ---------------------------------------------------------------------------
// P2: convw(1056) | scan_local(8) = 1064 blocks.
// scan_local writes block-LOCAL exclusive offsets into cursor (+ deg, bsum).
// ---------------------------------------------------------------------------
__device__ __forceinline__ void scan_local_body(
    int blk, const int* __restrict__ cnt, int* __restrict__ cursor,
    float* __restrict__ degf, int* __restrict__ bsum)
{
    __shared__ int wsum[8];
    int t = threadIdx.x;
    int base = blk * 2048 + t * 8;
    int c[8]; int s = 0;
    #pragma unroll
    for (int i = 0; i < 8; i++) { c[i] = cnt[base + i]; s += c[i]; }
    int lane = t & 31, wid = t >> 5;
    int v = s;
    #pragma unroll
    for (int o = 1; o < 32; o <<= 1) {
        int u = __shfl_up_sync(0xffffffffu, v, o);
        if (lane >= o) v += u;
    }
    if (lane == 31) wsum[wid] = v;
    __syncthreads();
    if (t < 32) {
        int w = (lane < 8) ? wsum[lane] : 0;
        #pragma unroll
        for (int o = 1; o < 8; o <<= 1) {
            int u = __shfl_up_sync(0xffffffffu, w, o);
            if (lane >= o) w += u;
        }
        if (lane < 8) wsum[lane] = w;
    }
    __syncthreads();
    int ex = (wid ? wsum[wid - 1] : 0) + (v - s);
    #pragma unroll
    for (int i = 0; i < 8; i++) {
        cursor[base + i] = ex;
        degf[base + i] = (float)c[i];
        ex += c[i];
    }
    if (t == 255) bsum[blk] = wsum[7];
}

__global__ __launch_bounds__(256) void prep2_kernel(
    const float* __restrict__ msg_w1, const float* __restrict__ upd_w1,
    const float* __restrict__ uwp, const float* __restrict__ upd_w2,
    const float* __restrict__ in_w, const float* __restrict__ out_w,
    const float* __restrict__ ffn_w1, const float* __restrict__ ffn_w2,
    __half* __restrict__ whpdps, __half* __restrict__ whuw,
    __half* __restrict__ whu2out, __half* __restrict__ whqkv,
    __half* __restrict__ whf1, __half* __restrict__ whf2,
    __half* __restrict__ whw1c,
    const int* __restrict__ cnt, int* __restrict__ cursor,
    float* __restrict__ degf, int* __restrict__ bsum)
{
    int b = blockIdx.x;
    if (b >= 1056) { scan_local_body(b - 1056, cnt, cursor, degf, bsum); return; }
    if (b < 256) {
        int idx = b * 256 + threadIdx.x;
        int n = idx >> 7, k = idx & 127;
        float w = (n < 256) ? msg_w1[k * 256 + n]
                            : msg_w1[(128 + k) * 256 + (n - 256)];
        whpdps[idx] = __float2half(w);
        return;
    }
    if (b < 448) {
        int idx = (b - 256) * 256 + threadIdx.x;
        int k = idx / 128, n = idx % 128;
        float w = (k < 128) ? upd_w1[k * 128 + n] : uwp[(size_t)(k - 128) * 128 + n];
        whuw[(size_t)n * 384 + k] = __float2half(w);
        return;
    }
    if (b < 576) {
        int idx = (b - 448) * 256 + threadIdx.x;
        int n = idx >> 8, k = idx & 255;
        float w = (k < 128) ? upd_w2[k * 128 + n] : out_w[(k - 128) * 128 + n];
        whu2out[idx] = __float2half(w);
        return;
    }
    if (b < 768) {
        int idx = (b - 576) * 256 + threadIdx.x;
        int k = idx / 384, n = idx % 384;
        whqkv[(size_t)n * 128 + k] = __float2half(in_w[idx]);
        return;
    }
    if (b < 896) {
        int idx = (b - 768) * 256 + threadIdx.x;
        int k = idx / 256, n = idx % 256;
        whf1[(size_t)n * 128 + k] = __float2half(ffn_w1[idx]);
        return;
    }
    if (b < 1024) {
        int idx = (b - 896) * 256 + threadIdx.x;
        int k = idx / 128, n = idx % 128;
        whf2[(size_t)n * 256 + k] = __float2half(ffn_w2[idx]);
        return;
    }
    {
        int idx = (b - 1024) * 256 + threadIdx.x;
        int n = idx >> 5, k = idx & 31;
        whw1c[idx] = __float2half(msg_w1[(256 + k) * 256 + n]);
    }
}

// ---------------------------------------------------------------------------
// HMMA GEMM body with epilogue functor.
// ---------------------------------------------------------------------------
template<bool GELU, class Epi>
__device__ __forceinline__ void hgemm_body(
    const float* __restrict__ A1, int K1,
    const float* __restrict__ A2, int K2,
    const __half* __restrict__ Bh,
    const float* __restrict__ bias,
    const float* __restrict__ bias2,
    const float* __restrict__ rowscale,
    int m0, int n0, __half* Ah, __half* Bs, Epi epi)
{
    const int K = K1 + K2;
    const int T = K >> 5;
    const int t = threadIdx.x;

    const int arow = t >> 1, aseg = (t & 1) * 16;
    const int brow = t >> 1, bseg = (t & 1) * 16;

    float4 raf[4];
    uint4 rbu0, rbu1;
    auto ldg_tile = [&](int kb) {
        #pragma unroll
        for (int i = 0; i < 4; i++) {
            int gk = kb + aseg + i * 4;
            const float* src = (gk < K1)
                ? (A1 + (size_t)(m0 + arow) * K1 + gk)
                : (A2 + (size_t)(m0 + arow) * K2 + (gk - K1));
            raf[i] = *(const float4*)src;
        }
        const __half* bsrc = Bh + (size_t)(n0 + brow) * K + kb + bseg;
        rbu0 = *(const uint4*)bsrc;
        rbu1 = *(const uint4*)(bsrc + 8);
    };
    auto sts_tile = [&](int buf) {
        __half2* ad = (__half2*)&Ah[buf * 128 * 40 + arow * 40 + aseg];
        #pragma unroll
        for (int i = 0; i < 4; i++) {
            ad[i * 2]     = __floats2half2_rn(raf[i].x, raf[i].y);
            ad[i * 2 + 1] = __floats2half2_rn(raf[i].z, raf[i].w);
        }
        __half* bd = &Bs[buf * 128 * 40 + brow * 40 + bseg];
        *(uint4*)bd       = rbu0;
        *(uint4*)(bd + 8) = rbu1;
    };

    const int wid = t >> 5, lane = t & 31;
    const int wm = wid & 3;
    const int wn = wid >> 2;
    const int lq = lane >> 2;
    const int lr = lane & 3;

    float d[2][8][4];
    #pragma unroll
    for (int mt = 0; mt < 2; mt++)
        #pragma unroll
        for (int nt = 0; nt < 8; nt++)
            #pragma unroll
            for (int c = 0; c < 4; c++) d[mt][nt][c] = 0.0f;

    ldg_tile(0); sts_tile(0);
    for (int kt = 0; kt < T; kt++) {
        __syncthreads();
        if (kt + 1 < T) ldg_tile((kt + 1) * 32);
        const __half* ap = Ah + (kt & 1) * 128 * 40;
        const __half* bp = Bs + (kt & 1) * 128 * 40;

        uint32_t afr[2][2][4];
        #pragma unroll
        for (int mt = 0; mt < 2; mt++) {
            int r = wm * 32 + mt * 16 + lq;
            #pragma unroll
            for (int ks = 0; ks < 2; ks++) {
                int k = ks * 16 + lr * 2;
                afr[mt][ks][0] = *(const uint32_t*)&ap[r * 40 + k];
                afr[mt][ks][1] = *(const uint32_t*)&ap[(r + 8) * 40 + k];
                afr[mt][ks][2] = *(const uint32_t*)&ap[r * 40 + k + 8];
                afr[mt][ks][3] = *(const uint32_t*)&ap[(r + 8) * 40 + k + 8];
            }
        }
        #pragma unroll
        for (int nt = 0; nt < 8; nt++) {
            int n = wn * 64 + nt * 8 + lq;
            uint32_t b00 = *(const uint32_t*)&bp[n * 40 + lr * 2];
            uint32_t b10 = *(const uint32_t*)&bp[n * 40 + lr * 2 + 8];
            uint32_t b01 = *(const uint32_t*)&bp[n * 40 + 16 + lr * 2];
            uint32_t b11 = *(const uint32_t*)&bp[n * 40 + 16 + lr * 2 + 8];
            #pragma unroll
            for (int mt = 0; mt < 2; mt++) {
                mma16816(d[mt][nt], afr[mt][0], b00, b10);
                mma16816(d[mt][nt], afr[mt][1], b01, b11);
            }
        }
        if (kt + 1 < T) sts_tile((kt + 1) & 1);
    }

    #pragma unroll
    for (int mt = 0; mt < 2; mt++) {
        int row = m0 + wm * 32 + mt * 16 + lq;
        float rs0 = rowscale ? rowscale[row]     : 0.0f;
        float rs8 = rowscale ? rowscale[row + 8] : 0.0f;
        #pragma unroll
        for (int nt = 0; nt < 8; nt++) {
            int col = n0 + wn * 64 + nt * 8 + lr * 2;
            float b0v = bias ? bias[col]     : 0.0f;
            float b1v = bias ? bias[col + 1] : 0.0f;
            float c0  = bias2 ? bias2[col]     : 0.0f;
            float c1  = bias2 ? bias2[col + 1] : 0.0f;
            float v0 = d[mt][nt][0] + b0v + rs0 * c0;
            float v1 = d[mt][nt][1] + b1v + rs0 * c1;
            float v2 = d[mt][nt][2] + b0v + rs8 * c0;
            float v3 = d[mt][nt][3] + b1v + rs8 * c1;
            if (GELU) {
                v0 = gelu_f(v0); v1 = gelu_f(v1);
                v2 = gelu_f(v2); v3 = gelu_f(v3);
            }
            epi(row, col, v0, v1, v2, v3);
        }
    }
}

// fp32-out wrapper (upd1)
template<bool GELU>
__global__ __launch_bounds__(256) void hgemm_kernel(
    const float* __restrict__ A1, int K1,
    const float* __restrict__ A2, int K2,
    const __half* __restrict__ Bh,
    const float* __restrict__ bias,
    const float* __restrict__ bias2,
    const float* __restrict__ rowscale,
    float* __restrict__ C, int NN)
{
    __shared__ __align__(16) __half Ah[2 * 128 * 40];
    __shared__ __align__(16) __half Bs[2 * 128 * 40];
    hgemm_body<GELU>(A1, K1, A2, K2, Bh, bias, bias2, rowscale,
        blockIdx.x * 128, blockIdx.y * 128, Ah, Bs,
        [&](int row, int col, float v0, float v1, float v2, float v3) {
            *(float2*)(C + (size_t)row       * NN + col) = make_float2(v0, v1);
            *(float2*)(C + (size_t)(row + 8) * NN + col) = make_float2(v2, v3);
        });
}

// P3: pdps(512)+qkv(384) GEMMs (896 blocks) | scatter (1024 blocks).
// Scatter adds the cross-block prefix from bsum itself (no scan_fix).
__global__ __launch_bounds__(256) void prep3_kernel(
    const float* __restrict__ xn, const __half* __restrict__ whpdps,
    __half* __restrict__ pdps,
    const float* __restrict__ x, const __half* __restrict__ whqkv,
    const float* __restrict__ in_b, __half* __restrict__ qkvh,
    const int* __restrict__ dstp, const int* __restrict__ srcp,
    int* __restrict__ cursor, const int* __restrict__ bsum,
    int* __restrict__ eperm, int* __restrict__ ssrc,
    int* __restrict__ sdst)
{
    int b = blockIdx.x;
    if (b >= 896) {
        __shared__ int pre[8];
        if (threadIdx.x == 0) {
            int a = 0;
            #pragma unroll
            for (int k = 0; k < 8; k++) { pre[k] = a; a += bsum[k]; }
        }
        __syncthreads();
        int e = (b - 896) * 256 + threadIdx.x;
        int d = dstp[e];
        int s = srcp[e];
        int pos = atomicAdd(&cursor[d], 1) + pre[d >> 11];
        eperm[pos] = e;
        ssrc[pos]  = s;
        sdst[pos]  = d;
        return;
    }
    __shared__ __align__(16) __half Ah[2 * 128 * 40];
    __shared__ __align__(16) __half Bs[2 * 128 * 40];
    int bx = b & 127, by = b >> 7;
    if (by < 4) {
        __half* C = pdps;
        hgemm_body<false>(xn, 128, nullptr, 0, whpdps, nullptr, nullptr,
            nullptr, bx * 128, by * 128, Ah, Bs,
            [&](int row, int col, float v0, float v1, float v2, float v3) {
                *(__half2*)(C + (size_t)row       * 512 + col) = __floats2half2_rn(v0, v1);
                *(__half2*)(C + (size_t)(row + 8) * 512 + col) = __floats2half2_rn(v2, v3);
            });
    } else {
        __half* C = qkvh;
        hgemm_body<false>(x, 128, nullptr, 0, whqkv, in_b, nullptr,
            nullptr, bx * 128, (by - 4) * 128, Ah, Bs,
            [&](int row, int col, float v0, float v1, float v2, float v3) {
                *(__half2*)(C + (size_t)row       * 384 + col) = __floats2half2_rn(v0, v1);
                *(__half2*)(C + (size_t)(row + 8) * 384 + col) = __floats2half2_rn(v2, v3);
            });
    }
}

// Fused: h1 = LN( x + [t1|obuf]@[U2;Wout] + (b2+bout) ) with n1 params.
__global__ __launch_bounds__(256) void upd2_out_ln_kernel(
    const float* __restrict__ t1, const float* __restrict__ obuf,
    const __half* __restrict__ whu2out, const float* __restrict__ bcat,
    const float* __restrict__ x,
    const float* __restrict__ n1_g, const float* __restrict__ n1_b,
    float* __restrict__ h1)
{
    __shared__ __align__(16) __half Ah[2 * 128 * 40];
    __shared__ __align__(16) __half Bs[2 * 128 * 40];
    extern __shared__ float Gs[];          // [128][132]
    const int m0 = blockIdx.x * 128;

    hgemm_body<false>(t1, 128, obuf, 128, whu2out, bcat, nullptr, nullptr,
        m0, 0, Ah, Bs,
        [&](int row, int col, float v0, float v1, float v2, float v3) {
            int rl = row - m0;
            float2 x0 = *(const float2*)(x + (size_t)row       * 128 + col);
            float2 x8 = *(const float2*)(x + (size_t)(row + 8) * 128 + col);
            Gs[rl * 132 + col]           = v0 + x0.x;
            Gs[rl * 132 + col + 1]       = v1 + x0.y;
            Gs[(rl + 8) * 132 + col]     = v2 + x8.x;
            Gs[(rl + 8) * 132 + col + 1] = v3 + x8.y;
        });
    __syncthreads();

    const int t = threadIdx.x, w = t >> 5, lane = t & 31;
    float4 gg = *(const float4*)(n1_g + lane * 4);
    float4 bb = *(const float4*)(n1_b + lane * 4);
    #pragma unroll 4
    for (int i = 0; i < 16; i++) {
        int r = w * 16 + i;
        float4 v = *(const float4*)&Gs[r * 132 + lane * 4];
        float s  = v.x + v.y + v.z + v.w;
        float ss = v.x*v.x + v.y*v.y + v.z*v.z + v.w*v.w;
        #pragma unroll
        for (int o = 16; o > 0; o >>= 1) {
            s  += __shfl_xor_sync(0xffffffffu, s,  o);
            ss += __shfl_xor_sync(0xffffffffu, ss, o);
        }
        float mean = s * (1.0f / 128.0f);
        float var  = ss * (1.0f / 128.0f) - mean * mean;
        float rstd = rsqrtf(var + 1e-5f);
        float4 o4;
        o4.x = (v.x - mean) * rstd * gg.x + bb.x;
        o4.y = (v.y - mean) * rstd * gg.y + bb.y;
        o4.z = (v.z - mean) * rstd * gg.z + bb.z;
        o4.w = (v.w - mean) * rstd * gg.w + bb.w;
        *(float4*)(h1 + (size_t)(m0 + r) * 128 + lane * 4) = o4;
    }
}

// ---------------------------------------------------------------------------
// Fused FFN: out = LN( h1 + ffn2(gelu(ffn1(h1))) )
// ---------------------------------------------------------------------------
__global__ __launch_bounds__(256) void ffn_fused_kernel(
    const float* __restrict__ h1,
    const __half* __restrict__ whf1, const float* __restrict__ ffn_b1,
    const __half* __restrict__ whf2, const float* __restrict__ ffn_b2,
    const float* __restrict__ n2_g, const float* __restrict__ n2_b,
    float* __restrict__ out)
{
    __shared__ __align__(16) __half Ah[2 * 128 * 40];
    __shared__ __align__(16) __half Bs[2 * 128 * 40];
    extern __shared__ __align__(16) char smraw[];
    __half* F  = (__half*)smraw;               // [128][264]
    float*  Gs = (float*)(F + 128 * 264);      // [128][132]
    const int m0 = blockIdx.x * 128;
    const int t  = threadIdx.x;

    #pragma unroll 1
    for (int pass = 0; pass < 2; pass++) {
        hgemm_body<true>(h1, 128, nullptr, 0, whf1, ffn_b1, nullptr, nullptr,
            m0, pass * 128, Ah, Bs,
            [&](int row, int col, float v0, float v1, float v2, float v3) {
                int rl = row - m0;
                *(__half2*)&F[rl * 264 + col]       = __floats2half2_rn(v0, v1);
                *(__half2*)&F[(rl + 8) * 264 + col] = __floats2half2_rn(v2, v3);
            });
        __syncthreads();
    }

    const int wid = t >> 5, lane = t & 31;
    const int wm = wid & 3;
    const int wn = wid >> 2;
    const int lq = lane >> 2;
    const int lr = lane & 3;

    float d[2][8][4];
    #pragma unroll
    for (int mt = 0; mt < 2; mt++)
        #pragma unroll
        for (int nt = 0; nt < 8; nt++)
            #pragma unroll
            for (int c = 0; c < 4; c++) d[mt][nt][c] = 0.0f;

    const int brow = t >> 1, bseg = (t & 1) * 16;
    uint4 rbu0, rbu1;
    auto ldgB = [&](int kb) {
        const __half* bsrc = whf2 + (size_t)brow * 256 + kb + bseg;
        rbu0 = *(const uint4*)bsrc;
        rbu1 = *(const uint4*)(bsrc + 8);
    };
    auto stsB = [&](int buf) {
        __half* bd = &Bs[buf * 128 * 40 + brow * 40 + bseg];
        *(uint4*)bd       = rbu0;
        *(uint4*)(bd + 8) = rbu1;
    };

    ldgB(0); stsB(0);
    for (int kt = 0; kt < 8; kt++) {
        __syncthreads();
        if (kt + 1 < 8) ldgB((kt + 1) * 32);
        const __half* bp = Bs + (kt & 1) * 128 * 40;

        uint32_t afr[2][2][4];
        #pragma unroll
        for (int mt = 0; mt < 2; mt++) {
            int r = wm * 32 + mt * 16 + lq;
            #pragma unroll
            for (int ks = 0; ks < 2; ks++) {
                int k = kt * 32 + ks * 16 + lr * 2;
                afr[mt][ks][0] = *(const uint32_t*)&F[r * 264 + k];
                afr[mt][ks][1] = *(const uint32_t*)&F[(r + 8) * 264 + k];
                afr[mt][ks][2] = *(const uint32_t*)&F[r * 264 + k + 8];
                afr[mt][ks][3] = *(const uint32_t*)&F[(r + 8) * 264 + k + 8];
            }
        }
        #pragma unroll
        for (int nt = 0; nt < 8; nt++) {
            int n = wn * 64 + nt * 8 + lq;
            uint32_t b00 = *(const uint32_t*)&bp[n * 40 + lr * 2];
            uint32_t b10 = *(const uint32_t*)&bp[n * 40 + lr * 2 + 8];
            uint32_t b01 = *(const uint32_t*)&bp[n * 40 + 16 + lr * 2];
            uint32_t b11 = *(const uint32_t*)&bp[n * 40 + 16 + lr * 2 + 8];
            #pragma unroll
            for (int mt = 0; mt < 2; mt++) {
                mma16816(d[mt][nt], afr[mt][0], b00, b10);
                mma16816(d[mt][nt], afr[mt][1], b01, b11);
            }
        }
        if (kt + 1 < 8) stsB((kt + 1) & 1);
    }

    #pragma unroll
    for (int mt = 0; mt < 2; mt++) {
        int row = m0 + wm * 32 + mt * 16 + lq;
        int rl  = row - m0;
        #pragma unroll
        for (int nt = 0; nt < 8; nt++) {
            int col = wn * 64 + nt * 8 + lr * 2;
            float b0v = ffn_b2[col], b1v = ffn_b2[col + 1];
            float2 h0 = *(const float2*)(h1 + (size_t)row       * 128 + col);
            float2 h8 = *(const float2*)(h1 + (size_t)(row + 8) * 128 + col);
            Gs[rl * 132 + col]           = d[mt][nt][0] + b0v + h0.x;
            Gs[rl * 132 + col + 1]       = d[mt][nt][1] + b1v + h0.y;
            Gs[(rl + 8) * 132 + col]     = d[mt][nt][2] + b0v + h8.x;
            Gs[(rl + 8) * 132 + col + 1] = d[mt][nt][3] + b1v + h8.y;
        }
    }
    __syncthreads();

    const int w = t >> 5;
    float4 gg = *(const float4*)(n2_g + lane * 4);
    float4 bb = *(const float4*)(n2_b + lane * 4);
    #pragma unroll 4
    for (int i = 0; i < 16; i++) {
        int r = w * 16 + i;
        float4 v = *(const float4*)&Gs[r * 132 + lane * 4];
        float s  = v.x + v.y + v.z + v.w;
        float ss = v.x*v.x + v.y*v.y + v.z*v.z + v.w*v.w;
        #pragma unroll
        for (int o = 16; o > 0; o >>= 1) {
            s  += __shfl_xor_sync(0xffffffffu, s,  o);
            ss += __shfl_xor_sync(0xffffffffu, ss, o);
        }
        float mean = s * (1.0f / 128.0f);
        float var  = ss * (1.0f / 128.0f) - mean * mean;
        float rstd = rsqrtf(var + 1e-5f);
        float4 o4;
        o4.x = (v.x - mean) * rstd * gg.x + bb.x;
        o4.y = (v.y - mean) * rstd * gg.y + bb.y;
        o4.z = (v.z - mean) * rstd * gg.z + bb.z;
        o4.w = (v.w - mean) * rstd * gg.w + bb.w;
        *(float4*)(out + (size_t)(m0 + r) * 128 + lane * 4) = o4;
    }
}

// ---------------------------------------------------------------------------
// Edge body: MLP + gelu + in-block segmented reduce. 256 threads.
// ---------------------------------------------------------------------------
__device__ __forceinline__ void edge_body(
    char* smraw, int eb,
    const float* __restrict__ ea, const int* __restrict__ eperm,
    const __half* __restrict__ whw1c, const float* __restrict__ b1,
    const __half* __restrict__ pdps,
    const int* __restrict__ sdst, const int* __restrict__ ssrc,
    float* __restrict__ aggrH)
{
    __half* Ws  = (__half*)smraw;                  // [256][36]
    __half* As  = Ws + 256 * 36;                   // [64][36]
    __half* Gsm = As + 64 * 36;                    // [64][264]
    float*  b1s = (float*)(Gsm + 64 * 264);        // [256]
    int*    ds  = (int*)(b1s + 256);               // [64]
    const int t  = threadIdx.x;
    const int e0 = eb * 64;

    {
        b1s[t] = b1[t];
        const uint4* wsrc = (const uint4*)whw1c;
        #pragma unroll
        for (int i = 0; i < 4; i++) {
            int u = t * 4 + i;
            int row = u >> 2, seg = (u & 3) * 8;
            uint4 v = wsrc[u];
            uint2* dst = (uint2*)&Ws[row * 36 + seg];
            dst[0] = make_uint2(v.x, v.y);
            dst[1] = make_uint2(v.z, v.w);
        }
    }
    {
        int el = t >> 2, part = t & 3;
        int e = eperm[e0 + el];
        const float4* src = (const float4*)(ea + (size_t)e * 32 + part * 8);
        float4 v0 = src[0], v1 = src[1];
        __half2* dst = (__half2*)(As + el * 36 + part * 8);
        dst[0] = __floats2half2_rn(v0.x, v0.y);
        dst[1] = __floats2half2_rn(v0.z, v0.w);
        dst[2] = __floats2half2_rn(v1.x, v1.y);
        dst[3] = __floats2half2_rn(v1.z, v1.w);
    }
    if (t < 64) ds[t] = sdst[e0 + t];
    __syncthreads();

    const int wid = t >> 5, lane = t & 31;
    const int wm = wid >> 2;
    const int wn = wid & 3;
    const int lq = lane >> 2;
    const int lr = lane & 3;

    float d[2][8][4];
    #pragma unroll
    for (int mt = 0; mt < 2; mt++)
        #pragma unroll
        for (int nt = 0; nt < 8; nt++)
            #pragma unroll
            for (int c = 0; c < 4; c++) d[mt][nt][c] = 0.0f;

    uint32_t afr[2][2][4];
    #pragma unroll
    for (int mt = 0; mt < 2; mt++) {
        int r = wm * 32 + mt * 16 + lq;
        #pragma unroll
        for (int ks = 0; ks < 2; ks++) {
            int k = ks * 16 + lr * 2;
            afr[mt][ks][0] = *(const uint32_t*)&As[r * 36 + k];
            afr[mt][ks][1] = *(const uint32_t*)&As[(r + 8) * 36 + k];
            afr[mt][ks][2] = *(const uint32_t*)&As[r * 36 + k + 8];
            afr[mt][ks][3] = *(const uint32_t*)&As[(r + 8) * 36 + k + 8];
        }
    }

    #pragma unroll
    for (int nt = 0; nt < 8; nt++) {
        int n = wn * 64 + nt * 8 + lq;
        uint32_t b0k0 = *(const uint32_t*)&Ws[n * 36 + lr * 2];
        uint32_t b1k0 = *(const uint32_t*)&Ws[n * 36 + lr * 2 + 8];
        uint32_t b0k1 = *(const uint32_t*)&Ws[n * 36 + 16 + lr * 2];
        uint32_t b1k1 = *(const uint32_t*)&Ws[n * 36 + 16 + lr * 2 + 8];
        #pragma unroll
        for (int mt = 0; mt < 2; mt++) {
            mma16816(d[mt][nt], afr[mt][0], b0k0, b1k0);
            mma16816(d[mt][nt], afr[mt][1], b0k1, b1k1);
        }
    }

    #pragma unroll
    for (int mt = 0; mt < 2; mt++) {
        int l0 = wm * 32 + mt * 16 + lq;
        int l8 = l0 + 8;
        int j0 = e0 + l0, j8 = e0 + l8;
        const __half* pd0 = pdps + (size_t)sdst[j0] * 512;
        const __half* ps0 = pdps + (size_t)ssrc[j0] * 512 + 256;
        const __half* pd8 = pdps + (size_t)sdst[j8] * 512;
        const __half* ps8 = pdps + (size_t)ssrc[j8] * 512 + 256;
        #pragma unroll
        for (int nt = 0; nt < 8; nt++) {
            int col = wn * 64 + nt * 8 + lr * 2;
            float2 a0 = __half22float2(*(const __half2*)(pd0 + col));
            float2 s0 = __half22float2(*(const __half2*)(ps0 + col));
            float2 a8 = __half22float2(*(const __half2*)(pd8 + col));
            float2 s8 = __half22float2(*(const __half2*)(ps8 + col));
            float bx = b1s[col], by = b1s[col + 1];
            float v0 = gelu_f(d[mt][nt][0] + bx + a0.x + s0.x);
            float v1 = gelu_f(d[mt][nt][1] + by + a0.y + s0.y);
            float v2 = gelu_f(d[mt][nt][2] + bx + a8.x + s8.x);
            float v3 = gelu_f(d[mt][nt][3] + by + a8.y + s8.y);
            *(__half2*)(Gsm + l0 * 264 + col) = __floats2half2_rn(v0, v1);
            *(__half2*)(Gsm + l8 * 264 + col) = __floats2half2_rn(v2, v3);
        }
    }
    __syncthreads();

    {
        int c = t;
        float acc = 0.0f;
        int prev = ds[0];
        #pragma unroll 8
        for (int r = 0; r < 64; r++) {
            int nd = ds[r];
            if (nd != prev) {
                atomicAdd(&aggrH[(size_t)prev * 256 + c], acc);
                acc = 0.0f;
                prev = nd;
            }
            acc += __half2float(Gsm[r * 264 + c]);
        }
        atomicAdd(&aggrH[(size_t)prev * 256 + c], acc);
    }
}

// ---------------------------------------------------------------------------
// Attention body (256-thread loads; warps 0-3 compute). Ks/Qs stride 36.
// ---------------------------------------------------------------------------
#define VTS 514
__device__ __forceinline__ void attn_body(
    char* smraw, int ab,
    const __half* __restrict__ qkv, float* __restrict__ o)
{
    __half* Ks = (__half*)smraw;            // [512][36]
    __half* Vt = Ks + 512 * 36;             // [32][VTS]
    __half* Qs = Vt + 32 * VTS;             // [64][36]
    const int t  = threadIdx.x;
    const int g  = ab >> 5;
    const int h  = (ab >> 3) & 3;
    const int qb = ab & 7;
    const size_t gb = (size_t)g * 512;
    const float scale = 0.17677669529663687f;

    #pragma unroll
    for (int i = 0; i < 16; i++) {
        int task = t + i * 256;
        int row = task >> 3, seg = task & 7;
        uint2 v = *(const uint2*)(qkv + (gb + row) * 384 + 128 + h * 32 + seg * 4);
        *(uint2*)&Ks[row * 36 + seg * 4] = v;
    }
    #pragma unroll
    for (int i = 0; i < 16; i++) {
        int task = t + i * 256;
        int row = task >> 3, seg = task & 7;
        const __half* src = qkv + (gb + row) * 384 + 256 + h * 32 + seg * 4;
        int d0 = seg * 4;
        Vt[(d0 + 0) * VTS + row] = src[0];
        Vt[(d0 + 1) * VTS + row] = src[1];
        Vt[(d0 + 2) * VTS + row] = src[2];
        Vt[(d0 + 3) * VTS + row] = src[3];
    }
    #pragma unroll
    for (int i = 0; i < 2; i++) {
        int task = t + i * 256;
        int row = task >> 3, seg = task & 7;
        const __half2* src = (const __half2*)(qkv + (gb + qb * 64 + row) * 384 + h * 32 + seg * 4);
        float2 v0 = __half22float2(src[0]);
        float2 v1 = __half22float2(src[1]);
        __half2* d = (__half2*)&Qs[row * 36 + seg * 4];
        d[0] = __floats2half2_rn(v0.x * scale, v0.y * scale);
        d[1] = __floats2half2_rn(v1.x * scale, v1.y * scale);
    }
    __syncthreads();

    if (t >= 128) return;

    const int wq = t >> 5, lane = t & 31;
    const int lq = lane >> 2, lr = lane & 3;

    uint32_t aq[2][4];
    #pragma unroll
    for (int ks = 0; ks < 2; ks++) {
        int base = (wq * 16 + lq) * 36 + ks * 16 + lr * 2;
        aq[ks][0] = *(const uint32_t*)&Qs[base];
        aq[ks][1] = *(const uint32_t*)&Qs[base + 8 * 36];
        aq[ks][2] = *(const uint32_t*)&Qs[base + 8];
        aq[ks][3] = *(const uint32_t*)&Qs[base + 8 * 36 + 8];
    }

    float m0 = -1e30f, m1 = -1e30f, l0 = 0.0f, l1 = 0.0f;
    float oA[4][4];
    #pragma unroll
    for (int n = 0; n < 4; n++)
        #pragma unroll
        for (int c = 0; c < 4; c++) oA[n][c] = 0.0f;

    for (int c = 0; c < 8; c++) {
        float s[8][4];
        #pragma unroll
        for (int nt = 0; nt < 8; nt++)
            #pragma unroll
            for (int q = 0; q < 4; q++) s[nt][q] = 0.0f;
        #pragma unroll
        for (int nt = 0; nt < 8; nt++) {
            int kb = (c * 64 + nt * 8 + lq) * 36 + lr * 2;
            mma16816(s[nt], aq[0], *(const uint32_t*)&Ks[kb],
                                    *(const uint32_t*)&Ks[kb + 8]);
            mma16816(s[nt], aq[1], *(const uint32_t*)&Ks[kb + 16],
                                    *(const uint32_t*)&Ks[kb + 24]);
        }
        float mc0 = -1e30f, mc1 = -1e30f;
        #pragma unroll
        for (int nt = 0; nt < 8; nt++) {
            mc0 = fmaxf(mc0, fmaxf(s[nt][0], s[nt][1]));
            mc1 = fmaxf(mc1, fmaxf(s[nt][2], s[nt][3]));
        }
        mc0 = fmaxf(mc0, __shfl_xor_sync(0xffffffffu, mc0, 1));
        mc0 = fmaxf(mc0, __shfl_xor_sync(0xffffffffu, mc0, 2));
        mc1 = fmaxf(mc1, __shfl_xor_sync(0xffffffffu, mc1, 1));
        mc1 = fmaxf(mc1, __shfl_xor_sync(0xffffffffu, mc1, 2));
        float mn0 = fmaxf(m0, mc0), mn1 = fmaxf(m1, mc1);
        float cr0 = __expf(m0 - mn0), cr1 = __expf(m1 - mn1);
        m0 = mn0; m1 = mn1;
        float rs0 = 0.0f, rs1 = 0.0f;
        #pragma unroll
        for (int nt = 0; nt < 8; nt++) {
            s[nt][0] = __expf(s[nt][0] - m0); rs0 += s[nt][0];
            s[nt][1] = __expf(s[nt][1] - m0); rs0 += s[nt][1];
            s[nt][2] = __expf(s[nt][2] - m1); rs1 += s[nt][2];
            s[nt][3] = __expf(s[nt][3] - m1); rs1 += s[nt][3];
        }
        rs0 += __shfl_xor_sync(0xffffffffu, rs0, 1);
        rs0 += __shfl_xor_sync(0xffffffffu, rs0, 2);
        rs1 += __shfl_xor_sync(0xffffffffu, rs1, 1);
        rs1 += __shfl_xor_sync(0xffffffffu, rs1, 2);
        l0 = l0 * cr0 + rs0;
        l1 = l1 * cr1 + rs1;
        #pragma unroll
        for (int n = 0; n < 4; n++) {
            oA[n][0] *= cr0; oA[n][1] *= cr0;
            oA[n][2] *= cr1; oA[n][3] *= cr1;
        }
        #pragma unroll
        for (int kt = 0; kt < 4; kt++) {
            uint32_t a[4];
            a[0] = packh2(s[2 * kt][0],     s[2 * kt][1]);
            a[1] = packh2(s[2 * kt][2],     s[2 * kt][3]);
            a[2] = packh2(s[2 * kt + 1][0], s[2 * kt + 1][1]);
            a[3] = packh2(s[2 * kt + 1][2], s[2 * kt + 1][3]);
            #pragma unroll
            for (int nd = 0; nd < 4; nd++) {
                int vb = (nd * 8 + lq) * VTS + c * 64 + kt * 16 + lr * 2;
                mma16816(oA[nd], a, *(const uint32_t*)&Vt[vb],
                                     *(const uint32_t*)&Vt[vb + 8]);
            }
        }
    }

    float i0 = 1.0f / l0, i1 = 1.0f / l1;
    int row = qb * 64 + wq * 16 + lq;
    float* orow = o + (gb + row) * 128 + h * 32;
    #pragma unroll
    for (int nd = 0; nd < 4; nd++) {
        *(float2*)(orow + nd * 8 + lr * 2) =
            make_float2(oA[nd][0] * i0, oA[nd][1] * i0);
        *(float2*)(orow + 8 * 128 + nd * 8 + lr * 2) =
            make_float2(oA[nd][2] * i1, oA[nd][3] * i1);
    }
}

// P5: merged attention (blocks 0..1023) + edge (1024..5119)
__global__ __launch_bounds__(256) void edge_attn_kernel(
    const __half* __restrict__ qkvh, float* __restrict__ obuf,
    const float* __restrict__ ea, const int* __restrict__ eperm,
    const __half* __restrict__ whw1c, const float* __restrict__ b1,
    const __half* __restrict__ pdps,
    const int* __restrict__ sdst, const int* __restrict__ ssrc,
    float* __restrict__ aggrH)
{
    extern __shared__ __align__(16) char smraw[];
    int b = blockIdx.x;
    if (b < 1024)
        attn_body(smraw, b, qkvh, obuf);
    else
        edge_body(smraw, b - 1024, ea, eperm, whw1c, b1, pdps, sdst, ssrc, aggrH);
}

// ---------------------------------------------------------------------------
// Host launcher
// ---------------------------------------------------------------------------
extern "C" void kernel_launch(void* const* d_in, const int* in_sizes, int n_in,
                              void* d_out, int out_size)
{
    const float* x      = (const float*)d_in[0];
    const int*   eidx   = (const int*)  d_in[1];
    const float* ea     = (const float*)d_in[2];
    /* d_in[3] = batch (unused) */
    const float* gnn_g  = (const float*)d_in[4];
    const float* gnn_b  = (const float*)d_in[5];
    const float* msg_w1 = (const float*)d_in[6];
    const float* msg_b1 = (const float*)d_in[7];
    const float* msg_w2 = (const float*)d_in[8];
    const float* msg_b2 = (const float*)d_in[9];
    const float* upd_w1 = (const float*)d_in[10];
    const float* upd_b1 = (const float*)d_in[11];
    const float* upd_w2 = (const float*)d_in[12];
    const float* upd_b2 = (const float*)d_in[13];
    const float* in_w   = (const float*)d_in[14];
    const float* in_b   = (const float*)d_in[15];
    const float* out_w  = (const float*)d_in[16];
    const float* out_b  = (const float*)d_in[17];
    const float* ffn_w1 = (const float*)d_in[18];
    const float* ffn_b1 = (const float*)d_in[19];
    const float* ffn_w2 = (const float*)d_in[20];
    const float* ffn_b2 = (const float*)d_in[21];
    const float* n1_g   = (const float*)d_in[22];
    const float* n1_b   = (const float*)d_in[23];
    const float* n2_g   = (const float*)d_in[24];
    const float* n2_b   = (const float*)d_in[25];
    float* out = (float*)d_out;

    const int* srcp = eidx;
    const int* dstp = eidx + EV;

    float *xn, *aggrH, *t1, *obuf, *h1, *deg, *uwp, *b2u, *bcat;
    __half *pdps, *qkvh, *whpdps, *whuw, *whu2out, *whqkv, *whf1, *whf2, *whw1c;
    int *cnt, *cursor, *eperm, *ssrc, *sdst, *bsum;
    cudaGetSymbolAddress((void**)&xn,    g_xn);
    cudaGetSymbolAddress((void**)&pdps,  g_pdps);
    cudaGetSymbolAddress((void**)&aggrH, g_aggrH);
    cudaGetSymbolAddress((void**)&t1,    g_t1);
    cudaGetSymbolAddress((void**)&qkvh,  g_qkvh);
    cudaGetSymbolAddress((void**)&obuf,  g_obuf);
    cudaGetSymbolAddress((void**)&h1,    g_h1);
    cudaGetSymbolAddress((void**)&deg,   g_deg);
    cudaGetSymbolAddress((void**)&uwp,   g_uwp);
    cudaGetSymbolAddress((void**)&b2u,   g_b2u);
    cudaGetSymbolAddress((void**)&bcat,  g_bcat);
    cudaGetSymbolAddress((void**)&cnt,   g_cnt);
    cudaGetSymbolAddress((void**)&cursor,g_cursor);
    cudaGetSymbolAddress((void**)&eperm, g_eperm);
    cudaGetSymbolAddress((void**)&ssrc,  g_ssrc);
    cudaGetSymbolAddress((void**)&sdst,  g_sdst);
    cudaGetSymbolAddress((void**)&bsum,  g_bsum);
    cudaGetSymbolAddress((void**)&whpdps, g_wh_pdps);
    cudaGetSymbolAddress((void**)&whuw,   g_wh_uw);
    cudaGetSymbolAddress((void**)&whu2out,g_wh_u2out);
    cudaGetSymbolAddress((void**)&whqkv,  g_wh_qkv);
    cudaGetSymbolAddress((void**)&whf1,   g_wh_f1);
    cudaGetSymbolAddress((void**)&whf2,   g_wh_f2);
    cudaGetSymbolAddress((void**)&whw1c,  g_wh_w1c);

    cudaFuncSetAttribute(edge_attn_kernel,
                         cudaFuncAttributeMaxDynamicSharedMemorySize, 74368);
    cudaFuncSetAttribute(upd2_out_ln_kernel,
                         cudaFuncAttributeMaxDynamicSharedMemorySize, 67584);
    cudaFuncSetAttribute(ffn_fused_kernel,
                         cudaFuncAttributeMaxDynamicSharedMemorySize, 135168);

    // 0) cnt zero (must precede P1's hist)
    cudaMemsetAsync(cnt, 0, NV * sizeof(int), 0);

    // P1: prep-GEMM | aggrH zero | prep_bias | hist | LN(x)
    prep1_kernel<<<3589, 256>>>(
        msg_w2, upd_w1 + 128 * 128, uwp,
        msg_b2, upd_b2, out_b, b2u, bcat,
        dstp, cnt, x, gnn_g, gnn_b, xn, aggrH);

    // P2: convw (all fp16 tables) | scan_local (cursor = local offsets)
    prep2_kernel<<<1064, 256>>>(
        msg_w1, upd_w1, uwp, upd_w2, in_w, out_w, ffn_w1, ffn_w2,
        whpdps, whuw, whu2out, whqkv, whf1, whf2, whw1c,
        cnt, cursor, deg, bsum);

    // P3: pdps+qkv GEMMs | scatter (prefix from bsum, hidden under GEMMs)
    prep3_kernel<<<1920, 256>>>(
        xn, whpdps, pdps, x, whqkv, in_b, qkvh,
        dstp, srcp, cursor, bsum, eperm, ssrc, sdst);

    // P4: merged flash attention + edge MLP/reduce
    edge_attn_kernel<<<1024 + EV / 64, 256, 74368>>>(
        qkvh, obuf, ea, eperm, whw1c, msg_b1, pdps, sdst, ssrc, aggrH);

    // tail: upd1 -> upd2+out+LN -> fused FFN+LN
    hgemm_kernel<true><<<dim3(NV / 128, 1), 256>>>(
        xn, 128, aggrH, 256, whuw, upd_b1, b2u, deg, t1, 128);
    upd2_out_ln_kernel<<<NV / 128, 256, 67584>>>(
        t1, obuf, whu2out, bcat, x, n1_g, n1_b, h1);
    ffn_fused_kernel<<<NV / 128, 256, 135168>>>(
        h1, whf1, ffn_b1, whf2, ffn_b2, n2_g, n2_b, out);
}